// round 8
// baseline (speedup 1.0000x reference)
#include <cuda_runtime.h>
#include <cuda_fp16.h>
#include <cstdint>

#define B_   128
#define NT   197
#define HH   12
#define HD   64
#define DIM_ 768
#define MTOK (B_ * NT)          // 25216 = 197*128
#define GMT  25344              // padded M: 256*99

// ---------------- scratch ----------------
__device__ __half g_qhi [(long long)GMT * 2304];
__device__ __half g_qlo [(long long)GMT * 2304];
__device__ __half g_xhi [(long long)GMT * DIM_];
__device__ __half g_xlo [(long long)GMT * DIM_];
__device__ __half g_aohi[(long long)GMT * DIM_];
__device__ __half g_aolo[(long long)GMT * DIM_];
__device__ __half g_qwhi[2304 * DIM_];
__device__ __half g_qwlo[2304 * DIM_];
__device__ __half g_pwhi[DIM_ * DIM_];
__device__ __half g_pwlo[DIM_ * DIM_];
__device__ float  g_bias[HH * NT * NT];

// ---------------- helpers ----------------
__device__ __forceinline__ uint32_t smem_u32(const void* p) {
    uint32_t a;
    asm("{ .reg .u64 t; cvta.to.shared.u64 t, %1; cvt.u32.u64 %0, t; }" : "=r"(a) : "l"(p));
    return a;
}

#define CPA16(dst, src)   asm volatile("cp.async.cg.shared.global [%0], [%1], 16;" :: "r"(dst), "l"(src) : "memory")
#define CPA_COMMIT()      asm volatile("cp.async.commit_group;" ::: "memory")
#define CPA_WAIT(n)       asm volatile("cp.async.wait_group %0;" :: "n"(n) : "memory")

#define LDSM_X4(r0, r1, r2, r3, addr) \
    asm volatile("ldmatrix.sync.aligned.m8n8.x4.shared.b16 {%0,%1,%2,%3}, [%4];" \
        : "=r"(r0), "=r"(r1), "=r"(r2), "=r"(r3) : "r"(addr))

#define LDSM_X4_T(r0, r1, r2, r3, addr) \
    asm volatile("ldmatrix.sync.aligned.m8n8.x4.trans.shared.b16 {%0,%1,%2,%3}, [%4];" \
        : "=r"(r0), "=r"(r1), "=r"(r2), "=r"(r3) : "r"(addr))

#define MMA16816(d, a, b0, b1) \
    asm volatile("mma.sync.aligned.m16n8k16.row.col.f32.f16.f16.f32 " \
        "{%0,%1,%2,%3}, {%4,%5,%6,%7}, {%8,%9}, {%0,%1,%2,%3};" \
        : "+f"((d)[0]), "+f"((d)[1]), "+f"((d)[2]), "+f"((d)[3]) \
        : "r"((a)[0]), "r"((a)[1]), "r"((a)[2]), "r"((a)[3]), "r"(b0), "r"(b1))

// swizzled tile offset for 64B rows (gemm tiles): chunk 0..3
__device__ __forceinline__ uint32_t sw_off(int row, int chunk) {
    return (uint32_t)(row * 64 + ((chunk ^ ((row >> 1) & 3)) << 4));
}
// swizzled offset for 128B rows (attention tiles): chunk 0..7
__device__ __forceinline__ uint32_t swb(int row, int chunk) {
    return (uint32_t)(row * 128 + ((chunk ^ (row & 7)) << 4));
}

static __device__ __forceinline__ void h_split(float v, __half& hi, __half& lo) {
    hi = __float2half_rn(v);
    lo = __float2half_rn(v - __half2float(hi));
}

// ---------------- elementwise fp16 split ----------------
__global__ void split_kernel(const float* __restrict__ in,
                             __half* __restrict__ hi, __half* __restrict__ lo, int n)
{
    int t = blockIdx.x * 256 + threadIdx.x;
    if (t < n) {
        __half h, l;
        h_split(in[t], h, l);
        hi[t] = h; lo[t] = l;
    }
}

// ---------------- bias gather ----------------
__global__ void bias_kernel(const float* __restrict__ table,
                            const int*   __restrict__ idx,
                            float* __restrict__ out)
{
    int t = blockIdx.x * blockDim.x + threadIdx.x;
    if (t < HH * NT * NT) {
        int ij = t % (NT * NT);
        int h  = t / (NT * NT);
        out[t] = table[idx[ij] * HH + h];
    }
}

// ---------------- 3xFP16 mma.sync GEMM: 256(M) x 128(N) tiles, 512 thr ----------------
#define GK     768
#define NCHUNK 24
#define STAGEB 49152                   // Ahi 16K + Alo 16K + Bhi 8K + Blo 8K
#define NSTAGE 3
#define GSMEM  (NSTAGE * STAGEB)       // 144 KB

static __device__ __forceinline__ void load_stage(
    uint32_t sbase, const __half* __restrict__ Ahi, const __half* __restrict__ Alo,
    const __half* __restrict__ Whi, const __half* __restrict__ Wlo,
    int m0, int n0, int k0, int tid)
{
    // A: 256 rows x 32 halves (hi+lo)
#pragma unroll
    for (int j = 0; j < 2; j++) {
        int id = tid + (j << 9);        // 0..1023
        int row = id >> 2, c = id & 3;
        uint32_t o = sw_off(row, c);
        size_t ga = (size_t)(m0 + row) * GK + k0 + c * 8;
        CPA16(sbase + o,         Ahi + ga);
        CPA16(sbase + 16384 + o, Alo + ga);
    }
    // B: 128 rows x 32 halves (hi+lo)
    {
        int row = tid >> 2, c = tid & 3;
        uint32_t o = sw_off(row, c);
        size_t gb = (size_t)(n0 + row) * GK + k0 + c * 8;
        CPA16(sbase + 32768 + o, Whi + gb);
        CPA16(sbase + 40960 + o, Wlo + gb);
    }
}

template<bool SPLIT>
__global__ __launch_bounds__(512, 1)
void gemm_hmma_kernel(const __half* __restrict__ Ahi, const __half* __restrict__ Alo,
                      const __half* __restrict__ Whi, const __half* __restrict__ Wlo,
                      const float* __restrict__ bias, float* __restrict__ C,
                      __half* __restrict__ Chi, __half* __restrict__ Clo,
                      int Nn, int Mvalid)
{
    extern __shared__ char dsm[];
    const int tid = threadIdx.x;
    const int lane = tid & 31;
    const int wid = tid >> 5;
    const int wm = (wid & 7) * 32;      // 8 warps along M (256)
    const int wn = (wid >> 3) * 64;     // 2 warps along N (128)
    const int m0 = blockIdx.y * 256;
    const int n0 = blockIdx.x * 128;
    const uint32_t sb = smem_u32(dsm);

    float acc[2][8][4];
#pragma unroll
    for (int mt = 0; mt < 2; mt++)
#pragma unroll
        for (int nt = 0; nt < 8; nt++)
#pragma unroll
            for (int e = 0; e < 4; e++) acc[mt][nt][e] = 0.f;

    const int a_row = lane & 15;
    const int a_kc  = lane >> 4;
    const int b_row = (lane & 7) + ((lane >> 4) << 3);
    const int b_kc  = (lane >> 3) & 1;

    load_stage(sb,          Ahi, Alo, Whi, Wlo, m0, n0, 0,  tid);
    CPA_COMMIT();
    load_stage(sb + STAGEB, Ahi, Alo, Whi, Wlo, m0, n0, 32, tid);
    CPA_COMMIT();

    int st = 0;
    for (int k = 0; k < NCHUNK; k++) {
        if (k + 1 < NCHUNK) { CPA_WAIT(1); } else { CPA_WAIT(0); }
        __syncthreads();
        if (k + 2 < NCHUNK) {
            int ls = st + 2; if (ls >= NSTAGE) ls -= NSTAGE;
            load_stage(sb + ls * STAGEB, Ahi, Alo, Whi, Wlo, m0, n0, (k + 2) * 32, tid);
            CPA_COMMIT();
        }

        const uint32_t cs  = sb + st * STAGEB;
        const uint32_t sAh = cs, sAl = cs + 16384, sBh = cs + 32768, sBl = cs + 40960;

#pragma unroll
        for (int kk = 0; kk < 2; kk++) {
            const int kc = kk * 2;
            uint32_t ah[2][4], al[2][4];
#pragma unroll
            for (int mt = 0; mt < 2; mt++) {
                uint32_t o = sw_off(wm + mt * 16 + a_row, kc + a_kc);
                LDSM_X4(ah[mt][0], ah[mt][1], ah[mt][2], ah[mt][3], sAh + o);
                LDSM_X4(al[mt][0], al[mt][1], al[mt][2], al[mt][3], sAl + o);
            }
#pragma unroll
            for (int ng = 0; ng < 4; ng++) {
                uint32_t bh[4], bl[4];
                uint32_t o = sw_off(wn + ng * 16 + b_row, kc + b_kc);
                LDSM_X4(bh[0], bh[1], bh[2], bh[3], sBh + o);
                LDSM_X4(bl[0], bl[1], bl[2], bl[3], sBl + o);
#pragma unroll
                for (int mt = 0; mt < 2; mt++) {
                    MMA16816(acc[mt][ng * 2 + 0], ah[mt], bh[0], bh[1]);
                    MMA16816(acc[mt][ng * 2 + 0], ah[mt], bl[0], bl[1]);
                    MMA16816(acc[mt][ng * 2 + 0], al[mt], bh[0], bh[1]);
                    MMA16816(acc[mt][ng * 2 + 1], ah[mt], bh[2], bh[3]);
                    MMA16816(acc[mt][ng * 2 + 1], ah[mt], bl[2], bl[3]);
                    MMA16816(acc[mt][ng * 2 + 1], al[mt], bh[2], bh[3]);
                }
            }
        }
        if (++st == NSTAGE) st = 0;
    }

    const int erow = lane >> 2;
    const int ecol = (lane & 3) * 2;
#pragma unroll
    for (int mt = 0; mt < 2; mt++) {
#pragma unroll
        for (int nt = 0; nt < 8; nt++) {
            int col = n0 + wn + nt * 8 + ecol;
            float b0 = __ldg(bias + col), b1 = __ldg(bias + col + 1);
            int r0 = m0 + wm + mt * 16 + erow;
            float v00 = acc[mt][nt][0] + b0, v01 = acc[mt][nt][1] + b1;
            float v10 = acc[mt][nt][2] + b0, v11 = acc[mt][nt][3] + b1;
            if (SPLIT) {
                __half h0, l0, h1, l1;
                h_split(v00, h0, l0); h_split(v01, h1, l1);
                *(__half2*)(Chi + (size_t)r0 * Nn + col) = __halves2half2(h0, h1);
                *(__half2*)(Clo + (size_t)r0 * Nn + col) = __halves2half2(l0, l1);
                h_split(v10, h0, l0); h_split(v11, h1, l1);
                *(__half2*)(Chi + (size_t)(r0 + 8) * Nn + col) = __halves2half2(h0, h1);
                *(__half2*)(Clo + (size_t)(r0 + 8) * Nn + col) = __halves2half2(l0, l1);
            } else {
                if (r0 < Mvalid)
                    *(float2*)(C + (size_t)r0 * Nn + col) = make_float2(v00, v01);
                if (r0 + 8 < Mvalid)
                    *(float2*)(C + (size_t)(r0 + 8) * Nn + col) = make_float2(v10, v11);
            }
        }
    }
}

// ---------------- HMMA attention (unchanged from R7) ----------------
#define KP     256
#define VP     208
#define PSTRB  432
#define PSTRH  216
#define SSTR   258
#define A_KH   0
#define A_KL   (A_KH + KP * 128)
#define A_VH   (A_KL + KP * 128)
#define A_VL   (A_VH + VP * 128)
#define A_QH   (A_VL + VP * 128)
#define A_QL   (A_QH + 2 * 32 * 128)
#define A_S    (A_QL + 2 * 32 * 128)
#define A_PH   (A_S + 32 * SSTR * 4)
#define A_PL   (A_PH + 32 * PSTRB)
#define A_INV  (A_PL + 32 * PSTRB)
#define A_TOT  (A_INV + 128)

__global__ __launch_bounds__(256) void attn_hmma_kernel(
    const __half* __restrict__ qhi, const __half* __restrict__ qlo,
    const float* __restrict__ bias,
    __half* __restrict__ aohi, __half* __restrict__ aolo)
{
    extern __shared__ char smb[];
    const uint32_t sb = smem_u32(smb);
    const int b = blockIdx.x / HH;
    const int h = blockIdx.x % HH;
    const int tid = threadIdx.x, lane = tid & 31, wid = tid >> 5;
    const __half* bh_ = qhi + (size_t)b * NT * 2304 + h * 64;
    const __half* bl_ = qlo + (size_t)b * NT * 2304 + h * 64;
    const float* biasH = bias + (size_t)h * NT * NT;

    for (int i = tid; i < ((KP - NT) * 128) / 4; i += 256) {
        ((uint32_t*)(smb + A_KH + NT * 128))[i] = 0;
        ((uint32_t*)(smb + A_KL + NT * 128))[i] = 0;
    }
    for (int i = tid; i < ((VP - NT) * 128) / 4; i += 256) {
        ((uint32_t*)(smb + A_VH + NT * 128))[i] = 0;
        ((uint32_t*)(smb + A_VL + NT * 128))[i] = 0;
    }
    for (int i = tid; i < (2 * 32 * PSTRB) / 4; i += 256)
        ((uint32_t*)(smb + A_PH))[i] = 0;

    for (int p = tid; p < NT * 8; p += 256) {
        int row = p >> 3, c = p & 7;
        uint32_t o = swb(row, c);
        size_t goff = (size_t)row * 2304 + 768 + c * 8;
        CPA16(sb + A_KH + o, bh_ + goff);
        CPA16(sb + A_KL + o, bl_ + goff);
        CPA16(sb + A_VH + o, bh_ + goff + 768);
        CPA16(sb + A_VL + o, bl_ + goff + 768);
    }
    for (int p = tid; p < 32 * 8; p += 256) {
        int r = p >> 3, c = p & 7;
        int gr = (r < NT) ? r : 0;
        size_t goff = (size_t)gr * 2304 + c * 8;
        uint32_t o = swb(r, c);
        CPA16(sb + A_QH + o, bh_ + goff);
        CPA16(sb + A_QL + o, bl_ + goff);
    }
    CPA_COMMIT();
    CPA_WAIT(0);
    __syncthreads();

    const int a_row16 = lane & 15;
    const int a_kc1   = lane >> 4;
    const int b_row8  = (lane & 7) + ((lane >> 4) << 3);
    const int b_kc1   = (lane >> 3) & 1;

    for (int qt = 0; qt < 7; qt++) {
        const int r0 = qt * 32;
        const int rows = min(32, NT - r0);
        const uint32_t qbuf = (uint32_t)((qt & 1) * 4096);

        {
            const int wm = (wid & 1) * 16;
            const int wn = (wid >> 1) * 64;
            float acc[8][4];
#pragma unroll
            for (int t = 0; t < 8; t++)
#pragma unroll
                for (int e = 0; e < 4; e++) acc[t][e] = 0.f;

            const int ar = wm + a_row16;
#pragma unroll
            for (int kk = 0; kk < 4; kk++) {
                uint32_t aoff = swb(ar, kk * 2 + a_kc1) + qbuf;
                uint32_t ah[4], al[4];
                LDSM_X4(ah[0], ah[1], ah[2], ah[3], sb + A_QH + aoff);
                LDSM_X4(al[0], al[1], al[2], al[3], sb + A_QL + aoff);
#pragma unroll
                for (int ng = 0; ng < 4; ng++) {
                    uint32_t boff = swb(wn + ng * 16 + b_row8, kk * 2 + b_kc1);
                    uint32_t bh[4], bl[4];
                    LDSM_X4(bh[0], bh[1], bh[2], bh[3], sb + A_KH + boff);
                    LDSM_X4(bl[0], bl[1], bl[2], bl[3], sb + A_KL + boff);
                    MMA16816(acc[ng * 2 + 0], ah, bh[0], bh[1]);
                    MMA16816(acc[ng * 2 + 0], ah, bl[0], bl[1]);
                    MMA16816(acc[ng * 2 + 0], al, bh[0], bh[1]);
                    MMA16816(acc[ng * 2 + 1], ah, bh[2], bh[3]);
                    MMA16816(acc[ng * 2 + 1], ah, bl[2], bl[3]);
                    MMA16816(acc[ng * 2 + 1], al, bh[2], bh[3]);
                }
            }
            const int erow = wm + (lane >> 2);
            const int ecol = (lane & 3) * 2;
            float* S = (float*)(smb + A_S);
#pragma unroll
            for (int nt = 0; nt < 8; nt++) {
                int col = wn + nt * 8 + ecol;
                float b00 = 0.f, b01 = 0.f, b10 = 0.f, b11 = 0.f;
                if (col < NT) {
                    int gr0 = r0 + erow, gr1 = r0 + erow + 8;
                    bool c1 = (col + 1 < NT);
                    if (gr0 < NT) {
                        b00 = biasH[(size_t)gr0 * NT + col];
                        if (c1) b01 = biasH[(size_t)gr0 * NT + col + 1];
                    }
                    if (gr1 < NT) {
                        b10 = biasH[(size_t)gr1 * NT + col];
                        if (c1) b11 = biasH[(size_t)gr1 * NT + col + 1];
                    }
                }
                *(float2*)(S + erow * SSTR + col) =
                    make_float2(acc[nt][0] * 0.125f + b00, acc[nt][1] * 0.125f + b01);
                *(float2*)(S + (erow + 8) * SSTR + col) =
                    make_float2(acc[nt][2] * 0.125f + b10, acc[nt][3] * 0.125f + b11);
            }
        }
        __syncthreads();

        if (qt + 1 < 7) {
            const int nr0 = (qt + 1) * 32;
            const uint32_t nqb = (uint32_t)(((qt + 1) & 1) * 4096);
            for (int p = tid; p < 32 * 8; p += 256) {
                int r = p >> 3, c = p & 7;
                int gr = (nr0 + r < NT) ? (nr0 + r) : 0;
                size_t goff = (size_t)gr * 2304 + c * 8;
                uint32_t o = swb(r, c) + nqb;
                CPA16(sb + A_QH + o, bh_ + goff);
                CPA16(sb + A_QL + o, bl_ + goff);
            }
            CPA_COMMIT();
        }

        {
            float* S = (float*)(smb + A_S);
            __half* PH = (__half*)(smb + A_PH);
            __half* PL = (__half*)(smb + A_PL);
            float* INV = (float*)(smb + A_INV);
#pragma unroll
            for (int i = 0; i < 4; i++) {
                int r = wid * 4 + i;
                if (r < rows) {
                    float m = -3.4e38f;
                    for (int c = lane; c < NT; c += 32) m = fmaxf(m, S[r * SSTR + c]);
#pragma unroll
                    for (int o = 16; o > 0; o >>= 1) m = fmaxf(m, __shfl_xor_sync(0xffffffffu, m, o));
                    float s = 0.f;
                    for (int c = lane; c < NT; c += 32) {
                        float e = __expf(S[r * SSTR + c] - m);
                        s += e;
                        __half eh, el;
                        h_split(e, eh, el);
                        PH[r * PSTRH + c] = eh;
                        PL[r * PSTRH + c] = el;
                    }
#pragma unroll
                    for (int o = 16; o > 0; o >>= 1) s += __shfl_xor_sync(0xffffffffu, s, o);
                    if (lane == 0) INV[r] = 1.f / s;
                }
            }
        }
        __syncthreads();

        {
            const int wm = (wid & 1) * 16;
            const int wd = (wid >> 1) * 16;
            float acc[2][4];
#pragma unroll
            for (int t = 0; t < 2; t++)
#pragma unroll
                for (int e = 0; e < 4; e++) acc[t][e] = 0.f;

            const int ar = wm + a_row16;
            const int vch = (wd >> 3) + (lane >> 4);
#pragma unroll
            for (int kk = 0; kk < 13; kk++) {
                uint32_t aoff = (uint32_t)(ar * PSTRB + (kk * 2 + a_kc1) * 16);
                uint32_t ah[4], al[4];
                LDSM_X4(ah[0], ah[1], ah[2], ah[3], sb + A_PH + aoff);
                LDSM_X4(al[0], al[1], al[2], al[3], sb + A_PL + aoff);
                uint32_t boff = swb(kk * 16 + (lane & 15), vch);
                uint32_t bh[4], bl[4];
                LDSM_X4_T(bh[0], bh[1], bh[2], bh[3], sb + A_VH + boff);
                LDSM_X4_T(bl[0], bl[1], bl[2], bl[3], sb + A_VL + boff);
                MMA16816(acc[0], ah, bh[0], bh[1]);
                MMA16816(acc[0], ah, bl[0], bl[1]);
                MMA16816(acc[0], al, bh[0], bh[1]);
                MMA16816(acc[1], ah, bh[2], bh[3]);
                MMA16816(acc[1], ah, bl[2], bl[3]);
                MMA16816(acc[1], al, bh[2], bh[3]);
            }
            const int erow = wm + (lane >> 2);
            const int ec = (lane & 3) * 2;
            float* INV = (float*)(smb + A_INV);
#pragma unroll
            for (int hf = 0; hf < 2; hf++) {
                int rr = erow + hf * 8;
                if (rr < rows) {
                    float inv = INV[rr];
                    size_t gb = ((size_t)b * NT + r0 + rr) * DIM_ + h * 64 + wd;
#pragma unroll
                    for (int nt = 0; nt < 2; nt++) {
                        int d = nt * 8 + ec;
                        __half h0, l0, h1, l1;
                        h_split(acc[nt][hf * 2 + 0] * inv, h0, l0);
                        h_split(acc[nt][hf * 2 + 1] * inv, h1, l1);
                        *(__half2*)(aohi + gb + d) = __halves2half2(h0, h1);
                        *(__half2*)(aolo + gb + d) = __halves2half2(l0, l1);
                    }
                }
            }
        }
        if (qt + 1 < 7) { CPA_WAIT(0); }
        __syncthreads();
    }
}

// ---------------- launch ----------------
extern "C" void kernel_launch(void* const* d_in, const int* in_sizes, int n_in,
                              void* d_out, int out_size)
{
    const float* x      = (const float*)d_in[0];
    const float* qkv_w  = (const float*)d_in[1];
    const float* qkv_b  = (const float*)d_in[2];
    const float* proj_w = (const float*)d_in[3];
    const float* proj_b = (const float*)d_in[4];
    const float* table  = (const float*)d_in[5];
    const int*   relidx = (const int*)d_in[6];
    float* out = (float*)d_out;

    float *p_bias;
    __half *p_qhi, *p_qlo, *p_xhi, *p_xlo, *p_aohi, *p_aolo;
    __half *p_qwhi, *p_qwlo, *p_pwhi, *p_pwlo;
    cudaGetSymbolAddress((void**)&p_qhi,  g_qhi);
    cudaGetSymbolAddress((void**)&p_qlo,  g_qlo);
    cudaGetSymbolAddress((void**)&p_xhi,  g_xhi);
    cudaGetSymbolAddress((void**)&p_xlo,  g_xlo);
    cudaGetSymbolAddress((void**)&p_aohi, g_aohi);
    cudaGetSymbolAddress((void**)&p_aolo, g_aolo);
    cudaGetSymbolAddress((void**)&p_qwhi, g_qwhi);
    cudaGetSymbolAddress((void**)&p_qwlo, g_qwlo);
    cudaGetSymbolAddress((void**)&p_pwhi, g_pwhi);
    cudaGetSymbolAddress((void**)&p_pwlo, g_pwlo);
    cudaGetSymbolAddress((void**)&p_bias, g_bias);

    cudaFuncSetAttribute(attn_hmma_kernel, cudaFuncAttributeMaxDynamicSharedMemorySize, A_TOT);
    cudaFuncSetAttribute(gemm_hmma_kernel<true>,  cudaFuncAttributeMaxDynamicSharedMemorySize, GSMEM);
    cudaFuncSetAttribute(gemm_hmma_kernel<false>, cudaFuncAttributeMaxDynamicSharedMemorySize, GSMEM);

    const int nx = MTOK * DIM_;
    split_kernel<<<(nx + 255) / 256, 256>>>(x, p_xhi, p_xlo, nx);
    split_kernel<<<(2304 * DIM_ + 255) / 256, 256>>>(qkv_w, p_qwhi, p_qwlo, 2304 * DIM_);
    split_kernel<<<(DIM_ * DIM_ + 255) / 256, 256>>>(proj_w, p_pwhi, p_pwlo, DIM_ * DIM_);

    bias_kernel<<<(HH * NT * NT + 255) / 256, 256>>>(table, relidx, p_bias);

    dim3 g1(2304 / 128, GMT / 256);
    gemm_hmma_kernel<true><<<g1, 512, GSMEM>>>(p_xhi, p_xlo, p_qwhi, p_qwlo, qkv_b,
                                               nullptr, p_qhi, p_qlo, 2304, GMT);

    attn_hmma_kernel<<<B_ * HH, 256, A_TOT>>>(p_qhi, p_qlo, p_bias, p_aohi, p_aolo);

    dim3 g2(DIM_ / 128, GMT / 256);
    gemm_hmma_kernel<false><<<g2, 512, GSMEM>>>(p_aohi, p_aolo, p_pwhi, p_pwlo, proj_b,
                                                out, nullptr, nullptr, DIM_, MTOK);
}

// round 9
// speedup vs baseline: 1.1575x; 1.1575x over previous
#include <cuda_runtime.h>
#include <cuda_fp16.h>
#include <cstdint>

#define B_   128
#define NT   197
#define HH   12
#define HD   64
#define DIM_ 768
#define MTOK (B_ * NT)          // 25216 = 197*128

// ---------------- scratch ----------------
__device__ __half g_qhi [(long long)MTOK * 2304];
__device__ __half g_qlo [(long long)MTOK * 2304];
__device__ __half g_xhi [(long long)MTOK * DIM_];
__device__ __half g_xlo [(long long)MTOK * DIM_];
__device__ __half g_aohi[(long long)MTOK * DIM_];
__device__ __half g_aolo[(long long)MTOK * DIM_];
__device__ __half g_qwhi[2304 * DIM_];
__device__ __half g_qwlo[2304 * DIM_];
__device__ __half g_pwhi[DIM_ * DIM_];
__device__ __half g_pwlo[DIM_ * DIM_];
__device__ float  g_bias[HH * NT * NT];

// ---------------- helpers ----------------
__device__ __forceinline__ uint32_t smem_u32(const void* p) {
    uint32_t a;
    asm("{ .reg .u64 t; cvta.to.shared.u64 t, %1; cvt.u32.u64 %0, t; }" : "=r"(a) : "l"(p));
    return a;
}

#define CPA16(dst, src)   asm volatile("cp.async.cg.shared.global [%0], [%1], 16;" :: "r"(dst), "l"(src) : "memory")
#define CPA_COMMIT()      asm volatile("cp.async.commit_group;" ::: "memory")
#define CPA_WAIT(n)       asm volatile("cp.async.wait_group %0;" :: "n"(n) : "memory")

#define LDSM_X4(r0, r1, r2, r3, addr) \
    asm volatile("ldmatrix.sync.aligned.m8n8.x4.shared.b16 {%0,%1,%2,%3}, [%4];" \
        : "=r"(r0), "=r"(r1), "=r"(r2), "=r"(r3) : "r"(addr))

#define LDSM_X2_T(r0, r1, addr) \
    asm volatile("ldmatrix.sync.aligned.m8n8.x2.trans.shared.b16 {%0,%1}, [%2];" \
        : "=r"(r0), "=r"(r1) : "r"(addr))

#define MMA16816(d, a, b0, b1) \
    asm volatile("mma.sync.aligned.m16n8k16.row.col.f32.f16.f16.f32 " \
        "{%0,%1,%2,%3}, {%4,%5,%6,%7}, {%8,%9}, {%0,%1,%2,%3};" \
        : "+f"((d)[0]), "+f"((d)[1]), "+f"((d)[2]), "+f"((d)[3]) \
        : "r"((a)[0]), "r"((a)[1]), "r"((a)[2]), "r"((a)[3]), "r"(b0), "r"(b1))

// swizzled tile offset for 64B rows (gemm tiles): chunk 0..3
__device__ __forceinline__ uint32_t sw_off(int row, int chunk) {
    return (uint32_t)(row * 64 + ((chunk ^ ((row >> 1) & 3)) << 4));
}
// swizzled offset for 128B rows (attention tiles): chunk 0..7
__device__ __forceinline__ uint32_t swb(int row, int chunk) {
    return (uint32_t)(row * 128 + ((chunk ^ (row & 7)) << 4));
}

static __device__ __forceinline__ void h_split(float v, __half& hi, __half& lo) {
    hi = __float2half_rn(v);
    lo = __float2half_rn(v - __half2float(hi));
}

// ---------------- elementwise fp16 split ----------------
__global__ void split_kernel(const float* __restrict__ in,
                             __half* __restrict__ hi, __half* __restrict__ lo, int n)
{
    int t = blockIdx.x * 256 + threadIdx.x;
    if (t < n) {
        __half h, l;
        h_split(in[t], h, l);
        hi[t] = h; lo[t] = l;
    }
}

// ---------------- bias gather ----------------
__global__ void bias_kernel(const float* __restrict__ table,
                            const int*   __restrict__ idx,
                            float* __restrict__ out)
{
    int t = blockIdx.x * blockDim.x + threadIdx.x;
    if (t < HH * NT * NT) {
        int ij = t % (NT * NT);
        int h  = t / (NT * NT);
        out[t] = table[idx[ij] * HH + h];
    }
}

// ---------------- 3xFP16 mma.sync GEMM, 3-stage pipeline (R7 config) ----------------
#define GK     768
#define NCHUNK 24
#define TILEB  8192
#define STAGEB (4 * TILEB)
#define NSTAGE 3
#define GSMEM  (NSTAGE * STAGEB)       // 96 KB

static __device__ __forceinline__ void load_stage(
    uint32_t sb, const __half* __restrict__ Ahi, const __half* __restrict__ Alo,
    const __half* __restrict__ Whi, const __half* __restrict__ Wlo,
    int m0, int n0, int k0, int tid)
{
#pragma unroll
    for (int j = 0; j < 2; j++) {
        int id = tid + (j << 8);
        int row = id >> 2, c = id & 3;
        uint32_t o = sw_off(row, c);
        size_t ga = (size_t)(m0 + row) * GK + k0 + c * 8;
        size_t gb = (size_t)(n0 + row) * GK + k0 + c * 8;
        CPA16(sb + o,             Ahi + ga);
        CPA16(sb + TILEB + o,     Alo + ga);
        CPA16(sb + 2 * TILEB + o, Whi + gb);
        CPA16(sb + 3 * TILEB + o, Wlo + gb);
    }
}

template<bool SPLIT>
__global__ __launch_bounds__(256, 2)
void gemm_hmma_kernel(const __half* __restrict__ Ahi, const __half* __restrict__ Alo,
                      const __half* __restrict__ Whi, const __half* __restrict__ Wlo,
                      const float* __restrict__ bias, float* __restrict__ C,
                      __half* __restrict__ Chi, __half* __restrict__ Clo, int Nn)
{
    extern __shared__ char dsm[];
    const int tid = threadIdx.x;
    const int lane = tid & 31;
    const int wid = tid >> 5;
    const int wm = (wid & 3) * 32;
    const int wn = (wid >> 2) * 64;
    const int m0 = blockIdx.y * 128;
    const int n0 = blockIdx.x * 128;
    const uint32_t sb = smem_u32(dsm);

    float acc[2][8][4];
#pragma unroll
    for (int mt = 0; mt < 2; mt++)
#pragma unroll
        for (int nt = 0; nt < 8; nt++)
#pragma unroll
            for (int e = 0; e < 4; e++) acc[mt][nt][e] = 0.f;

    const int a_row = lane & 15;
    const int a_kc  = lane >> 4;
    const int b_row = (lane & 7) + ((lane >> 4) << 3);
    const int b_kc  = (lane >> 3) & 1;

    load_stage(sb,          Ahi, Alo, Whi, Wlo, m0, n0, 0,  tid);
    CPA_COMMIT();
    load_stage(sb + STAGEB, Ahi, Alo, Whi, Wlo, m0, n0, 32, tid);
    CPA_COMMIT();

    int st = 0;
    for (int k = 0; k < NCHUNK; k++) {
        if (k + 1 < NCHUNK) { CPA_WAIT(1); } else { CPA_WAIT(0); }
        __syncthreads();
        if (k + 2 < NCHUNK) {
            int ls = st + 2; if (ls >= NSTAGE) ls -= NSTAGE;
            load_stage(sb + ls * STAGEB, Ahi, Alo, Whi, Wlo, m0, n0, (k + 2) * 32, tid);
            CPA_COMMIT();
        }

        const uint32_t cs  = sb + st * STAGEB;
        const uint32_t sAh = cs, sAl = cs + TILEB, sBh = cs + 2 * TILEB, sBl = cs + 3 * TILEB;

#pragma unroll
        for (int kk = 0; kk < 2; kk++) {
            const int kc = kk * 2;
            uint32_t ah[2][4], al[2][4];
#pragma unroll
            for (int mt = 0; mt < 2; mt++) {
                uint32_t o = sw_off(wm + mt * 16 + a_row, kc + a_kc);
                LDSM_X4(ah[mt][0], ah[mt][1], ah[mt][2], ah[mt][3], sAh + o);
                LDSM_X4(al[mt][0], al[mt][1], al[mt][2], al[mt][3], sAl + o);
            }
#pragma unroll
            for (int ng = 0; ng < 4; ng++) {
                uint32_t bh[4], bl[4];
                uint32_t o = sw_off(wn + ng * 16 + b_row, kc + b_kc);
                LDSM_X4(bh[0], bh[1], bh[2], bh[3], sBh + o);
                LDSM_X4(bl[0], bl[1], bl[2], bl[3], sBl + o);
#pragma unroll
                for (int mt = 0; mt < 2; mt++) {
                    MMA16816(acc[mt][ng * 2 + 0], ah[mt], bh[0], bh[1]);
                    MMA16816(acc[mt][ng * 2 + 0], ah[mt], bl[0], bl[1]);
                    MMA16816(acc[mt][ng * 2 + 0], al[mt], bh[0], bh[1]);
                    MMA16816(acc[mt][ng * 2 + 1], ah[mt], bh[2], bh[3]);
                    MMA16816(acc[mt][ng * 2 + 1], ah[mt], bl[2], bl[3]);
                    MMA16816(acc[mt][ng * 2 + 1], al[mt], bh[2], bh[3]);
                }
            }
        }
        if (++st == NSTAGE) st = 0;
    }

    const int erow = lane >> 2;
    const int ecol = (lane & 3) * 2;
#pragma unroll
    for (int mt = 0; mt < 2; mt++) {
#pragma unroll
        for (int nt = 0; nt < 8; nt++) {
            int col = n0 + wn + nt * 8 + ecol;
            float b0 = __ldg(bias + col), b1 = __ldg(bias + col + 1);
            int r0 = m0 + wm + mt * 16 + erow;
            float v00 = acc[mt][nt][0] + b0, v01 = acc[mt][nt][1] + b1;
            float v10 = acc[mt][nt][2] + b0, v11 = acc[mt][nt][3] + b1;
            if (SPLIT) {
                __half h0, l0, h1, l1;
                h_split(v00, h0, l0); h_split(v01, h1, l1);
                *(__half2*)(Chi + (size_t)r0 * Nn + col) = __halves2half2(h0, h1);
                *(__half2*)(Clo + (size_t)r0 * Nn + col) = __halves2half2(l0, l1);
                h_split(v10, h0, l0); h_split(v11, h1, l1);
                *(__half2*)(Chi + (size_t)(r0 + 8) * Nn + col) = __halves2half2(h0, h1);
                *(__half2*)(Clo + (size_t)(r0 + 8) * Nn + col) = __halves2half2(l0, l1);
            } else {
                *(float2*)(C + (size_t)r0 * Nn + col)       = make_float2(v00, v01);
                *(float2*)(C + (size_t)(r0 + 8) * Nn + col) = make_float2(v10, v11);
            }
        }
    }
}

// ---------------- HMMA attention: 512 threads (16 warps) ----------------
#define ATT    512
#define KP     256
#define VP     208
#define PSTRB  432
#define PSTRH  216
#define SSTR   258
#define A_KH   0
#define A_KL   (A_KH + KP * 128)
#define A_VH   (A_KL + KP * 128)
#define A_VL   (A_VH + VP * 128)
#define A_QH   (A_VL + VP * 128)
#define A_QL   (A_QH + 2 * 32 * 128)
#define A_S    (A_QL + 2 * 32 * 128)
#define A_PH   (A_S + 32 * SSTR * 4)
#define A_PL   (A_PH + 32 * PSTRB)
#define A_INV  (A_PL + 32 * PSTRB)
#define A_TOT  (A_INV + 128)

__global__ __launch_bounds__(ATT, 1) void attn_hmma_kernel(
    const __half* __restrict__ qhi, const __half* __restrict__ qlo,
    const float* __restrict__ bias,
    __half* __restrict__ aohi, __half* __restrict__ aolo)
{
    extern __shared__ char smb[];
    const uint32_t sb = smem_u32(smb);
    const int b = blockIdx.x / HH;
    const int h = blockIdx.x % HH;
    const int tid = threadIdx.x, lane = tid & 31, wid = tid >> 5;
    const __half* bh_ = qhi + (size_t)b * NT * 2304 + h * 64;
    const __half* bl_ = qlo + (size_t)b * NT * 2304 + h * 64;
    const float* biasH = bias + (size_t)h * NT * NT;

    for (int i = tid; i < ((KP - NT) * 128) / 4; i += ATT) {
        ((uint32_t*)(smb + A_KH + NT * 128))[i] = 0;
        ((uint32_t*)(smb + A_KL + NT * 128))[i] = 0;
    }
    for (int i = tid; i < ((VP - NT) * 128) / 4; i += ATT) {
        ((uint32_t*)(smb + A_VH + NT * 128))[i] = 0;
        ((uint32_t*)(smb + A_VL + NT * 128))[i] = 0;
    }
    for (int i = tid; i < (2 * 32 * PSTRB) / 4; i += ATT)
        ((uint32_t*)(smb + A_PH))[i] = 0;

    for (int p = tid; p < NT * 8; p += ATT) {
        int row = p >> 3, c = p & 7;
        uint32_t o = swb(row, c);
        size_t goff = (size_t)row * 2304 + 768 + c * 8;
        CPA16(sb + A_KH + o, bh_ + goff);
        CPA16(sb + A_KL + o, bl_ + goff);
        CPA16(sb + A_VH + o, bh_ + goff + 768);
        CPA16(sb + A_VL + o, bl_ + goff + 768);
    }
    for (int p = tid; p < 32 * 8; p += ATT) {
        int r = p >> 3, c = p & 7;
        int gr = (r < NT) ? r : 0;
        size_t goff = (size_t)gr * 2304 + c * 8;
        uint32_t o = swb(r, c);
        CPA16(sb + A_QH + o, bh_ + goff);
        CPA16(sb + A_QL + o, bl_ + goff);
    }
    CPA_COMMIT();
    CPA_WAIT(0);
    __syncthreads();

    const int a_row16 = lane & 15;
    const int a_kc1   = lane >> 4;
    const int b_row8  = (lane & 7) + ((lane >> 4) << 3);
    const int b_kc1   = (lane >> 3) & 1;

    for (int qt = 0; qt < 7; qt++) {
        const int r0 = qt * 32;
        const int rows = min(32, NT - r0);
        const uint32_t qbuf = (uint32_t)((qt & 1) * 4096);

        // ---- S = 0.125 * Q K^T + bias : 16 warps, each 16x32 ----
        {
            const int wm = (wid & 1) * 16;
            const int wn = (wid >> 1) * 32;
            float acc[4][4];
#pragma unroll
            for (int t = 0; t < 4; t++)
#pragma unroll
                for (int e = 0; e < 4; e++) acc[t][e] = 0.f;

            const int ar = wm + a_row16;
#pragma unroll
            for (int kk = 0; kk < 4; kk++) {
                uint32_t aoff = swb(ar, kk * 2 + a_kc1) + qbuf;
                uint32_t ah[4], al[4];
                LDSM_X4(ah[0], ah[1], ah[2], ah[3], sb + A_QH + aoff);
                LDSM_X4(al[0], al[1], al[2], al[3], sb + A_QL + aoff);
#pragma unroll
                for (int ng = 0; ng < 2; ng++) {
                    uint32_t boff = swb(wn + ng * 16 + b_row8, kk * 2 + b_kc1);
                    uint32_t bh[4], bl[4];
                    LDSM_X4(bh[0], bh[1], bh[2], bh[3], sb + A_KH + boff);
                    LDSM_X4(bl[0], bl[1], bl[2], bl[3], sb + A_KL + boff);
                    MMA16816(acc[ng * 2 + 0], ah, bh[0], bh[1]);
                    MMA16816(acc[ng * 2 + 0], ah, bl[0], bl[1]);
                    MMA16816(acc[ng * 2 + 0], al, bh[0], bh[1]);
                    MMA16816(acc[ng * 2 + 1], ah, bh[2], bh[3]);
                    MMA16816(acc[ng * 2 + 1], ah, bl[2], bl[3]);
                    MMA16816(acc[ng * 2 + 1], al, bh[2], bh[3]);
                }
            }
            const int erow = wm + (lane >> 2);
            const int ecol = (lane & 3) * 2;
            float* S = (float*)(smb + A_S);
#pragma unroll
            for (int nt = 0; nt < 4; nt++) {
                int col = wn + nt * 8 + ecol;
                float b00 = 0.f, b01 = 0.f, b10 = 0.f, b11 = 0.f;
                if (col < NT) {
                    int gr0 = r0 + erow, gr1 = r0 + erow + 8;
                    bool c1 = (col + 1 < NT);
                    if (gr0 < NT) {
                        b00 = biasH[(size_t)gr0 * NT + col];
                        if (c1) b01 = biasH[(size_t)gr0 * NT + col + 1];
                    }
                    if (gr1 < NT) {
                        b10 = biasH[(size_t)gr1 * NT + col];
                        if (c1) b11 = biasH[(size_t)gr1 * NT + col + 1];
                    }
                }
                *(float2*)(S + erow * SSTR + col) =
                    make_float2(acc[nt][0] * 0.125f + b00, acc[nt][1] * 0.125f + b01);
                *(float2*)(S + (erow + 8) * SSTR + col) =
                    make_float2(acc[nt][2] * 0.125f + b10, acc[nt][3] * 0.125f + b11);
            }
        }
        __syncthreads();

        if (qt + 1 < 7) {
            const int nr0 = (qt + 1) * 32;
            const uint32_t nqb = (uint32_t)(((qt + 1) & 1) * 4096);
            for (int p = tid; p < 32 * 8; p += ATT) {
                int r = p >> 3, c = p & 7;
                int gr = (nr0 + r < NT) ? (nr0 + r) : 0;
                size_t goff = (size_t)gr * 2304 + c * 8;
                uint32_t o = swb(r, c) + nqb;
                CPA16(sb + A_QH + o, bh_ + goff);
                CPA16(sb + A_QL + o, bl_ + goff);
            }
            CPA_COMMIT();
        }

        // ---- softmax: 2 rows per warp ----
        {
            float* S = (float*)(smb + A_S);
            __half* PH = (__half*)(smb + A_PH);
            __half* PL = (__half*)(smb + A_PL);
            float* INV = (float*)(smb + A_INV);
#pragma unroll
            for (int i = 0; i < 2; i++) {
                int r = wid * 2 + i;
                if (r < rows) {
                    float m = -3.4e38f;
                    for (int c = lane; c < NT; c += 32) m = fmaxf(m, S[r * SSTR + c]);
#pragma unroll
                    for (int o = 16; o > 0; o >>= 1) m = fmaxf(m, __shfl_xor_sync(0xffffffffu, m, o));
                    float s = 0.f;
                    for (int c = lane; c < NT; c += 32) {
                        float e = __expf(S[r * SSTR + c] - m);
                        s += e;
                        __half eh, el;
                        h_split(e, eh, el);
                        PH[r * PSTRH + c] = eh;
                        PL[r * PSTRH + c] = el;
                    }
#pragma unroll
                    for (int o = 16; o > 0; o >>= 1) s += __shfl_xor_sync(0xffffffffu, s, o);
                    if (lane == 0) INV[r] = 1.f / s;
                }
            }
        }
        __syncthreads();

        // ---- AV = P V : 16 warps, each 16x8 (V via ldmatrix.x2.trans) ----
        {
            const int wm = (wid & 1) * 16;
            const int wd = (wid >> 1) * 8;
            float acc[4];
#pragma unroll
            for (int e = 0; e < 4; e++) acc[e] = 0.f;

            const int ar = wm + a_row16;
#pragma unroll
            for (int kk = 0; kk < 13; kk++) {
                uint32_t aoff = (uint32_t)(ar * PSTRB + (kk * 2 + a_kc1) * 16);
                uint32_t ah[4], al[4];
                LDSM_X4(ah[0], ah[1], ah[2], ah[3], sb + A_PH + aoff);
                LDSM_X4(al[0], al[1], al[2], al[3], sb + A_PL + aoff);
                uint32_t boff = swb(kk * 16 + (lane & 15), wd >> 3);
                uint32_t bh0, bh1, bl0, bl1;
                LDSM_X2_T(bh0, bh1, sb + A_VH + boff);
                LDSM_X2_T(bl0, bl1, sb + A_VL + boff);
                MMA16816(acc, ah, bh0, bh1);
                MMA16816(acc, ah, bl0, bl1);
                MMA16816(acc, al, bh0, bh1);
            }
            const int erow = wm + (lane >> 2);
            const int ec = (lane & 3) * 2;
            float* INV = (float*)(smb + A_INV);
#pragma unroll
            for (int hf = 0; hf < 2; hf++) {
                int rr = erow + hf * 8;
                if (rr < rows) {
                    float inv = INV[rr];
                    size_t gb = ((size_t)b * NT + r0 + rr) * DIM_ + h * 64 + wd;
                    __half h0, l0, h1, l1;
                    h_split(acc[hf * 2 + 0] * inv, h0, l0);
                    h_split(acc[hf * 2 + 1] * inv, h1, l1);
                    *(__half2*)(aohi + gb + ec) = __halves2half2(h0, h1);
                    *(__half2*)(aolo + gb + ec) = __halves2half2(l0, l1);
                }
            }
        }
        if (qt + 1 < 7) { CPA_WAIT(0); }
        __syncthreads();
    }
}

// ---------------- launch ----------------
extern "C" void kernel_launch(void* const* d_in, const int* in_sizes, int n_in,
                              void* d_out, int out_size)
{
    const float* x      = (const float*)d_in[0];
    const float* qkv_w  = (const float*)d_in[1];
    const float* qkv_b  = (const float*)d_in[2];
    const float* proj_w = (const float*)d_in[3];
    const float* proj_b = (const float*)d_in[4];
    const float* table  = (const float*)d_in[5];
    const int*   relidx = (const int*)d_in[6];
    float* out = (float*)d_out;

    float *p_bias;
    __half *p_qhi, *p_qlo, *p_xhi, *p_xlo, *p_aohi, *p_aolo;
    __half *p_qwhi, *p_qwlo, *p_pwhi, *p_pwlo;
    cudaGetSymbolAddress((void**)&p_qhi,  g_qhi);
    cudaGetSymbolAddress((void**)&p_qlo,  g_qlo);
    cudaGetSymbolAddress((void**)&p_xhi,  g_xhi);
    cudaGetSymbolAddress((void**)&p_xlo,  g_xlo);
    cudaGetSymbolAddress((void**)&p_aohi, g_aohi);
    cudaGetSymbolAddress((void**)&p_aolo, g_aolo);
    cudaGetSymbolAddress((void**)&p_qwhi, g_qwhi);
    cudaGetSymbolAddress((void**)&p_qwlo, g_qwlo);
    cudaGetSymbolAddress((void**)&p_pwhi, g_pwhi);
    cudaGetSymbolAddress((void**)&p_pwlo, g_pwlo);
    cudaGetSymbolAddress((void**)&p_bias, g_bias);

    cudaFuncSetAttribute(attn_hmma_kernel, cudaFuncAttributeMaxDynamicSharedMemorySize, A_TOT);
    cudaFuncSetAttribute(gemm_hmma_kernel<true>,  cudaFuncAttributeMaxDynamicSharedMemorySize, GSMEM);
    cudaFuncSetAttribute(gemm_hmma_kernel<false>, cudaFuncAttributeMaxDynamicSharedMemorySize, GSMEM);

    const int nx = MTOK * DIM_;
    split_kernel<<<(nx + 255) / 256, 256>>>(x, p_xhi, p_xlo, nx);
    split_kernel<<<(2304 * DIM_ + 255) / 256, 256>>>(qkv_w, p_qwhi, p_qwlo, 2304 * DIM_);
    split_kernel<<<(DIM_ * DIM_ + 255) / 256, 256>>>(proj_w, p_pwhi, p_pwlo, DIM_ * DIM_);

    bias_kernel<<<(HH * NT * NT + 255) / 256, 256>>>(table, relidx, p_bias);

    dim3 g1(2304 / 128, MTOK / 128);
    gemm_hmma_kernel<true><<<g1, 256, GSMEM>>>(p_xhi, p_xlo, p_qwhi, p_qwlo, qkv_b,
                                               nullptr, p_qhi, p_qlo, 2304);

    attn_hmma_kernel<<<B_ * HH, ATT, A_TOT>>>(p_qhi, p_qlo, p_bias, p_aohi, p_aolo);

    dim3 g2(DIM_ / 128, MTOK / 128);
    gemm_hmma_kernel<false><<<g2, 256, GSMEM>>>(p_aohi, p_aolo, p_pwhi, p_pwlo, proj_b,
                                                out, nullptr, nullptr, DIM_);
}

// round 10
// speedup vs baseline: 1.1764x; 1.0164x over previous
#include <cuda_runtime.h>
#include <cuda_fp16.h>
#include <cstdint>

#define B_   128
#define NT   197
#define HH   12
#define HD   64
#define DIM_ 768
#define MTOK (B_ * NT)          // 25216 = 197*128

// ---------------- scratch ----------------
__device__ __half g_qhi [(long long)MTOK * 2304];
__device__ __half g_qlo [(long long)MTOK * 2304];
__device__ __half g_xhi [(long long)MTOK * DIM_];
__device__ __half g_xlo [(long long)MTOK * DIM_];
__device__ __half g_aohi[(long long)MTOK * DIM_];
__device__ __half g_aolo[(long long)MTOK * DIM_];
__device__ __half g_qwhi[2304 * DIM_];
__device__ __half g_qwlo[2304 * DIM_];
__device__ __half g_pwhi[DIM_ * DIM_];
__device__ __half g_pwlo[DIM_ * DIM_];
__device__ float  g_bias[HH * NT * NT];

// ---------------- helpers ----------------
__device__ __forceinline__ uint32_t smem_u32(const void* p) {
    uint32_t a;
    asm("{ .reg .u64 t; cvta.to.shared.u64 t, %1; cvt.u32.u64 %0, t; }" : "=r"(a) : "l"(p));
    return a;
}

#define CPA16(dst, src)   asm volatile("cp.async.cg.shared.global [%0], [%1], 16;" :: "r"(dst), "l"(src) : "memory")
#define CPA_COMMIT()      asm volatile("cp.async.commit_group;" ::: "memory")
#define CPA_WAIT(n)       asm volatile("cp.async.wait_group %0;" :: "n"(n) : "memory")

#define LDSM_X4(r0, r1, r2, r3, addr) \
    asm volatile("ldmatrix.sync.aligned.m8n8.x4.shared.b16 {%0,%1,%2,%3}, [%4];" \
        : "=r"(r0), "=r"(r1), "=r"(r2), "=r"(r3) : "r"(addr))

#define LDSM_X2_T(r0, r1, addr) \
    asm volatile("ldmatrix.sync.aligned.m8n8.x2.trans.shared.b16 {%0,%1}, [%2];" \
        : "=r"(r0), "=r"(r1) : "r"(addr))

#define MMA16816(d, a, b0, b1) \
    asm volatile("mma.sync.aligned.m16n8k16.row.col.f32.f16.f16.f32 " \
        "{%0,%1,%2,%3}, {%4,%5,%6,%7}, {%8,%9}, {%0,%1,%2,%3};" \
        : "+f"((d)[0]), "+f"((d)[1]), "+f"((d)[2]), "+f"((d)[3]) \
        : "r"((a)[0]), "r"((a)[1]), "r"((a)[2]), "r"((a)[3]), "r"(b0), "r"(b1))

// swizzled tile offset for 64B rows (gemm tiles): chunk 0..3
__device__ __forceinline__ uint32_t sw_off(int row, int chunk) {
    return (uint32_t)(row * 64 + ((chunk ^ ((row >> 1) & 3)) << 4));
}
// swizzled offset for 128B rows (attention tiles): chunk 0..7
__device__ __forceinline__ uint32_t swb(int row, int chunk) {
    return (uint32_t)(row * 128 + ((chunk ^ (row & 7)) << 4));
}

static __device__ __forceinline__ void h_split(float v, __half& hi, __half& lo) {
    hi = __float2half_rn(v);
    lo = __float2half_rn(v - __half2float(hi));
}

// ---------------- merged elementwise fp16 split (3 arrays, 1 launch) ----------------
__global__ void split3_kernel(const float* __restrict__ in0, __half* __restrict__ hi0, __half* __restrict__ lo0, int n0,
                              const float* __restrict__ in1, __half* __restrict__ hi1, __half* __restrict__ lo1, int n1,
                              const float* __restrict__ in2, __half* __restrict__ hi2, __half* __restrict__ lo2, int n2)
{
    int t = blockIdx.x * 256 + threadIdx.x;
    const float* in; __half *hi, *lo;
    if (t < n0)               { in = in0;  hi = hi0; lo = lo0; }
    else if (t < n0 + n1)     { t -= n0;       in = in1; hi = hi1; lo = lo1; }
    else if (t < n0 + n1 + n2){ t -= n0 + n1;  in = in2; hi = hi2; lo = lo2; }
    else return;
    __half h, l;
    h_split(in[t], h, l);
    hi[t] = h; lo[t] = l;
}

// ---------------- bias gather ----------------
__global__ void bias_kernel(const float* __restrict__ table,
                            const int*   __restrict__ idx,
                            float* __restrict__ out)
{
    int t = blockIdx.x * blockDim.x + threadIdx.x;
    if (t < HH * NT * NT) {
        int ij = t % (NT * NT);
        int h  = t / (NT * NT);
        out[t] = table[idx[ij] * HH + h];
    }
}

// ---------------- 3xFP16 mma.sync GEMM, 3-stage pipeline (R7 config, unchanged) ----------------
#define GK     768
#define NCHUNK 24
#define TILEB  8192
#define STAGEB (4 * TILEB)
#define NSTAGE 3
#define GSMEM  (NSTAGE * STAGEB)       // 96 KB

static __device__ __forceinline__ void load_stage(
    uint32_t sb, const __half* __restrict__ Ahi, const __half* __restrict__ Alo,
    const __half* __restrict__ Whi, const __half* __restrict__ Wlo,
    int m0, int n0, int k0, int tid)
{
#pragma unroll
    for (int j = 0; j < 2; j++) {
        int id = tid + (j << 8);
        int row = id >> 2, c = id & 3;
        uint32_t o = sw_off(row, c);
        size_t ga = (size_t)(m0 + row) * GK + k0 + c * 8;
        size_t gb = (size_t)(n0 + row) * GK + k0 + c * 8;
        CPA16(sb + o,             Ahi + ga);
        CPA16(sb + TILEB + o,     Alo + ga);
        CPA16(sb + 2 * TILEB + o, Whi + gb);
        CPA16(sb + 3 * TILEB + o, Wlo + gb);
    }
}

template<bool SPLIT>
__global__ __launch_bounds__(256, 2)
void gemm_hmma_kernel(const __half* __restrict__ Ahi, const __half* __restrict__ Alo,
                      const __half* __restrict__ Whi, const __half* __restrict__ Wlo,
                      const float* __restrict__ bias, float* __restrict__ C,
                      __half* __restrict__ Chi, __half* __restrict__ Clo, int Nn)
{
    extern __shared__ char dsm[];
    const int tid = threadIdx.x;
    const int lane = tid & 31;
    const int wid = tid >> 5;
    const int wm = (wid & 3) * 32;
    const int wn = (wid >> 2) * 64;
    const int m0 = blockIdx.y * 128;
    const int n0 = blockIdx.x * 128;
    const uint32_t sb = smem_u32(dsm);

    float acc[2][8][4];
#pragma unroll
    for (int mt = 0; mt < 2; mt++)
#pragma unroll
        for (int nt = 0; nt < 8; nt++)
#pragma unroll
            for (int e = 0; e < 4; e++) acc[mt][nt][e] = 0.f;

    const int a_row = lane & 15;
    const int a_kc  = lane >> 4;
    const int b_row = (lane & 7) + ((lane >> 4) << 3);
    const int b_kc  = (lane >> 3) & 1;

    load_stage(sb,          Ahi, Alo, Whi, Wlo, m0, n0, 0,  tid);
    CPA_COMMIT();
    load_stage(sb + STAGEB, Ahi, Alo, Whi, Wlo, m0, n0, 32, tid);
    CPA_COMMIT();

    int st = 0;
    for (int k = 0; k < NCHUNK; k++) {
        if (k + 1 < NCHUNK) { CPA_WAIT(1); } else { CPA_WAIT(0); }
        __syncthreads();
        if (k + 2 < NCHUNK) {
            int ls = st + 2; if (ls >= NSTAGE) ls -= NSTAGE;
            load_stage(sb + ls * STAGEB, Ahi, Alo, Whi, Wlo, m0, n0, (k + 2) * 32, tid);
            CPA_COMMIT();
        }

        const uint32_t cs  = sb + st * STAGEB;
        const uint32_t sAh = cs, sAl = cs + TILEB, sBh = cs + 2 * TILEB, sBl = cs + 3 * TILEB;

#pragma unroll
        for (int kk = 0; kk < 2; kk++) {
            const int kc = kk * 2;
            uint32_t ah[2][4], al[2][4];
#pragma unroll
            for (int mt = 0; mt < 2; mt++) {
                uint32_t o = sw_off(wm + mt * 16 + a_row, kc + a_kc);
                LDSM_X4(ah[mt][0], ah[mt][1], ah[mt][2], ah[mt][3], sAh + o);
                LDSM_X4(al[mt][0], al[mt][1], al[mt][2], al[mt][3], sAl + o);
            }
#pragma unroll
            for (int ng = 0; ng < 4; ng++) {
                uint32_t bh[4], bl[4];
                uint32_t o = sw_off(wn + ng * 16 + b_row, kc + b_kc);
                LDSM_X4(bh[0], bh[1], bh[2], bh[3], sBh + o);
                LDSM_X4(bl[0], bl[1], bl[2], bl[3], sBl + o);
#pragma unroll
                for (int mt = 0; mt < 2; mt++) {
                    MMA16816(acc[mt][ng * 2 + 0], ah[mt], bh[0], bh[1]);
                    MMA16816(acc[mt][ng * 2 + 0], ah[mt], bl[0], bl[1]);
                    MMA16816(acc[mt][ng * 2 + 0], al[mt], bh[0], bh[1]);
                    MMA16816(acc[mt][ng * 2 + 1], ah[mt], bh[2], bh[3]);
                    MMA16816(acc[mt][ng * 2 + 1], ah[mt], bl[2], bl[3]);
                    MMA16816(acc[mt][ng * 2 + 1], al[mt], bh[2], bh[3]);
                }
            }
        }
        if (++st == NSTAGE) st = 0;
    }

    const int erow = lane >> 2;
    const int ecol = (lane & 3) * 2;
#pragma unroll
    for (int mt = 0; mt < 2; mt++) {
#pragma unroll
        for (int nt = 0; nt < 8; nt++) {
            int col = n0 + wn + nt * 8 + ecol;
            float b0 = __ldg(bias + col), b1 = __ldg(bias + col + 1);
            int r0 = m0 + wm + mt * 16 + erow;
            float v00 = acc[mt][nt][0] + b0, v01 = acc[mt][nt][1] + b1;
            float v10 = acc[mt][nt][2] + b0, v11 = acc[mt][nt][3] + b1;
            if (SPLIT) {
                __half h0, l0, h1, l1;
                h_split(v00, h0, l0); h_split(v01, h1, l1);
                *(__half2*)(Chi + (size_t)r0 * Nn + col) = __halves2half2(h0, h1);
                *(__half2*)(Clo + (size_t)r0 * Nn + col) = __halves2half2(l0, l1);
                h_split(v10, h0, l0); h_split(v11, h1, l1);
                *(__half2*)(Chi + (size_t)(r0 + 8) * Nn + col) = __halves2half2(h0, h1);
                *(__half2*)(Clo + (size_t)(r0 + 8) * Nn + col) = __halves2half2(l0, l1);
            } else {
                *(float2*)(C + (size_t)r0 * Nn + col)       = make_float2(v00, v01);
                *(float2*)(C + (size_t)(r0 + 8) * Nn + col) = make_float2(v10, v11);
            }
        }
    }
}

// ---------------- HMMA attention: 512 threads, KP=224, V_hi register-hoisted ----------------
#define ATT    512
#define KP     224
#define VP     208
#define PSTRB  432
#define PSTRH  216
#define SSTR   258
#define A_KH   0
#define A_KL   (A_KH + KP * 128)
#define A_VH   (A_KL + KP * 128)
#define A_VL   (A_VH + VP * 128)
#define A_QH   (A_VL + VP * 128)
#define A_QL   (A_QH + 2 * 32 * 128)
#define A_S    (A_QL + 2 * 32 * 128)
#define A_PH   (A_S + 32 * SSTR * 4)
#define A_PL   (A_PH + 32 * PSTRB)
#define A_INV  (A_PL + 32 * PSTRB)
#define A_TOT  (A_INV + 128)

__global__ __launch_bounds__(ATT, 1) void attn_hmma_kernel(
    const __half* __restrict__ qhi, const __half* __restrict__ qlo,
    const float* __restrict__ bias,
    __half* __restrict__ aohi, __half* __restrict__ aolo)
{
    extern __shared__ char smb[];
    const uint32_t sb = smem_u32(smb);
    const int b = blockIdx.x / HH;
    const int h = blockIdx.x % HH;
    const int tid = threadIdx.x, lane = tid & 31, wid = tid >> 5;
    const __half* bh_ = qhi + (size_t)b * NT * 2304 + h * 64;
    const __half* bl_ = qlo + (size_t)b * NT * 2304 + h * 64;
    const float* biasH = bias + (size_t)h * NT * NT;

    for (int i = tid; i < ((KP - NT) * 128) / 4; i += ATT) {
        ((uint32_t*)(smb + A_KH + NT * 128))[i] = 0;
        ((uint32_t*)(smb + A_KL + NT * 128))[i] = 0;
    }
    for (int i = tid; i < ((VP - NT) * 128) / 4; i += ATT) {
        ((uint32_t*)(smb + A_VH + NT * 128))[i] = 0;
        ((uint32_t*)(smb + A_VL + NT * 128))[i] = 0;
    }
    for (int i = tid; i < (2 * 32 * PSTRB) / 4; i += ATT)
        ((uint32_t*)(smb + A_PH))[i] = 0;

    for (int p = tid; p < NT * 8; p += ATT) {
        int row = p >> 3, c = p & 7;
        uint32_t o = swb(row, c);
        size_t goff = (size_t)row * 2304 + 768 + c * 8;
        CPA16(sb + A_KH + o, bh_ + goff);
        CPA16(sb + A_KL + o, bl_ + goff);
        CPA16(sb + A_VH + o, bh_ + goff + 768);
        CPA16(sb + A_VL + o, bl_ + goff + 768);
    }
    for (int p = tid; p < 32 * 8; p += ATT) {
        int r = p >> 3, c = p & 7;
        int gr = (r < NT) ? r : 0;
        size_t goff = (size_t)gr * 2304 + c * 8;
        uint32_t o = swb(r, c);
        CPA16(sb + A_QH + o, bh_ + goff);
        CPA16(sb + A_QL + o, bl_ + goff);
    }
    CPA_COMMIT();
    CPA_WAIT(0);
    __syncthreads();

    const int a_row16 = lane & 15;
    const int a_kc1   = lane >> 4;
    const int b_row8  = (lane & 7) + ((lane >> 4) << 3);
    const int b_kc1   = (lane >> 3) & 1;

    // AV warp geometry (fixed across qt)
    const int av_wm = (wid & 1) * 16;
    const int av_wd = (wid >> 1) * 8;

    // hoist V_hi fragments (q-tile-invariant): 13 kk x 2 regs
    uint32_t vfh[13][2];
#pragma unroll
    for (int kk = 0; kk < 13; kk++) {
        uint32_t boff = swb(kk * 16 + (lane & 15), av_wd >> 3);
        LDSM_X2_T(vfh[kk][0], vfh[kk][1], sb + A_VH + boff);
    }

    for (int qt = 0; qt < 7; qt++) {
        const int r0 = qt * 32;
        const int rows = min(32, NT - r0);
        const uint32_t qbuf = (uint32_t)((qt & 1) * 4096);

        // ---- S = 0.125 * Q K^T + bias : 14 warps, each 16x32 over 224 keys ----
        if (wid < 14) {
            const int wm = (wid & 1) * 16;
            const int wn = (wid >> 1) * 32;
            float acc[4][4];
#pragma unroll
            for (int t = 0; t < 4; t++)
#pragma unroll
                for (int e = 0; e < 4; e++) acc[t][e] = 0.f;

            const int ar = wm + a_row16;
#pragma unroll
            for (int kk = 0; kk < 4; kk++) {
                uint32_t aoff = swb(ar, kk * 2 + a_kc1) + qbuf;
                uint32_t ah[4], al[4];
                LDSM_X4(ah[0], ah[1], ah[2], ah[3], sb + A_QH + aoff);
                LDSM_X4(al[0], al[1], al[2], al[3], sb + A_QL + aoff);
#pragma unroll
                for (int ng = 0; ng < 2; ng++) {
                    uint32_t boff = swb(wn + ng * 16 + b_row8, kk * 2 + b_kc1);
                    uint32_t bh[4], bl[4];
                    LDSM_X4(bh[0], bh[1], bh[2], bh[3], sb + A_KH + boff);
                    LDSM_X4(bl[0], bl[1], bl[2], bl[3], sb + A_KL + boff);
                    MMA16816(acc[ng * 2 + 0], ah, bh[0], bh[1]);
                    MMA16816(acc[ng * 2 + 0], ah, bl[0], bl[1]);
                    MMA16816(acc[ng * 2 + 0], al, bh[0], bh[1]);
                    MMA16816(acc[ng * 2 + 1], ah, bh[2], bh[3]);
                    MMA16816(acc[ng * 2 + 1], ah, bl[2], bl[3]);
                    MMA16816(acc[ng * 2 + 1], al, bh[2], bh[3]);
                }
            }
            const int erow = wm + (lane >> 2);
            const int ecol = (lane & 3) * 2;
            float* S = (float*)(smb + A_S);
#pragma unroll
            for (int nt = 0; nt < 4; nt++) {
                int col = wn + nt * 8 + ecol;
                float b00 = 0.f, b01 = 0.f, b10 = 0.f, b11 = 0.f;
                if (col < NT) {
                    int gr0 = r0 + erow, gr1 = r0 + erow + 8;
                    bool c1 = (col + 1 < NT);
                    if (gr0 < NT) {
                        b00 = biasH[(size_t)gr0 * NT + col];
                        if (c1) b01 = biasH[(size_t)gr0 * NT + col + 1];
                    }
                    if (gr1 < NT) {
                        b10 = biasH[(size_t)gr1 * NT + col];
                        if (c1) b11 = biasH[(size_t)gr1 * NT + col + 1];
                    }
                }
                *(float2*)(S + erow * SSTR + col) =
                    make_float2(acc[nt][0] * 0.125f + b00, acc[nt][1] * 0.125f + b01);
                *(float2*)(S + (erow + 8) * SSTR + col) =
                    make_float2(acc[nt][2] * 0.125f + b10, acc[nt][3] * 0.125f + b11);
            }
        }
        __syncthreads();

        if (qt + 1 < 7) {
            const int nr0 = (qt + 1) * 32;
            const uint32_t nqb = (uint32_t)(((qt + 1) & 1) * 4096);
            for (int p = tid; p < 32 * 8; p += ATT) {
                int r = p >> 3, c = p & 7;
                int gr = (nr0 + r < NT) ? (nr0 + r) : 0;
                size_t goff = (size_t)gr * 2304 + c * 8;
                uint32_t o = swb(r, c) + nqb;
                CPA16(sb + A_QH + o, bh_ + goff);
                CPA16(sb + A_QL + o, bl_ + goff);
            }
            CPA_COMMIT();
        }

        // ---- softmax: 2 rows per warp ----
        {
            float* S = (float*)(smb + A_S);
            __half* PH = (__half*)(smb + A_PH);
            __half* PL = (__half*)(smb + A_PL);
            float* INV = (float*)(smb + A_INV);
#pragma unroll
            for (int i = 0; i < 2; i++) {
                int r = wid * 2 + i;
                if (r < rows) {
                    float m = -3.4e38f;
                    for (int c = lane; c < NT; c += 32) m = fmaxf(m, S[r * SSTR + c]);
#pragma unroll
                    for (int o = 16; o > 0; o >>= 1) m = fmaxf(m, __shfl_xor_sync(0xffffffffu, m, o));
                    float s = 0.f;
                    for (int c = lane; c < NT; c += 32) {
                        float e = __expf(S[r * SSTR + c] - m);
                        s += e;
                        __half eh, el;
                        h_split(e, eh, el);
                        PH[r * PSTRH + c] = eh;
                        PL[r * PSTRH + c] = el;
                    }
#pragma unroll
                    for (int o = 16; o > 0; o >>= 1) s += __shfl_xor_sync(0xffffffffu, s, o);
                    if (lane == 0) INV[r] = 1.f / s;
                }
            }
        }
        __syncthreads();

        // ---- AV = P V : 16 warps, each 16x8; V_hi from registers ----
        {
            float acc[4];
#pragma unroll
            for (int e = 0; e < 4; e++) acc[e] = 0.f;

            const int ar = av_wm + a_row16;
#pragma unroll
            for (int kk = 0; kk < 13; kk++) {
                uint32_t aoff = (uint32_t)(ar * PSTRB + (kk * 2 + a_kc1) * 16);
                uint32_t ah[4], al[4];
                LDSM_X4(ah[0], ah[1], ah[2], ah[3], sb + A_PH + aoff);
                LDSM_X4(al[0], al[1], al[2], al[3], sb + A_PL + aoff);
                uint32_t boff = swb(kk * 16 + (lane & 15), av_wd >> 3);
                uint32_t bl0, bl1;
                LDSM_X2_T(bl0, bl1, sb + A_VL + boff);
                MMA16816(acc, ah, vfh[kk][0], vfh[kk][1]);
                MMA16816(acc, ah, bl0, bl1);
                MMA16816(acc, al, vfh[kk][0], vfh[kk][1]);
            }
            const int erow = av_wm + (lane >> 2);
            const int ec = (lane & 3) * 2;
            float* INV = (float*)(smb + A_INV);
#pragma unroll
            for (int hf = 0; hf < 2; hf++) {
                int rr = erow + hf * 8;
                if (rr < rows) {
                    float inv = INV[rr];
                    size_t gb = ((size_t)b * NT + r0 + rr) * DIM_ + h * 64 + av_wd;
                    __half h0, l0, h1, l1;
                    h_split(acc[hf * 2 + 0] * inv, h0, l0);
                    h_split(acc[hf * 2 + 1] * inv, h1, l1);
                    *(__half2*)(aohi + gb + ec) = __halves2half2(h0, h1);
                    *(__half2*)(aolo + gb + ec) = __halves2half2(l0, l1);
                }
            }
        }
        if (qt + 1 < 7) { CPA_WAIT(0); }
        __syncthreads();
    }
}

// ---------------- launch ----------------
extern "C" void kernel_launch(void* const* d_in, const int* in_sizes, int n_in,
                              void* d_out, int out_size)
{
    const float* x      = (const float*)d_in[0];
    const float* qkv_w  = (const float*)d_in[1];
    const float* qkv_b  = (const float*)d_in[2];
    const float* proj_w = (const float*)d_in[3];
    const float* proj_b = (const float*)d_in[4];
    const float* table  = (const float*)d_in[5];
    const int*   relidx = (const int*)d_in[6];
    float* out = (float*)d_out;

    float *p_bias;
    __half *p_qhi, *p_qlo, *p_xhi, *p_xlo, *p_aohi, *p_aolo;
    __half *p_qwhi, *p_qwlo, *p_pwhi, *p_pwlo;
    cudaGetSymbolAddress((void**)&p_qhi,  g_qhi);
    cudaGetSymbolAddress((void**)&p_qlo,  g_qlo);
    cudaGetSymbolAddress((void**)&p_xhi,  g_xhi);
    cudaGetSymbolAddress((void**)&p_xlo,  g_xlo);
    cudaGetSymbolAddress((void**)&p_aohi, g_aohi);
    cudaGetSymbolAddress((void**)&p_aolo, g_aolo);
    cudaGetSymbolAddress((void**)&p_qwhi, g_qwhi);
    cudaGetSymbolAddress((void**)&p_qwlo, g_qwlo);
    cudaGetSymbolAddress((void**)&p_pwhi, g_pwhi);
    cudaGetSymbolAddress((void**)&p_pwlo, g_pwlo);
    cudaGetSymbolAddress((void**)&p_bias, g_bias);

    cudaFuncSetAttribute(attn_hmma_kernel, cudaFuncAttributeMaxDynamicSharedMemorySize, A_TOT);
    cudaFuncSetAttribute(gemm_hmma_kernel<true>,  cudaFuncAttributeMaxDynamicSharedMemorySize, GSMEM);
    cudaFuncSetAttribute(gemm_hmma_kernel<false>, cudaFuncAttributeMaxDynamicSharedMemorySize, GSMEM);

    const int n0 = MTOK * DIM_;
    const int n1 = 2304 * DIM_;
    const int n2 = DIM_ * DIM_;
    split3_kernel<<<(n0 + n1 + n2 + 255) / 256, 256>>>(
        x, p_xhi, p_xlo, n0,
        qkv_w, p_qwhi, p_qwlo, n1,
        proj_w, p_pwhi, p_pwlo, n2);

    bias_kernel<<<(HH * NT * NT + 255) / 256, 256>>>(table, relidx, p_bias);

    dim3 g1(2304 / 128, MTOK / 128);
    gemm_hmma_kernel<true><<<g1, 256, GSMEM>>>(p_xhi, p_xlo, p_qwhi, p_qwlo, qkv_b,
                                               nullptr, p_qhi, p_qlo, 2304);

    attn_hmma_kernel<<<B_ * HH, ATT, A_TOT>>>(p_qhi, p_qlo, p_bias, p_aohi, p_aolo);

    dim3 g2(DIM_ / 128, MTOK / 128);
    gemm_hmma_kernel<false><<<g2, 256, GSMEM>>>(p_aohi, p_aolo, p_pwhi, p_pwlo, proj_b,
                                                out, nullptr, nullptr, DIM_);
}

// round 11
// speedup vs baseline: 1.2634x; 1.0739x over previous
#include <cuda_runtime.h>
#include <cuda_fp16.h>
#include <cstdint>

#define B_   128
#define NT   197
#define HH   12
#define HD   64
#define DIM_ 768
#define MTOK (B_ * NT)          // 25216 = 197*128

// ---------------- scratch ----------------
__device__ __half g_qhi [(long long)MTOK * 2304];
__device__ __half g_qlo [(long long)MTOK * 2304];
__device__ __half g_xhi [(long long)MTOK * DIM_];
__device__ __half g_xlo [(long long)MTOK * DIM_];
__device__ __half g_aohi[(long long)MTOK * DIM_];
__device__ __half g_aolo[(long long)MTOK * DIM_];
__device__ __half g_qwhi[2304 * DIM_];
__device__ __half g_qwlo[2304 * DIM_];
__device__ __half g_pwhi[DIM_ * DIM_];
__device__ __half g_pwlo[DIM_ * DIM_];
__device__ float  g_bias[HH * NT * NT];

// ---------------- helpers ----------------
__device__ __forceinline__ uint32_t smem_u32(const void* p) {
    uint32_t a;
    asm("{ .reg .u64 t; cvta.to.shared.u64 t, %1; cvt.u32.u64 %0, t; }" : "=r"(a) : "l"(p));
    return a;
}

#define CPA16(dst, src)   asm volatile("cp.async.cg.shared.global [%0], [%1], 16;" :: "r"(dst), "l"(src) : "memory")
#define CPA_COMMIT()      asm volatile("cp.async.commit_group;" ::: "memory")
#define CPA_WAIT(n)       asm volatile("cp.async.wait_group %0;" :: "n"(n) : "memory")

#define LDSM_X4(r0, r1, r2, r3, addr) \
    asm volatile("ldmatrix.sync.aligned.m8n8.x4.shared.b16 {%0,%1,%2,%3}, [%4];" \
        : "=r"(r0), "=r"(r1), "=r"(r2), "=r"(r3) : "r"(addr))

#define LDSM_X2_T(r0, r1, addr) \
    asm volatile("ldmatrix.sync.aligned.m8n8.x2.trans.shared.b16 {%0,%1}, [%2];" \
        : "=r"(r0), "=r"(r1) : "r"(addr))

#define MMA16816(d, a, b0, b1) \
    asm volatile("mma.sync.aligned.m16n8k16.row.col.f32.f16.f16.f32 " \
        "{%0,%1,%2,%3}, {%4,%5,%6,%7}, {%8,%9}, {%0,%1,%2,%3};" \
        : "+f"((d)[0]), "+f"((d)[1]), "+f"((d)[2]), "+f"((d)[3]) \
        : "r"((a)[0]), "r"((a)[1]), "r"((a)[2]), "r"((a)[3]), "r"(b0), "r"(b1))

// swizzled tile offset for 64B rows (gemm tiles): chunk 0..3
__device__ __forceinline__ uint32_t sw_off(int row, int chunk) {
    return (uint32_t)(row * 64 + ((chunk ^ ((row >> 1) & 3)) << 4));
}
// swizzled offset for 128B rows (attention tiles): chunk 0..7
__device__ __forceinline__ uint32_t swb(int row, int chunk) {
    return (uint32_t)(row * 128 + ((chunk ^ (row & 7)) << 4));
}

static __device__ __forceinline__ void h_split(float v, __half& hi, __half& lo) {
    hi = __float2half_rn(v);
    lo = __float2half_rn(v - __half2float(hi));
}

// ---------------- merged elementwise fp16 split (3 arrays, 1 launch) ----------------
__global__ void split3_kernel(const float* __restrict__ in0, __half* __restrict__ hi0, __half* __restrict__ lo0, int n0,
                              const float* __restrict__ in1, __half* __restrict__ hi1, __half* __restrict__ lo1, int n1,
                              const float* __restrict__ in2, __half* __restrict__ hi2, __half* __restrict__ lo2, int n2)
{
    int t = blockIdx.x * 256 + threadIdx.x;
    const float* in; __half *hi, *lo;
    if (t < n0)               { in = in0;  hi = hi0; lo = lo0; }
    else if (t < n0 + n1)     { t -= n0;       in = in1; hi = hi1; lo = lo1; }
    else if (t < n0 + n1 + n2){ t -= n0 + n1;  in = in2; hi = hi2; lo = lo2; }
    else return;
    __half h, l;
    h_split(in[t], h, l);
    hi[t] = h; lo[t] = l;
}

// ---------------- bias gather ----------------
__global__ void bias_kernel(const float* __restrict__ table,
                            const int*   __restrict__ idx,
                            float* __restrict__ out)
{
    int t = blockIdx.x * blockDim.x + threadIdx.x;
    if (t < HH * NT * NT) {
        int ij = t % (NT * NT);
        int h  = t / (NT * NT);
        out[t] = table[idx[ij] * HH + h];
    }
}

// ---------------- 3xFP16 mma.sync GEMM, 3-stage pipeline (unchanged) ----------------
#define GK     768
#define NCHUNK 24
#define TILEB  8192
#define STAGEB (4 * TILEB)
#define NSTAGE 3
#define GSMEM  (NSTAGE * STAGEB)       // 96 KB

static __device__ __forceinline__ void load_stage(
    uint32_t sb, const __half* __restrict__ Ahi, const __half* __restrict__ Alo,
    const __half* __restrict__ Whi, const __half* __restrict__ Wlo,
    int m0, int n0, int k0, int tid)
{
#pragma unroll
    for (int j = 0; j < 2; j++) {
        int id = tid + (j << 8);
        int row = id >> 2, c = id & 3;
        uint32_t o = sw_off(row, c);
        size_t ga = (size_t)(m0 + row) * GK + k0 + c * 8;
        size_t gb = (size_t)(n0 + row) * GK + k0 + c * 8;
        CPA16(sb + o,             Ahi + ga);
        CPA16(sb + TILEB + o,     Alo + ga);
        CPA16(sb + 2 * TILEB + o, Whi + gb);
        CPA16(sb + 3 * TILEB + o, Wlo + gb);
    }
}

template<bool SPLIT>
__global__ __launch_bounds__(256, 2)
void gemm_hmma_kernel(const __half* __restrict__ Ahi, const __half* __restrict__ Alo,
                      const __half* __restrict__ Whi, const __half* __restrict__ Wlo,
                      const float* __restrict__ bias, float* __restrict__ C,
                      __half* __restrict__ Chi, __half* __restrict__ Clo, int Nn)
{
    extern __shared__ char dsm[];
    const int tid = threadIdx.x;
    const int lane = tid & 31;
    const int wid = tid >> 5;
    const int wm = (wid & 3) * 32;
    const int wn = (wid >> 2) * 64;
    const int m0 = blockIdx.y * 128;
    const int n0 = blockIdx.x * 128;
    const uint32_t sb = smem_u32(dsm);

    float acc[2][8][4];
#pragma unroll
    for (int mt = 0; mt < 2; mt++)
#pragma unroll
        for (int nt = 0; nt < 8; nt++)
#pragma unroll
            for (int e = 0; e < 4; e++) acc[mt][nt][e] = 0.f;

    const int a_row = lane & 15;
    const int a_kc  = lane >> 4;
    const int b_row = (lane & 7) + ((lane >> 4) << 3);
    const int b_kc  = (lane >> 3) & 1;

    load_stage(sb,          Ahi, Alo, Whi, Wlo, m0, n0, 0,  tid);
    CPA_COMMIT();
    load_stage(sb + STAGEB, Ahi, Alo, Whi, Wlo, m0, n0, 32, tid);
    CPA_COMMIT();

    int st = 0;
    for (int k = 0; k < NCHUNK; k++) {
        if (k + 1 < NCHUNK) { CPA_WAIT(1); } else { CPA_WAIT(0); }
        __syncthreads();
        if (k + 2 < NCHUNK) {
            int ls = st + 2; if (ls >= NSTAGE) ls -= NSTAGE;
            load_stage(sb + ls * STAGEB, Ahi, Alo, Whi, Wlo, m0, n0, (k + 2) * 32, tid);
            CPA_COMMIT();
        }

        const uint32_t cs  = sb + st * STAGEB;
        const uint32_t sAh = cs, sAl = cs + TILEB, sBh = cs + 2 * TILEB, sBl = cs + 3 * TILEB;

#pragma unroll
        for (int kk = 0; kk < 2; kk++) {
            const int kc = kk * 2;
            uint32_t ah[2][4], al[2][4];
#pragma unroll
            for (int mt = 0; mt < 2; mt++) {
                uint32_t o = sw_off(wm + mt * 16 + a_row, kc + a_kc);
                LDSM_X4(ah[mt][0], ah[mt][1], ah[mt][2], ah[mt][3], sAh + o);
                LDSM_X4(al[mt][0], al[mt][1], al[mt][2], al[mt][3], sAl + o);
            }
#pragma unroll
            for (int ng = 0; ng < 4; ng++) {
                uint32_t bh[4], bl[4];
                uint32_t o = sw_off(wn + ng * 16 + b_row, kc + b_kc);
                LDSM_X4(bh[0], bh[1], bh[2], bh[3], sBh + o);
                LDSM_X4(bl[0], bl[1], bl[2], bl[3], sBl + o);
#pragma unroll
                for (int mt = 0; mt < 2; mt++) {
                    MMA16816(acc[mt][ng * 2 + 0], ah[mt], bh[0], bh[1]);
                    MMA16816(acc[mt][ng * 2 + 0], ah[mt], bl[0], bl[1]);
                    MMA16816(acc[mt][ng * 2 + 0], al[mt], bh[0], bh[1]);
                    MMA16816(acc[mt][ng * 2 + 1], ah[mt], bh[2], bh[3]);
                    MMA16816(acc[mt][ng * 2 + 1], ah[mt], bl[2], bl[3]);
                    MMA16816(acc[mt][ng * 2 + 1], al[mt], bh[2], bh[3]);
                }
            }
        }
        if (++st == NSTAGE) st = 0;
    }

    const int erow = lane >> 2;
    const int ecol = (lane & 3) * 2;
#pragma unroll
    for (int mt = 0; mt < 2; mt++) {
#pragma unroll
        for (int nt = 0; nt < 8; nt++) {
            int col = n0 + wn + nt * 8 + ecol;
            float b0 = __ldg(bias + col), b1 = __ldg(bias + col + 1);
            int r0 = m0 + wm + mt * 16 + erow;
            float v00 = acc[mt][nt][0] + b0, v01 = acc[mt][nt][1] + b1;
            float v10 = acc[mt][nt][2] + b0, v11 = acc[mt][nt][3] + b1;
            if (SPLIT) {
                __half h0, l0, h1, l1;
                h_split(v00, h0, l0); h_split(v01, h1, l1);
                *(__half2*)(Chi + (size_t)r0 * Nn + col) = __halves2half2(h0, h1);
                *(__half2*)(Clo + (size_t)r0 * Nn + col) = __halves2half2(l0, l1);
                h_split(v10, h0, l0); h_split(v11, h1, l1);
                *(__half2*)(Chi + (size_t)(r0 + 8) * Nn + col) = __halves2half2(h0, h1);
                *(__half2*)(Clo + (size_t)(r0 + 8) * Nn + col) = __halves2half2(l0, l1);
            } else {
                *(float2*)(C + (size_t)r0 * Nn + col)       = make_float2(v00, v01);
                *(float2*)(C + (size_t)(r0 + 8) * Nn + col) = make_float2(v10, v11);
            }
        }
    }
}

// ---------------- HMMA attention: 512 thr, register-resident softmax ----------------
#define ATT    512
#define KP     224
#define VP     208
#define PSTRB  432
#define PSTRH  216
#define A_KH   0
#define A_KL   (A_KH + KP * 128)          // 28672
#define A_VH   (A_KL + KP * 128)          // 57344
#define A_VL   (A_VH + VP * 128)          // 83968
#define A_QH   (A_VL + VP * 128)          // 110592 (2 bufs x 4096)
#define A_QL   (A_QH + 2 * 32 * 128)      // 118784
#define A_PH   (A_QL + 2 * 32 * 128)      // 126976
#define A_PL   (A_PH + 32 * PSTRB)        // 140800
#define A_PMAX (A_PL + 32 * PSTRB)        // 154624 (32 rows x 7 grps floats)
#define A_PSUM (A_PMAX + 32 * 7 * 4)      // 155520
#define A_TOT  (A_PSUM + 32 * 7 * 4)      // 156416

__global__ __launch_bounds__(ATT, 1) void attn_hmma_kernel(
    const __half* __restrict__ qhi, const __half* __restrict__ qlo,
    const float* __restrict__ bias,
    __half* __restrict__ aohi, __half* __restrict__ aolo)
{
    extern __shared__ char smb[];
    const uint32_t sb = smem_u32(smb);
    const int b = blockIdx.x / HH;
    const int h = blockIdx.x % HH;
    const int tid = threadIdx.x, lane = tid & 31, wid = tid >> 5;
    const __half* bh_ = qhi + (size_t)b * NT * 2304 + h * 64;
    const __half* bl_ = qlo + (size_t)b * NT * 2304 + h * 64;
    const float* biasH = bias + (size_t)h * NT * NT;
    float* PMAX = (float*)(smb + A_PMAX);
    float* PSUM = (float*)(smb + A_PSUM);

    for (int i = tid; i < ((KP - NT) * 128) / 4; i += ATT) {
        ((uint32_t*)(smb + A_KH + NT * 128))[i] = 0;
        ((uint32_t*)(smb + A_KL + NT * 128))[i] = 0;
    }
    for (int i = tid; i < ((VP - NT) * 128) / 4; i += ATT) {
        ((uint32_t*)(smb + A_VH + NT * 128))[i] = 0;
        ((uint32_t*)(smb + A_VL + NT * 128))[i] = 0;
    }
    for (int i = tid; i < (2 * 32 * PSTRB) / 4; i += ATT)
        ((uint32_t*)(smb + A_PH))[i] = 0;

    for (int p = tid; p < NT * 8; p += ATT) {
        int row = p >> 3, c = p & 7;
        uint32_t o = swb(row, c);
        size_t goff = (size_t)row * 2304 + 768 + c * 8;
        CPA16(sb + A_KH + o, bh_ + goff);
        CPA16(sb + A_KL + o, bl_ + goff);
        CPA16(sb + A_VH + o, bh_ + goff + 768);
        CPA16(sb + A_VL + o, bl_ + goff + 768);
    }
    for (int p = tid; p < 32 * 8; p += ATT) {
        int r = p >> 3, c = p & 7;
        int gr = (r < NT) ? r : 0;
        size_t goff = (size_t)gr * 2304 + c * 8;
        uint32_t o = swb(r, c);
        CPA16(sb + A_QH + o, bh_ + goff);
        CPA16(sb + A_QL + o, bl_ + goff);
    }
    CPA_COMMIT();
    CPA_WAIT(0);
    __syncthreads();

    const int a_row16 = lane & 15;
    const int a_kc1   = lane >> 4;
    const int b_row8  = (lane & 7) + ((lane >> 4) << 3);
    const int b_kc1   = (lane >> 3) & 1;

    // AV warp geometry (fixed across qt)
    const int av_wm = (wid & 1) * 16;
    const int av_wd = (wid >> 1) * 8;

    // hoist V_hi fragments (q-tile-invariant)
    uint32_t vfh[13][2];
#pragma unroll
    for (int kk = 0; kk < 13; kk++) {
        uint32_t boff = swb(kk * 16 + (lane & 15), av_wd >> 3);
        LDSM_X2_T(vfh[kk][0], vfh[kk][1], sb + A_VH + boff);
    }

    for (int qt = 0; qt < 7; qt++) {
        const int r0 = qt * 32;
        const int rows = min(32, NT - r0);
        const uint32_t qbuf = (uint32_t)((qt & 1) * 4096);

        // S-phase registers live across pass 1 / pass 2
        float acc[4][4];
        const int s_wm = (wid & 1) * 16;
        const int s_wn = (wid >> 1) * 32;
        const int erow = s_wm + (lane >> 2);     // local rows erow, erow+8
        const int ecol = (lane & 3) * 2;
        const int grp = wid >> 1;                // 0..6 for wid<14

        // ---- pass 1: S = 0.125*QK^T + bias in regs; partial row-max ----
        if (wid < 14) {
#pragma unroll
            for (int t = 0; t < 4; t++)
#pragma unroll
                for (int e = 0; e < 4; e++) acc[t][e] = 0.f;

            const int ar = s_wm + a_row16;
#pragma unroll
            for (int kk = 0; kk < 4; kk++) {
                uint32_t aoff = swb(ar, kk * 2 + a_kc1) + qbuf;
                uint32_t ah[4], al[4];
                LDSM_X4(ah[0], ah[1], ah[2], ah[3], sb + A_QH + aoff);
                LDSM_X4(al[0], al[1], al[2], al[3], sb + A_QL + aoff);
#pragma unroll
                for (int ng = 0; ng < 2; ng++) {
                    uint32_t boff = swb(s_wn + ng * 16 + b_row8, kk * 2 + b_kc1);
                    uint32_t bh[4], bl[4];
                    LDSM_X4(bh[0], bh[1], bh[2], bh[3], sb + A_KH + boff);
                    LDSM_X4(bl[0], bl[1], bl[2], bl[3], sb + A_KL + boff);
                    MMA16816(acc[ng * 2 + 0], ah, bh[0], bh[1]);
                    MMA16816(acc[ng * 2 + 0], ah, bl[0], bl[1]);
                    MMA16816(acc[ng * 2 + 0], al, bh[0], bh[1]);
                    MMA16816(acc[ng * 2 + 1], ah, bh[2], bh[3]);
                    MMA16816(acc[ng * 2 + 1], ah, bl[2], bl[3]);
                    MMA16816(acc[ng * 2 + 1], al, bh[2], bh[3]);
                }
            }
            float pm0 = -3.4e38f, pm1 = -3.4e38f;
#pragma unroll
            for (int nt = 0; nt < 4; nt++) {
                int col = s_wn + nt * 8 + ecol;
                int gr0 = r0 + erow, gr1 = r0 + erow + 8;
                float b00 = 0.f, b01 = 0.f, b10 = 0.f, b11 = 0.f;
                if (col < NT) {
                    bool c1 = (col + 1 < NT);
                    if (gr0 < NT) {
                        b00 = biasH[(size_t)gr0 * NT + col];
                        if (c1) b01 = biasH[(size_t)gr0 * NT + col + 1];
                    }
                    if (gr1 < NT) {
                        b10 = biasH[(size_t)gr1 * NT + col];
                        if (c1) b11 = biasH[(size_t)gr1 * NT + col + 1];
                    }
                }
                acc[nt][0] = acc[nt][0] * 0.125f + b00;
                acc[nt][1] = acc[nt][1] * 0.125f + b01;
                acc[nt][2] = acc[nt][2] * 0.125f + b10;
                acc[nt][3] = acc[nt][3] * 0.125f + b11;
                if (col < NT)     { pm0 = fmaxf(pm0, acc[nt][0]); pm1 = fmaxf(pm1, acc[nt][2]); }
                if (col + 1 < NT) { pm0 = fmaxf(pm0, acc[nt][1]); pm1 = fmaxf(pm1, acc[nt][3]); }
            }
            pm0 = fmaxf(pm0, __shfl_xor_sync(0xffffffffu, pm0, 1));
            pm0 = fmaxf(pm0, __shfl_xor_sync(0xffffffffu, pm0, 2));
            pm1 = fmaxf(pm1, __shfl_xor_sync(0xffffffffu, pm1, 1));
            pm1 = fmaxf(pm1, __shfl_xor_sync(0xffffffffu, pm1, 2));
            if ((lane & 3) == 0) {
                PMAX[erow * 7 + grp]       = pm0;
                PMAX[(erow + 8) * 7 + grp] = pm1;
            }
        }
        __syncthreads();

        // Q prefetch for next tile (all warps)
        if (qt + 1 < 7) {
            const int nr0 = (qt + 1) * 32;
            const uint32_t nqb = (uint32_t)(((qt + 1) & 1) * 4096);
            for (int p = tid; p < 32 * 8; p += ATT) {
                int r = p >> 3, c = p & 7;
                int gr = (nr0 + r < NT) ? (nr0 + r) : 0;
                size_t goff = (size_t)gr * 2304 + c * 8;
                uint32_t o = swb(r, c) + nqb;
                CPA16(sb + A_QH + o, bh_ + goff);
                CPA16(sb + A_QL + o, bl_ + goff);
            }
            CPA_COMMIT();
        }

        // ---- pass 2: exp in regs, write P hi/lo, partial row-sum ----
        if (wid < 14) {
            float gm0 = PMAX[erow * 7], gm1 = PMAX[(erow + 8) * 7];
#pragma unroll
            for (int g = 1; g < 7; g++) {
                gm0 = fmaxf(gm0, PMAX[erow * 7 + g]);
                gm1 = fmaxf(gm1, PMAX[(erow + 8) * 7 + g]);
            }
            __half* PH = (__half*)(smb + A_PH);
            __half* PL = (__half*)(smb + A_PL);
            float ps0 = 0.f, ps1 = 0.f;
#pragma unroll
            for (int nt = 0; nt < 4; nt++) {
                int col = s_wn + nt * 8 + ecol;
                if (col < NT) {
                    float e00 = __expf(acc[nt][0] - gm0);
                    float e01 = __expf(acc[nt][1] - gm0);
                    float e10 = __expf(acc[nt][2] - gm1);
                    float e11 = __expf(acc[nt][3] - gm1);
                    if (col + 1 >= NT) { e01 = 0.f; e11 = 0.f; }
                    ps0 += e00 + e01;
                    ps1 += e10 + e11;
                    __half h0, l0, h1, l1;
                    h_split(e00, h0, l0); h_split(e01, h1, l1);
                    *(__half2*)(PH + erow * PSTRH + col) = __halves2half2(h0, h1);
                    *(__half2*)(PL + erow * PSTRH + col) = __halves2half2(l0, l1);
                    h_split(e10, h0, l0); h_split(e11, h1, l1);
                    *(__half2*)(PH + (erow + 8) * PSTRH + col) = __halves2half2(h0, h1);
                    *(__half2*)(PL + (erow + 8) * PSTRH + col) = __halves2half2(l0, l1);
                }
            }
            ps0 += __shfl_xor_sync(0xffffffffu, ps0, 1);
            ps0 += __shfl_xor_sync(0xffffffffu, ps0, 2);
            ps1 += __shfl_xor_sync(0xffffffffu, ps1, 1);
            ps1 += __shfl_xor_sync(0xffffffffu, ps1, 2);
            if ((lane & 3) == 0) {
                PSUM[erow * 7 + grp]       = ps0;
                PSUM[(erow + 8) * 7 + grp] = ps1;
            }
        }
        __syncthreads();

        // ---- AV = P V : 16 warps, each 16x8; V_hi from registers ----
        {
            float acv[4];
#pragma unroll
            for (int e = 0; e < 4; e++) acv[e] = 0.f;

            const int ar = av_wm + a_row16;
#pragma unroll
            for (int kk = 0; kk < 13; kk++) {
                uint32_t aoff = (uint32_t)(ar * PSTRB + (kk * 2 + a_kc1) * 16);
                uint32_t ah[4], al[4];
                LDSM_X4(ah[0], ah[1], ah[2], ah[3], sb + A_PH + aoff);
                LDSM_X4(al[0], al[1], al[2], al[3], sb + A_PL + aoff);
                uint32_t boff = swb(kk * 16 + (lane & 15), av_wd >> 3);
                uint32_t bl0, bl1;
                LDSM_X2_T(bl0, bl1, sb + A_VL + boff);
                MMA16816(acv, ah, vfh[kk][0], vfh[kk][1]);
                MMA16816(acv, ah, bl0, bl1);
                MMA16816(acv, al, vfh[kk][0], vfh[kk][1]);
            }
            const int oerow = av_wm + (lane >> 2);
            const int ec = (lane & 3) * 2;
#pragma unroll
            for (int hf = 0; hf < 2; hf++) {
                int rr = oerow + hf * 8;
                if (rr < rows) {
                    float s = PSUM[rr * 7];
#pragma unroll
                    for (int g = 1; g < 7; g++) s += PSUM[rr * 7 + g];
                    float inv = 1.f / s;
                    size_t gb = ((size_t)b * NT + r0 + rr) * DIM_ + h * 64 + av_wd;
                    __half h0, l0, h1, l1;
                    h_split(acv[hf * 2 + 0] * inv, h0, l0);
                    h_split(acv[hf * 2 + 1] * inv, h1, l1);
                    *(__half2*)(aohi + gb + ec) = __halves2half2(h0, h1);
                    *(__half2*)(aolo + gb + ec) = __halves2half2(l0, l1);
                }
            }
        }
        if (qt + 1 < 7) { CPA_WAIT(0); }
        __syncthreads();
    }
}

// ---------------- launch ----------------
extern "C" void kernel_launch(void* const* d_in, const int* in_sizes, int n_in,
                              void* d_out, int out_size)
{
    const float* x      = (const float*)d_in[0];
    const float* qkv_w  = (const float*)d_in[1];
    const float* qkv_b  = (const float*)d_in[2];
    const float* proj_w = (const float*)d_in[3];
    const float* proj_b = (const float*)d_in[4];
    const float* table  = (const float*)d_in[5];
    const int*   relidx = (const int*)d_in[6];
    float* out = (float*)d_out;

    float *p_bias;
    __half *p_qhi, *p_qlo, *p_xhi, *p_xlo, *p_aohi, *p_aolo;
    __half *p_qwhi, *p_qwlo, *p_pwhi, *p_pwlo;
    cudaGetSymbolAddress((void**)&p_qhi,  g_qhi);
    cudaGetSymbolAddress((void**)&p_qlo,  g_qlo);
    cudaGetSymbolAddress((void**)&p_xhi,  g_xhi);
    cudaGetSymbolAddress((void**)&p_xlo,  g_xlo);
    cudaGetSymbolAddress((void**)&p_aohi, g_aohi);
    cudaGetSymbolAddress((void**)&p_aolo, g_aolo);
    cudaGetSymbolAddress((void**)&p_qwhi, g_qwhi);
    cudaGetSymbolAddress((void**)&p_qwlo, g_qwlo);
    cudaGetSymbolAddress((void**)&p_pwhi, g_pwhi);
    cudaGetSymbolAddress((void**)&p_pwlo, g_pwlo);
    cudaGetSymbolAddress((void**)&p_bias, g_bias);

    cudaFuncSetAttribute(attn_hmma_kernel, cudaFuncAttributeMaxDynamicSharedMemorySize, A_TOT);
    cudaFuncSetAttribute(gemm_hmma_kernel<true>,  cudaFuncAttributeMaxDynamicSharedMemorySize, GSMEM);
    cudaFuncSetAttribute(gemm_hmma_kernel<false>, cudaFuncAttributeMaxDynamicSharedMemorySize, GSMEM);

    const int n0 = MTOK * DIM_;
    const int n1 = 2304 * DIM_;
    const int n2 = DIM_ * DIM_;
    split3_kernel<<<(n0 + n1 + n2 + 255) / 256, 256>>>(
        x, p_xhi, p_xlo, n0,
        qkv_w, p_qwhi, p_qwlo, n1,
        proj_w, p_pwhi, p_pwlo, n2);

    bias_kernel<<<(HH * NT * NT + 255) / 256, 256>>>(table, relidx, p_bias);

    dim3 g1(2304 / 128, MTOK / 128);
    gemm_hmma_kernel<true><<<g1, 256, GSMEM>>>(p_xhi, p_xlo, p_qwhi, p_qwlo, qkv_b,
                                               nullptr, p_qhi, p_qlo, 2304);

    attn_hmma_kernel<<<B_ * HH, ATT, A_TOT>>>(p_qhi, p_qlo, p_bias, p_aohi, p_aolo);

    dim3 g2(DIM_ / 128, MTOK / 128);
    gemm_hmma_kernel<false><<<g2, 256, GSMEM>>>(p_aohi, p_aolo, p_pwhi, p_pwlo, proj_b,
                                                out, nullptr, nullptr, DIM_);
}

// round 12
// speedup vs baseline: 1.3039x; 1.0321x over previous
#include <cuda_runtime.h>
#include <cuda_fp16.h>
#include <cstdint>

#define B_   128
#define NT   197
#define HH   12
#define HD   64
#define DIM_ 768
#define MTOK (B_ * NT)          // 25216 = 197*128

// ---------------- scratch ----------------
__device__ __half g_qhi [(long long)MTOK * 2304];
__device__ __half g_qlo [(long long)MTOK * 2304];
__device__ __half g_xhi [(long long)MTOK * DIM_];
__device__ __half g_xlo [(long long)MTOK * DIM_];
__device__ __half g_aohi[(long long)MTOK * DIM_];
__device__ __half g_aolo[(long long)MTOK * DIM_];
__device__ __half g_qwhi[2304 * DIM_];
__device__ __half g_qwlo[2304 * DIM_];
__device__ __half g_pwhi[DIM_ * DIM_];
__device__ __half g_pwlo[DIM_ * DIM_];
__device__ float  g_bias[HH * NT * NT];

// ---------------- helpers ----------------
__device__ __forceinline__ uint32_t smem_u32(const void* p) {
    uint32_t a;
    asm("{ .reg .u64 t; cvta.to.shared.u64 t, %1; cvt.u32.u64 %0, t; }" : "=r"(a) : "l"(p));
    return a;
}

#define CPA16(dst, src)   asm volatile("cp.async.cg.shared.global [%0], [%1], 16;" :: "r"(dst), "l"(src) : "memory")
#define CPA_COMMIT()      asm volatile("cp.async.commit_group;" ::: "memory")
#define CPA_WAIT(n)       asm volatile("cp.async.wait_group %0;" :: "n"(n) : "memory")

#define LDSM_X4(r0, r1, r2, r3, addr) \
    asm volatile("ldmatrix.sync.aligned.m8n8.x4.shared.b16 {%0,%1,%2,%3}, [%4];" \
        : "=r"(r0), "=r"(r1), "=r"(r2), "=r"(r3) : "r"(addr))

#define LDSM_X2_T(r0, r1, addr) \
    asm volatile("ldmatrix.sync.aligned.m8n8.x2.trans.shared.b16 {%0,%1}, [%2];" \
        : "=r"(r0), "=r"(r1) : "r"(addr))

#define MMA16816(d, a, b0, b1) \
    asm volatile("mma.sync.aligned.m16n8k16.row.col.f32.f16.f16.f32 " \
        "{%0,%1,%2,%3}, {%4,%5,%6,%7}, {%8,%9}, {%0,%1,%2,%3};" \
        : "+f"((d)[0]), "+f"((d)[1]), "+f"((d)[2]), "+f"((d)[3]) \
        : "r"((a)[0]), "r"((a)[1]), "r"((a)[2]), "r"((a)[3]), "r"(b0), "r"(b1))

// swizzled tile offset for 64B rows (gemm tiles): chunk 0..3
__device__ __forceinline__ uint32_t sw_off(int row, int chunk) {
    return (uint32_t)(row * 64 + ((chunk ^ ((row >> 1) & 3)) << 4));
}
// swizzled offset for 128B rows (attention tiles): chunk 0..7
__device__ __forceinline__ uint32_t swb(int row, int chunk) {
    return (uint32_t)(row * 128 + ((chunk ^ (row & 7)) << 4));
}

static __device__ __forceinline__ void h_split(float v, __half& hi, __half& lo) {
    hi = __float2half_rn(v);
    lo = __float2half_rn(v - __half2float(hi));
}

// ---------------- merged elementwise fp16 split (3 arrays, 1 launch) ----------------
__global__ void split3_kernel(const float* __restrict__ in0, __half* __restrict__ hi0, __half* __restrict__ lo0, int n0,
                              const float* __restrict__ in1, __half* __restrict__ hi1, __half* __restrict__ lo1, int n1,
                              const float* __restrict__ in2, __half* __restrict__ hi2, __half* __restrict__ lo2, int n2)
{
    int t = blockIdx.x * 256 + threadIdx.x;
    const float* in; __half *hi, *lo;
    if (t < n0)               { in = in0;  hi = hi0; lo = lo0; }
    else if (t < n0 + n1)     { t -= n0;       in = in1; hi = hi1; lo = lo1; }
    else if (t < n0 + n1 + n2){ t -= n0 + n1;  in = in2; hi = hi2; lo = lo2; }
    else return;
    __half h, l;
    h_split(in[t], h, l);
    hi[t] = h; lo[t] = l;
}

// ---------------- bias gather ----------------
__global__ void bias_kernel(const float* __restrict__ table,
                            const int*   __restrict__ idx,
                            float* __restrict__ out)
{
    int t = blockIdx.x * blockDim.x + threadIdx.x;
    if (t < HH * NT * NT) {
        int ij = t % (NT * NT);
        int h  = t / (NT * NT);
        out[t] = table[idx[ij] * HH + h];
    }
}

// ---------------- 3xFP16 mma.sync GEMM, 3-stage pipeline (unchanged) ----------------
#define GK     768
#define NCHUNK 24
#define TILEB  8192
#define STAGEB (4 * TILEB)
#define NSTAGE 3
#define GSMEM  (NSTAGE * STAGEB)       // 96 KB

static __device__ __forceinline__ void load_stage(
    uint32_t sb, const __half* __restrict__ Ahi, const __half* __restrict__ Alo,
    const __half* __restrict__ Whi, const __half* __restrict__ Wlo,
    int m0, int n0, int k0, int tid)
{
#pragma unroll
    for (int j = 0; j < 2; j++) {
        int id = tid + (j << 8);
        int row = id >> 2, c = id & 3;
        uint32_t o = sw_off(row, c);
        size_t ga = (size_t)(m0 + row) * GK + k0 + c * 8;
        size_t gb = (size_t)(n0 + row) * GK + k0 + c * 8;
        CPA16(sb + o,             Ahi + ga);
        CPA16(sb + TILEB + o,     Alo + ga);
        CPA16(sb + 2 * TILEB + o, Whi + gb);
        CPA16(sb + 3 * TILEB + o, Wlo + gb);
    }
}

template<bool SPLIT>
__global__ __launch_bounds__(256, 2)
void gemm_hmma_kernel(const __half* __restrict__ Ahi, const __half* __restrict__ Alo,
                      const __half* __restrict__ Whi, const __half* __restrict__ Wlo,
                      const float* __restrict__ bias, float* __restrict__ C,
                      __half* __restrict__ Chi, __half* __restrict__ Clo, int Nn)
{
    extern __shared__ char dsm[];
    const int tid = threadIdx.x;
    const int lane = tid & 31;
    const int wid = tid >> 5;
    const int wm = (wid & 3) * 32;
    const int wn = (wid >> 2) * 64;
    const int m0 = blockIdx.y * 128;
    const int n0 = blockIdx.x * 128;
    const uint32_t sb = smem_u32(dsm);

    float acc[2][8][4];
#pragma unroll
    for (int mt = 0; mt < 2; mt++)
#pragma unroll
        for (int nt = 0; nt < 8; nt++)
#pragma unroll
            for (int e = 0; e < 4; e++) acc[mt][nt][e] = 0.f;

    const int a_row = lane & 15;
    const int a_kc  = lane >> 4;
    const int b_row = (lane & 7) + ((lane >> 4) << 3);
    const int b_kc  = (lane >> 3) & 1;

    load_stage(sb,          Ahi, Alo, Whi, Wlo, m0, n0, 0,  tid);
    CPA_COMMIT();
    load_stage(sb + STAGEB, Ahi, Alo, Whi, Wlo, m0, n0, 32, tid);
    CPA_COMMIT();

    int st = 0;
    for (int k = 0; k < NCHUNK; k++) {
        if (k + 1 < NCHUNK) { CPA_WAIT(1); } else { CPA_WAIT(0); }
        __syncthreads();
        if (k + 2 < NCHUNK) {
            int ls = st + 2; if (ls >= NSTAGE) ls -= NSTAGE;
            load_stage(sb + ls * STAGEB, Ahi, Alo, Whi, Wlo, m0, n0, (k + 2) * 32, tid);
            CPA_COMMIT();
        }

        const uint32_t cs  = sb + st * STAGEB;
        const uint32_t sAh = cs, sAl = cs + TILEB, sBh = cs + 2 * TILEB, sBl = cs + 3 * TILEB;

#pragma unroll
        for (int kk = 0; kk < 2; kk++) {
            const int kc = kk * 2;
            uint32_t ah[2][4], al[2][4];
#pragma unroll
            for (int mt = 0; mt < 2; mt++) {
                uint32_t o = sw_off(wm + mt * 16 + a_row, kc + a_kc);
                LDSM_X4(ah[mt][0], ah[mt][1], ah[mt][2], ah[mt][3], sAh + o);
                LDSM_X4(al[mt][0], al[mt][1], al[mt][2], al[mt][3], sAl + o);
            }
#pragma unroll
            for (int ng = 0; ng < 4; ng++) {
                uint32_t bh[4], bl[4];
                uint32_t o = sw_off(wn + ng * 16 + b_row, kc + b_kc);
                LDSM_X4(bh[0], bh[1], bh[2], bh[3], sBh + o);
                LDSM_X4(bl[0], bl[1], bl[2], bl[3], sBl + o);
#pragma unroll
                for (int mt = 0; mt < 2; mt++) {
                    MMA16816(acc[mt][ng * 2 + 0], ah[mt], bh[0], bh[1]);
                    MMA16816(acc[mt][ng * 2 + 0], ah[mt], bl[0], bl[1]);
                    MMA16816(acc[mt][ng * 2 + 0], al[mt], bh[0], bh[1]);
                    MMA16816(acc[mt][ng * 2 + 1], ah[mt], bh[2], bh[3]);
                    MMA16816(acc[mt][ng * 2 + 1], ah[mt], bl[2], bl[3]);
                    MMA16816(acc[mt][ng * 2 + 1], al[mt], bh[2], bh[3]);
                }
            }
        }
        if (++st == NSTAGE) st = 0;
    }

    const int erow = lane >> 2;
    const int ecol = (lane & 3) * 2;
#pragma unroll
    for (int mt = 0; mt < 2; mt++) {
#pragma unroll
        for (int nt = 0; nt < 8; nt++) {
            int col = n0 + wn + nt * 8 + ecol;
            float b0 = __ldg(bias + col), b1 = __ldg(bias + col + 1);
            int r0 = m0 + wm + mt * 16 + erow;
            float v00 = acc[mt][nt][0] + b0, v01 = acc[mt][nt][1] + b1;
            float v10 = acc[mt][nt][2] + b0, v11 = acc[mt][nt][3] + b1;
            if (SPLIT) {
                __half h0, l0, h1, l1;
                h_split(v00, h0, l0); h_split(v01, h1, l1);
                *(__half2*)(Chi + (size_t)r0 * Nn + col) = __halves2half2(h0, h1);
                *(__half2*)(Clo + (size_t)r0 * Nn + col) = __halves2half2(l0, l1);
                h_split(v10, h0, l0); h_split(v11, h1, l1);
                *(__half2*)(Chi + (size_t)(r0 + 8) * Nn + col) = __halves2half2(h0, h1);
                *(__half2*)(Clo + (size_t)(r0 + 8) * Nn + col) = __halves2half2(l0, l1);
            } else {
                *(float2*)(C + (size_t)r0 * Nn + col)       = make_float2(v00, v01);
                *(float2*)(C + (size_t)(r0 + 8) * Nn + col) = make_float2(v10, v11);
            }
        }
    }
}

// ---------------- HMMA attention: 512 thr, reg softmax, P_hi-only AV ----------------
#define ATT    512
#define KP     224
#define VP     208
#define PSTRB  432
#define PSTRH  216
#define A_KH   0
#define A_KL   (A_KH + KP * 128)          // 28672
#define A_VH   (A_KL + KP * 128)          // 57344
#define A_VL   (A_VH + VP * 128)          // 83968
#define A_QH   (A_VL + VP * 128)          // 110592 (2 bufs x 4096)
#define A_QL   (A_QH + 2 * 32 * 128)      // 118784
#define A_PH   (A_QL + 2 * 32 * 128)      // 126976
#define A_PMAX (A_PH + 32 * PSTRB)        // 140800
#define A_PSUM (A_PMAX + 32 * 7 * 4)      // 141696
#define A_TOT  (A_PSUM + 32 * 7 * 4)      // 142592

__global__ __launch_bounds__(ATT, 1) void attn_hmma_kernel(
    const __half* __restrict__ qhi, const __half* __restrict__ qlo,
    const float* __restrict__ bias,
    __half* __restrict__ aohi, __half* __restrict__ aolo)
{
    extern __shared__ char smb[];
    const uint32_t sb = smem_u32(smb);
    const int b = blockIdx.x / HH;
    const int h = blockIdx.x % HH;
    const int tid = threadIdx.x, lane = tid & 31, wid = tid >> 5;
    const __half* bh_ = qhi + (size_t)b * NT * 2304 + h * 64;
    const __half* bl_ = qlo + (size_t)b * NT * 2304 + h * 64;
    const float* biasH = bias + (size_t)h * NT * NT;
    float* PMAX = (float*)(smb + A_PMAX);
    float* PSUM = (float*)(smb + A_PSUM);

    for (int i = tid; i < ((KP - NT) * 128) / 4; i += ATT) {
        ((uint32_t*)(smb + A_KH + NT * 128))[i] = 0;
        ((uint32_t*)(smb + A_KL + NT * 128))[i] = 0;
    }
    for (int i = tid; i < ((VP - NT) * 128) / 4; i += ATT) {
        ((uint32_t*)(smb + A_VH + NT * 128))[i] = 0;
        ((uint32_t*)(smb + A_VL + NT * 128))[i] = 0;
    }
    for (int i = tid; i < (32 * PSTRB) / 4; i += ATT)
        ((uint32_t*)(smb + A_PH))[i] = 0;

    for (int p = tid; p < NT * 8; p += ATT) {
        int row = p >> 3, c = p & 7;
        uint32_t o = swb(row, c);
        size_t goff = (size_t)row * 2304 + 768 + c * 8;
        CPA16(sb + A_KH + o, bh_ + goff);
        CPA16(sb + A_KL + o, bl_ + goff);
        CPA16(sb + A_VH + o, bh_ + goff + 768);
        CPA16(sb + A_VL + o, bl_ + goff + 768);
    }
    for (int p = tid; p < 32 * 8; p += ATT) {
        int r = p >> 3, c = p & 7;
        int gr = (r < NT) ? r : 0;
        size_t goff = (size_t)gr * 2304 + c * 8;
        uint32_t o = swb(r, c);
        CPA16(sb + A_QH + o, bh_ + goff);
        CPA16(sb + A_QL + o, bl_ + goff);
    }
    CPA_COMMIT();
    CPA_WAIT(0);
    __syncthreads();

    const int a_row16 = lane & 15;
    const int a_kc1   = lane >> 4;
    const int b_row8  = (lane & 7) + ((lane >> 4) << 3);
    const int b_kc1   = (lane >> 3) & 1;

    // AV warp geometry (fixed across qt)
    const int av_wm = (wid & 1) * 16;
    const int av_wd = (wid >> 1) * 8;

    // hoist V_hi fragments (q-tile-invariant)
    uint32_t vfh[13][2];
#pragma unroll
    for (int kk = 0; kk < 13; kk++) {
        uint32_t boff = swb(kk * 16 + (lane & 15), av_wd >> 3);
        LDSM_X2_T(vfh[kk][0], vfh[kk][1], sb + A_VH + boff);
    }

    for (int qt = 0; qt < 7; qt++) {
        const int r0 = qt * 32;
        const int rows = min(32, NT - r0);
        const uint32_t qbuf = (uint32_t)((qt & 1) * 4096);

        // S-phase registers live across pass 1 / pass 2
        float acc[4][4];
        const int s_wm = (wid & 1) * 16;
        const int s_wn = (wid >> 1) * 32;
        const int erow = s_wm + (lane >> 2);     // local rows erow, erow+8
        const int ecol = (lane & 3) * 2;
        const int grp = wid >> 1;                // 0..6 for wid<14

        // ---- pass 1: S = 0.125*QK^T + bias in regs; partial row-max ----
        if (wid < 14) {
#pragma unroll
            for (int t = 0; t < 4; t++)
#pragma unroll
                for (int e = 0; e < 4; e++) acc[t][e] = 0.f;

            const int ar = s_wm + a_row16;
#pragma unroll
            for (int kk = 0; kk < 4; kk++) {
                uint32_t aoff = swb(ar, kk * 2 + a_kc1) + qbuf;
                uint32_t ah[4], al[4];
                LDSM_X4(ah[0], ah[1], ah[2], ah[3], sb + A_QH + aoff);
                LDSM_X4(al[0], al[1], al[2], al[3], sb + A_QL + aoff);
#pragma unroll
                for (int ng = 0; ng < 2; ng++) {
                    uint32_t boff = swb(s_wn + ng * 16 + b_row8, kk * 2 + b_kc1);
                    uint32_t bh[4], bl[4];
                    LDSM_X4(bh[0], bh[1], bh[2], bh[3], sb + A_KH + boff);
                    LDSM_X4(bl[0], bl[1], bl[2], bl[3], sb + A_KL + boff);
                    MMA16816(acc[ng * 2 + 0], ah, bh[0], bh[1]);
                    MMA16816(acc[ng * 2 + 0], ah, bl[0], bl[1]);
                    MMA16816(acc[ng * 2 + 0], al, bh[0], bh[1]);
                    MMA16816(acc[ng * 2 + 1], ah, bh[2], bh[3]);
                    MMA16816(acc[ng * 2 + 1], ah, bl[2], bl[3]);
                    MMA16816(acc[ng * 2 + 1], al, bh[2], bh[3]);
                }
            }
            float pm0 = -3.4e38f, pm1 = -3.4e38f;
#pragma unroll
            for (int nt = 0; nt < 4; nt++) {
                int col = s_wn + nt * 8 + ecol;
                int gr0 = r0 + erow, gr1 = r0 + erow + 8;
                float b00 = 0.f, b01 = 0.f, b10 = 0.f, b11 = 0.f;
                if (col < NT) {
                    bool c1 = (col + 1 < NT);
                    if (gr0 < NT) {
                        b00 = biasH[(size_t)gr0 * NT + col];
                        if (c1) b01 = biasH[(size_t)gr0 * NT + col + 1];
                    }
                    if (gr1 < NT) {
                        b10 = biasH[(size_t)gr1 * NT + col];
                        if (c1) b11 = biasH[(size_t)gr1 * NT + col + 1];
                    }
                }
                acc[nt][0] = acc[nt][0] * 0.125f + b00;
                acc[nt][1] = acc[nt][1] * 0.125f + b01;
                acc[nt][2] = acc[nt][2] * 0.125f + b10;
                acc[nt][3] = acc[nt][3] * 0.125f + b11;
                if (col < NT)     { pm0 = fmaxf(pm0, acc[nt][0]); pm1 = fmaxf(pm1, acc[nt][2]); }
                if (col + 1 < NT) { pm0 = fmaxf(pm0, acc[nt][1]); pm1 = fmaxf(pm1, acc[nt][3]); }
            }
            pm0 = fmaxf(pm0, __shfl_xor_sync(0xffffffffu, pm0, 1));
            pm0 = fmaxf(pm0, __shfl_xor_sync(0xffffffffu, pm0, 2));
            pm1 = fmaxf(pm1, __shfl_xor_sync(0xffffffffu, pm1, 1));
            pm1 = fmaxf(pm1, __shfl_xor_sync(0xffffffffu, pm1, 2));
            if ((lane & 3) == 0) {
                PMAX[erow * 7 + grp]       = pm0;
                PMAX[(erow + 8) * 7 + grp] = pm1;
            }
        }
        __syncthreads();

        // Q prefetch for next tile (all warps)
        if (qt + 1 < 7) {
            const int nr0 = (qt + 1) * 32;
            const uint32_t nqb = (uint32_t)(((qt + 1) & 1) * 4096);
            for (int p = tid; p < 32 * 8; p += ATT) {
                int r = p >> 3, c = p & 7;
                int gr = (nr0 + r < NT) ? (nr0 + r) : 0;
                size_t goff = (size_t)gr * 2304 + c * 8;
                uint32_t o = swb(r, c) + nqb;
                CPA16(sb + A_QH + o, bh_ + goff);
                CPA16(sb + A_QL + o, bl_ + goff);
            }
            CPA_COMMIT();
        }

        // ---- pass 2: exp in regs, write P (fp16 only), partial row-sum ----
        if (wid < 14) {
            float gm0 = PMAX[erow * 7], gm1 = PMAX[(erow + 8) * 7];
#pragma unroll
            for (int g = 1; g < 7; g++) {
                gm0 = fmaxf(gm0, PMAX[erow * 7 + g]);
                gm1 = fmaxf(gm1, PMAX[(erow + 8) * 7 + g]);
            }
            __half* PH = (__half*)(smb + A_PH);
            float ps0 = 0.f, ps1 = 0.f;
#pragma unroll
            for (int nt = 0; nt < 4; nt++) {
                int col = s_wn + nt * 8 + ecol;
                if (col < NT) {
                    float e00 = __expf(acc[nt][0] - gm0);
                    float e01 = __expf(acc[nt][1] - gm0);
                    float e10 = __expf(acc[nt][2] - gm1);
                    float e11 = __expf(acc[nt][3] - gm1);
                    if (col + 1 >= NT) { e01 = 0.f; e11 = 0.f; }
                    ps0 += e00 + e01;
                    ps1 += e10 + e11;
                    *(__half2*)(PH + erow * PSTRH + col) =
                        __halves2half2(__float2half_rn(e00), __float2half_rn(e01));
                    *(__half2*)(PH + (erow + 8) * PSTRH + col) =
                        __halves2half2(__float2half_rn(e10), __float2half_rn(e11));
                }
            }
            ps0 += __shfl_xor_sync(0xffffffffu, ps0, 1);
            ps0 += __shfl_xor_sync(0xffffffffu, ps0, 2);
            ps1 += __shfl_xor_sync(0xffffffffu, ps1, 1);
            ps1 += __shfl_xor_sync(0xffffffffu, ps1, 2);
            if ((lane & 3) == 0) {
                PSUM[erow * 7 + grp]       = ps0;
                PSUM[(erow + 8) * 7 + grp] = ps1;
            }
        }
        __syncthreads();

        // ---- AV = P_hi * (V_hi + V_lo) : 16 warps, each 16x8 ----
        {
            float acv[4];
#pragma unroll
            for (int e = 0; e < 4; e++) acv[e] = 0.f;

            const int ar = av_wm + a_row16;
#pragma unroll
            for (int kk = 0; kk < 13; kk++) {
                uint32_t aoff = (uint32_t)(ar * PSTRB + (kk * 2 + a_kc1) * 16);
                uint32_t ah[4];
                LDSM_X4(ah[0], ah[1], ah[2], ah[3], sb + A_PH + aoff);
                uint32_t boff = swb(kk * 16 + (lane & 15), av_wd >> 3);
                uint32_t bl0, bl1;
                LDSM_X2_T(bl0, bl1, sb + A_VL + boff);
                MMA16816(acv, ah, vfh[kk][0], vfh[kk][1]);
                MMA16816(acv, ah, bl0, bl1);
            }
            const int oerow = av_wm + (lane >> 2);
            const int ec = (lane & 3) * 2;
#pragma unroll
            for (int hf = 0; hf < 2; hf++) {
                int rr = oerow + hf * 8;
                if (rr < rows) {
                    float s = PSUM[rr * 7];
#pragma unroll
                    for (int g = 1; g < 7; g++) s += PSUM[rr * 7 + g];
                    float inv = 1.f / s;
                    size_t gb = ((size_t)b * NT + r0 + rr) * DIM_ + h * 64 + av_wd;
                    __half h0, l0, h1, l1;
                    h_split(acv[hf * 2 + 0] * inv, h0, l0);
                    h_split(acv[hf * 2 + 1] * inv, h1, l1);
                    *(__half2*)(aohi + gb + ec) = __halves2half2(h0, h1);
                    *(__half2*)(aolo + gb + ec) = __halves2half2(l0, l1);
                }
            }
        }
        if (qt + 1 < 7) { CPA_WAIT(0); }
        __syncthreads();
    }
}

// ---------------- launch ----------------
extern "C" void kernel_launch(void* const* d_in, const int* in_sizes, int n_in,
                              void* d_out, int out_size)
{
    const float* x      = (const float*)d_in[0];
    const float* qkv_w  = (const float*)d_in[1];
    const float* qkv_b  = (const float*)d_in[2];
    const float* proj_w = (const float*)d_in[3];
    const float* proj_b = (const float*)d_in[4];
    const float* table  = (const float*)d_in[5];
    const int*   relidx = (const int*)d_in[6];
    float* out = (float*)d_out;

    float *p_bias;
    __half *p_qhi, *p_qlo, *p_xhi, *p_xlo, *p_aohi, *p_aolo;
    __half *p_qwhi, *p_qwlo, *p_pwhi, *p_pwlo;
    cudaGetSymbolAddress((void**)&p_qhi,  g_qhi);
    cudaGetSymbolAddress((void**)&p_qlo,  g_qlo);
    cudaGetSymbolAddress((void**)&p_xhi,  g_xhi);
    cudaGetSymbolAddress((void**)&p_xlo,  g_xlo);
    cudaGetSymbolAddress((void**)&p_aohi, g_aohi);
    cudaGetSymbolAddress((void**)&p_aolo, g_aolo);
    cudaGetSymbolAddress((void**)&p_qwhi, g_qwhi);
    cudaGetSymbolAddress((void**)&p_qwlo, g_qwlo);
    cudaGetSymbolAddress((void**)&p_pwhi, g_pwhi);
    cudaGetSymbolAddress((void**)&p_pwlo, g_pwlo);
    cudaGetSymbolAddress((void**)&p_bias, g_bias);

    cudaFuncSetAttribute(attn_hmma_kernel, cudaFuncAttributeMaxDynamicSharedMemorySize, A_TOT);
    cudaFuncSetAttribute(gemm_hmma_kernel<true>,  cudaFuncAttributeMaxDynamicSharedMemorySize, GSMEM);
    cudaFuncSetAttribute(gemm_hmma_kernel<false>, cudaFuncAttributeMaxDynamicSharedMemorySize, GSMEM);

    const int n0 = MTOK * DIM_;
    const int n1 = 2304 * DIM_;
    const int n2 = DIM_ * DIM_;
    split3_kernel<<<(n0 + n1 + n2 + 255) / 256, 256>>>(
        x, p_xhi, p_xlo, n0,
        qkv_w, p_qwhi, p_qwlo, n1,
        proj_w, p_pwhi, p_pwlo, n2);

    bias_kernel<<<(HH * NT * NT + 255) / 256, 256>>>(table, relidx, p_bias);

    dim3 g1(2304 / 128, MTOK / 128);
    gemm_hmma_kernel<true><<<g1, 256, GSMEM>>>(p_xhi, p_xlo, p_qwhi, p_qwlo, qkv_b,
                                               nullptr, p_qhi, p_qlo, 2304);

    attn_hmma_kernel<<<B_ * HH, ATT, A_TOT>>>(p_qhi, p_qlo, p_bias, p_aohi, p_aolo);

    dim3 g2(DIM_ / 128, MTOK / 128);
    gemm_hmma_kernel<false><<<g2, 256, GSMEM>>>(p_aohi, p_aolo, p_pwhi, p_pwlo, proj_b,
                                                out, nullptr, nullptr, DIM_);
}

// round 13
// speedup vs baseline: 1.3448x; 1.0314x over previous
#include <cuda_runtime.h>
#include <cuda_fp16.h>
#include <cstdint>

#define B_   128
#define NT   197
#define HH   12
#define HD   64
#define DIM_ 768
#define MTOK (B_ * NT)          // 25216 = 197*128

// ---------------- scratch ----------------
__device__ __half g_qhi [(long long)MTOK * 2304];
__device__ __half g_qlo [(long long)MTOK * 2304];
__device__ __half g_xhi [(long long)MTOK * DIM_];
__device__ __half g_xlo [(long long)MTOK * DIM_];
__device__ __half g_aohi[(long long)MTOK * DIM_];
__device__ __half g_aolo[(long long)MTOK * DIM_];
__device__ __half g_qwhi[2304 * DIM_];
__device__ __half g_qwlo[2304 * DIM_];
__device__ __half g_pwhi[DIM_ * DIM_];
__device__ __half g_pwlo[DIM_ * DIM_];
__device__ float  g_bias[HH * NT * NT];

// ---------------- helpers ----------------
__device__ __forceinline__ uint32_t smem_u32(const void* p) {
    uint32_t a;
    asm("{ .reg .u64 t; cvta.to.shared.u64 t, %1; cvt.u32.u64 %0, t; }" : "=r"(a) : "l"(p));
    return a;
}

#define CPA16(dst, src)   asm volatile("cp.async.cg.shared.global [%0], [%1], 16;" :: "r"(dst), "l"(src) : "memory")
#define CPA_COMMIT()      asm volatile("cp.async.commit_group;" ::: "memory")
#define CPA_WAIT(n)       asm volatile("cp.async.wait_group %0;" :: "n"(n) : "memory")

#define LDSM_X4(r0, r1, r2, r3, addr) \
    asm volatile("ldmatrix.sync.aligned.m8n8.x4.shared.b16 {%0,%1,%2,%3}, [%4];" \
        : "=r"(r0), "=r"(r1), "=r"(r2), "=r"(r3) : "r"(addr))

#define LDSM_X2_T(r0, r1, addr) \
    asm volatile("ldmatrix.sync.aligned.m8n8.x2.trans.shared.b16 {%0,%1}, [%2];" \
        : "=r"(r0), "=r"(r1) : "r"(addr))

#define MMA16816(d, a, b0, b1) \
    asm volatile("mma.sync.aligned.m16n8k16.row.col.f32.f16.f16.f32 " \
        "{%0,%1,%2,%3}, {%4,%5,%6,%7}, {%8,%9}, {%0,%1,%2,%3};" \
        : "+f"((d)[0]), "+f"((d)[1]), "+f"((d)[2]), "+f"((d)[3]) \
        : "r"((a)[0]), "r"((a)[1]), "r"((a)[2]), "r"((a)[3]), "r"(b0), "r"(b1))

// swizzled tile offset for 64B rows (gemm tiles): chunk 0..3
__device__ __forceinline__ uint32_t sw_off(int row, int chunk) {
    return (uint32_t)(row * 64 + ((chunk ^ ((row >> 1) & 3)) << 4));
}
// swizzled offset for 128B rows (attention tiles): chunk 0..7
__device__ __forceinline__ uint32_t swb(int row, int chunk) {
    return (uint32_t)(row * 128 + ((chunk ^ (row & 7)) << 4));
}

static __device__ __forceinline__ void h_split(float v, __half& hi, __half& lo) {
    hi = __float2half_rn(v);
    lo = __float2half_rn(v - __half2float(hi));
}

// ---------------- merged elementwise fp16 split (3 arrays, 1 launch) ----------------
__global__ void split3_kernel(const float* __restrict__ in0, __half* __restrict__ hi0, __half* __restrict__ lo0, int n0,
                              const float* __restrict__ in1, __half* __restrict__ hi1, __half* __restrict__ lo1, int n1,
                              const float* __restrict__ in2, __half* __restrict__ hi2, __half* __restrict__ lo2, int n2)
{
    int t = blockIdx.x * 256 + threadIdx.x;
    const float* in; __half *hi, *lo;
    if (t < n0)               { in = in0;  hi = hi0; lo = lo0; }
    else if (t < n0 + n1)     { t -= n0;       in = in1; hi = hi1; lo = lo1; }
    else if (t < n0 + n1 + n2){ t -= n0 + n1;  in = in2; hi = hi2; lo = lo2; }
    else return;
    __half h, l;
    h_split(in[t], h, l);
    hi[t] = h; lo[t] = l;
}

// ---------------- bias gather ----------------
__global__ void bias_kernel(const float* __restrict__ table,
                            const int*   __restrict__ idx,
                            float* __restrict__ out)
{
    int t = blockIdx.x * blockDim.x + threadIdx.x;
    if (t < HH * NT * NT) {
        int ij = t % (NT * NT);
        int h  = t / (NT * NT);
        out[t] = table[idx[ij] * HH + h];
    }
}

// ---------------- 3xFP16 mma.sync GEMM, 3-stage pipeline ----------------
// full3=false (q/k column tiles): drop A_lo entirely (loads + ldsm + al*bh MMA)
#define GK     768
#define NCHUNK 24
#define TILEB  8192
#define STAGEB (4 * TILEB)
#define NSTAGE 3
#define GSMEM  (NSTAGE * STAGEB)       // 96 KB

static __device__ __forceinline__ void load_stage(
    uint32_t sb, const __half* __restrict__ Ahi, const __half* __restrict__ Alo,
    const __half* __restrict__ Whi, const __half* __restrict__ Wlo,
    int m0, int n0, int k0, int tid, bool full3)
{
#pragma unroll
    for (int j = 0; j < 2; j++) {
        int id = tid + (j << 8);
        int row = id >> 2, c = id & 3;
        uint32_t o = sw_off(row, c);
        size_t ga = (size_t)(m0 + row) * GK + k0 + c * 8;
        size_t gb = (size_t)(n0 + row) * GK + k0 + c * 8;
        CPA16(sb + o,             Ahi + ga);
        if (full3) CPA16(sb + TILEB + o, Alo + ga);
        CPA16(sb + 2 * TILEB + o, Whi + gb);
        CPA16(sb + 3 * TILEB + o, Wlo + gb);
    }
}

template<bool SPLIT>
__global__ __launch_bounds__(256, 2)
void gemm_hmma_kernel(const __half* __restrict__ Ahi, const __half* __restrict__ Alo,
                      const __half* __restrict__ Whi, const __half* __restrict__ Wlo,
                      const float* __restrict__ bias, float* __restrict__ C,
                      __half* __restrict__ Chi, __half* __restrict__ Clo,
                      int Nn, int nFull3)
{
    extern __shared__ char dsm[];
    const int tid = threadIdx.x;
    const int lane = tid & 31;
    const int wid = tid >> 5;
    const int wm = (wid & 3) * 32;
    const int wn = (wid >> 2) * 64;
    const int m0 = blockIdx.y * 128;
    const int n0 = blockIdx.x * 128;
    const uint32_t sb = smem_u32(dsm);
    const bool full3 = (n0 >= nFull3);   // v-tiles and proj keep 3-term

    float acc[2][8][4];
#pragma unroll
    for (int mt = 0; mt < 2; mt++)
#pragma unroll
        for (int nt = 0; nt < 8; nt++)
#pragma unroll
            for (int e = 0; e < 4; e++) acc[mt][nt][e] = 0.f;

    const int a_row = lane & 15;
    const int a_kc  = lane >> 4;
    const int b_row = (lane & 7) + ((lane >> 4) << 3);
    const int b_kc  = (lane >> 3) & 1;

    load_stage(sb,          Ahi, Alo, Whi, Wlo, m0, n0, 0,  tid, full3);
    CPA_COMMIT();
    load_stage(sb + STAGEB, Ahi, Alo, Whi, Wlo, m0, n0, 32, tid, full3);
    CPA_COMMIT();

    int st = 0;
    for (int k = 0; k < NCHUNK; k++) {
        if (k + 1 < NCHUNK) { CPA_WAIT(1); } else { CPA_WAIT(0); }
        __syncthreads();
        if (k + 2 < NCHUNK) {
            int ls = st + 2; if (ls >= NSTAGE) ls -= NSTAGE;
            load_stage(sb + ls * STAGEB, Ahi, Alo, Whi, Wlo, m0, n0, (k + 2) * 32, tid, full3);
            CPA_COMMIT();
        }

        const uint32_t cs  = sb + st * STAGEB;
        const uint32_t sAh = cs, sAl = cs + TILEB, sBh = cs + 2 * TILEB, sBl = cs + 3 * TILEB;

#pragma unroll
        for (int kk = 0; kk < 2; kk++) {
            const int kc = kk * 2;
            uint32_t ah[2][4], al[2][4];
#pragma unroll
            for (int mt = 0; mt < 2; mt++) {
                uint32_t o = sw_off(wm + mt * 16 + a_row, kc + a_kc);
                LDSM_X4(ah[mt][0], ah[mt][1], ah[mt][2], ah[mt][3], sAh + o);
                if (full3) LDSM_X4(al[mt][0], al[mt][1], al[mt][2], al[mt][3], sAl + o);
            }
#pragma unroll
            for (int ng = 0; ng < 4; ng++) {
                uint32_t bh[4], bl[4];
                uint32_t o = sw_off(wn + ng * 16 + b_row, kc + b_kc);
                LDSM_X4(bh[0], bh[1], bh[2], bh[3], sBh + o);
                LDSM_X4(bl[0], bl[1], bl[2], bl[3], sBl + o);
#pragma unroll
                for (int mt = 0; mt < 2; mt++) {
                    MMA16816(acc[mt][ng * 2 + 0], ah[mt], bh[0], bh[1]);
                    MMA16816(acc[mt][ng * 2 + 0], ah[mt], bl[0], bl[1]);
                    MMA16816(acc[mt][ng * 2 + 1], ah[mt], bh[2], bh[3]);
                    MMA16816(acc[mt][ng * 2 + 1], ah[mt], bl[2], bl[3]);
                    if (full3) {
                        MMA16816(acc[mt][ng * 2 + 0], al[mt], bh[0], bh[1]);
                        MMA16816(acc[mt][ng * 2 + 1], al[mt], bh[2], bh[3]);
                    }
                }
            }
        }
        if (++st == NSTAGE) st = 0;
    }

    const int erow = lane >> 2;
    const int ecol = (lane & 3) * 2;
#pragma unroll
    for (int mt = 0; mt < 2; mt++) {
#pragma unroll
        for (int nt = 0; nt < 8; nt++) {
            int col = n0 + wn + nt * 8 + ecol;
            float b0 = __ldg(bias + col), b1 = __ldg(bias + col + 1);
            int r0 = m0 + wm + mt * 16 + erow;
            float v00 = acc[mt][nt][0] + b0, v01 = acc[mt][nt][1] + b1;
            float v10 = acc[mt][nt][2] + b0, v11 = acc[mt][nt][3] + b1;
            if (SPLIT) {
                __half h0, l0, h1, l1;
                h_split(v00, h0, l0); h_split(v01, h1, l1);
                *(__half2*)(Chi + (size_t)r0 * Nn + col) = __halves2half2(h0, h1);
                *(__half2*)(Clo + (size_t)r0 * Nn + col) = __halves2half2(l0, l1);
                h_split(v10, h0, l0); h_split(v11, h1, l1);
                *(__half2*)(Chi + (size_t)(r0 + 8) * Nn + col) = __halves2half2(h0, h1);
                *(__half2*)(Clo + (size_t)(r0 + 8) * Nn + col) = __halves2half2(l0, l1);
            } else {
                *(float2*)(C + (size_t)r0 * Nn + col)       = make_float2(v00, v01);
                *(float2*)(C + (size_t)(r0 + 8) * Nn + col) = make_float2(v10, v11);
            }
        }
    }
}

// ---------------- HMMA attention: 512 thr, reg softmax, q_hi-only S, P_hi-only AV ----------------
#define ATT    512
#define KP     224
#define VP     208
#define PSTRB  432
#define PSTRH  216
#define A_KH   0
#define A_KL   (A_KH + KP * 128)          // 28672
#define A_VH   (A_KL + KP * 128)          // 57344
#define A_VL   (A_VH + VP * 128)          // 83968
#define A_QH   (A_VL + VP * 128)          // 110592 (2 bufs x 4096)
#define A_PH   (A_QH + 2 * 32 * 128)      // 118784
#define A_PMAX (A_PH + 32 * PSTRB)        // 132608
#define A_PSUM (A_PMAX + 32 * 7 * 4)      // 133504
#define A_TOT  (A_PSUM + 32 * 7 * 4)      // 134400

__global__ __launch_bounds__(ATT, 1) void attn_hmma_kernel(
    const __half* __restrict__ qhi, const __half* __restrict__ qlo,
    const float* __restrict__ bias,
    __half* __restrict__ aohi, __half* __restrict__ aolo)
{
    extern __shared__ char smb[];
    const uint32_t sb = smem_u32(smb);
    const int b = blockIdx.x / HH;
    const int h = blockIdx.x % HH;
    const int tid = threadIdx.x, lane = tid & 31, wid = tid >> 5;
    const __half* bh_ = qhi + (size_t)b * NT * 2304 + h * 64;
    const __half* bl_ = qlo + (size_t)b * NT * 2304 + h * 64;
    const float* biasH = bias + (size_t)h * NT * NT;
    float* PMAX = (float*)(smb + A_PMAX);
    float* PSUM = (float*)(smb + A_PSUM);

    for (int i = tid; i < ((KP - NT) * 128) / 4; i += ATT) {
        ((uint32_t*)(smb + A_KH + NT * 128))[i] = 0;
        ((uint32_t*)(smb + A_KL + NT * 128))[i] = 0;
    }
    for (int i = tid; i < ((VP - NT) * 128) / 4; i += ATT) {
        ((uint32_t*)(smb + A_VH + NT * 128))[i] = 0;
        ((uint32_t*)(smb + A_VL + NT * 128))[i] = 0;
    }
    for (int i = tid; i < (32 * PSTRB) / 4; i += ATT)
        ((uint32_t*)(smb + A_PH))[i] = 0;

    for (int p = tid; p < NT * 8; p += ATT) {
        int row = p >> 3, c = p & 7;
        uint32_t o = swb(row, c);
        size_t goff = (size_t)row * 2304 + 768 + c * 8;
        CPA16(sb + A_KH + o, bh_ + goff);
        CPA16(sb + A_KL + o, bl_ + goff);
        CPA16(sb + A_VH + o, bh_ + goff + 768);
        CPA16(sb + A_VL + o, bl_ + goff + 768);
    }
    for (int p = tid; p < 32 * 8; p += ATT) {
        int r = p >> 3, c = p & 7;
        int gr = (r < NT) ? r : 0;
        size_t goff = (size_t)gr * 2304 + c * 8;
        CPA16(sb + A_QH + swb(r, c), bh_ + goff);
    }
    CPA_COMMIT();
    CPA_WAIT(0);
    __syncthreads();

    const int a_row16 = lane & 15;
    const int a_kc1   = lane >> 4;
    const int b_row8  = (lane & 7) + ((lane >> 4) << 3);
    const int b_kc1   = (lane >> 3) & 1;

    // AV warp geometry (fixed across qt)
    const int av_wm = (wid & 1) * 16;
    const int av_wd = (wid >> 1) * 8;

    // hoist V_hi fragments (q-tile-invariant)
    uint32_t vfh[13][2];
#pragma unroll
    for (int kk = 0; kk < 13; kk++) {
        uint32_t boff = swb(kk * 16 + (lane & 15), av_wd >> 3);
        LDSM_X2_T(vfh[kk][0], vfh[kk][1], sb + A_VH + boff);
    }

    for (int qt = 0; qt < 7; qt++) {
        const int r0 = qt * 32;
        const int rows = min(32, NT - r0);
        const uint32_t qbuf = (uint32_t)((qt & 1) * 4096);

        // S-phase registers live across pass 1 / pass 2
        float acc[4][4];
        const int s_wm = (wid & 1) * 16;
        const int s_wn = (wid >> 1) * 32;
        const int erow = s_wm + (lane >> 2);     // local rows erow, erow+8
        const int ecol = (lane & 3) * 2;
        const int grp = wid >> 1;                // 0..6 for wid<14

        // ---- pass 1: S = 0.125*(q_hi K^T) + bias in regs; partial row-max ----
        if (wid < 14) {
#pragma unroll
            for (int t = 0; t < 4; t++)
#pragma unroll
                for (int e = 0; e < 4; e++) acc[t][e] = 0.f;

            const int ar = s_wm + a_row16;
#pragma unroll
            for (int kk = 0; kk < 4; kk++) {
                uint32_t aoff = swb(ar, kk * 2 + a_kc1) + qbuf;
                uint32_t ah[4];
                LDSM_X4(ah[0], ah[1], ah[2], ah[3], sb + A_QH + aoff);
#pragma unroll
                for (int ng = 0; ng < 2; ng++) {
                    uint32_t boff = swb(s_wn + ng * 16 + b_row8, kk * 2 + b_kc1);
                    uint32_t bh[4], bl[4];
                    LDSM_X4(bh[0], bh[1], bh[2], bh[3], sb + A_KH + boff);
                    LDSM_X4(bl[0], bl[1], bl[2], bl[3], sb + A_KL + boff);
                    MMA16816(acc[ng * 2 + 0], ah, bh[0], bh[1]);
                    MMA16816(acc[ng * 2 + 0], ah, bl[0], bl[1]);
                    MMA16816(acc[ng * 2 + 1], ah, bh[2], bh[3]);
                    MMA16816(acc[ng * 2 + 1], ah, bl[2], bl[3]);
                }
            }
            float pm0 = -3.4e38f, pm1 = -3.4e38f;
#pragma unroll
            for (int nt = 0; nt < 4; nt++) {
                int col = s_wn + nt * 8 + ecol;
                int gr0 = r0 + erow, gr1 = r0 + erow + 8;
                float b00 = 0.f, b01 = 0.f, b10 = 0.f, b11 = 0.f;
                if (col < NT) {
                    bool c1 = (col + 1 < NT);
                    if (gr0 < NT) {
                        b00 = biasH[(size_t)gr0 * NT + col];
                        if (c1) b01 = biasH[(size_t)gr0 * NT + col + 1];
                    }
                    if (gr1 < NT) {
                        b10 = biasH[(size_t)gr1 * NT + col];
                        if (c1) b11 = biasH[(size_t)gr1 * NT + col + 1];
                    }
                }
                acc[nt][0] = acc[nt][0] * 0.125f + b00;
                acc[nt][1] = acc[nt][1] * 0.125f + b01;
                acc[nt][2] = acc[nt][2] * 0.125f + b10;
                acc[nt][3] = acc[nt][3] * 0.125f + b11;
                if (col < NT)     { pm0 = fmaxf(pm0, acc[nt][0]); pm1 = fmaxf(pm1, acc[nt][2]); }
                if (col + 1 < NT) { pm0 = fmaxf(pm0, acc[nt][1]); pm1 = fmaxf(pm1, acc[nt][3]); }
            }
            pm0 = fmaxf(pm0, __shfl_xor_sync(0xffffffffu, pm0, 1));
            pm0 = fmaxf(pm0, __shfl_xor_sync(0xffffffffu, pm0, 2));
            pm1 = fmaxf(pm1, __shfl_xor_sync(0xffffffffu, pm1, 1));
            pm1 = fmaxf(pm1, __shfl_xor_sync(0xffffffffu, pm1, 2));
            if ((lane & 3) == 0) {
                PMAX[erow * 7 + grp]       = pm0;
                PMAX[(erow + 8) * 7 + grp] = pm1;
            }
        }
        __syncthreads();

        // Q prefetch for next tile (hi only)
        if (qt + 1 < 7) {
            const int nr0 = (qt + 1) * 32;
            const uint32_t nqb = (uint32_t)(((qt + 1) & 1) * 4096);
            for (int p = tid; p < 32 * 8; p += ATT) {
                int r = p >> 3, c = p & 7;
                int gr = (nr0 + r < NT) ? (nr0 + r) : 0;
                size_t goff = (size_t)gr * 2304 + c * 8;
                CPA16(sb + A_QH + swb(r, c) + nqb, bh_ + goff);
            }
            CPA_COMMIT();
        }

        // ---- pass 2: exp in regs, write P (fp16 only), partial row-sum ----
        if (wid < 14) {
            float gm0 = PMAX[erow * 7], gm1 = PMAX[(erow + 8) * 7];
#pragma unroll
            for (int g = 1; g < 7; g++) {
                gm0 = fmaxf(gm0, PMAX[erow * 7 + g]);
                gm1 = fmaxf(gm1, PMAX[(erow + 8) * 7 + g]);
            }
            __half* PH = (__half*)(smb + A_PH);
            float ps0 = 0.f, ps1 = 0.f;
#pragma unroll
            for (int nt = 0; nt < 4; nt++) {
                int col = s_wn + nt * 8 + ecol;
                if (col < NT) {
                    float e00 = __expf(acc[nt][0] - gm0);
                    float e01 = __expf(acc[nt][1] - gm0);
                    float e10 = __expf(acc[nt][2] - gm1);
                    float e11 = __expf(acc[nt][3] - gm1);
                    if (col + 1 >= NT) { e01 = 0.f; e11 = 0.f; }
                    ps0 += e00 + e01;
                    ps1 += e10 + e11;
                    *(__half2*)(PH + erow * PSTRH + col) =
                        __halves2half2(__float2half_rn(e00), __float2half_rn(e01));
                    *(__half2*)(PH + (erow + 8) * PSTRH + col) =
                        __halves2half2(__float2half_rn(e10), __float2half_rn(e11));
                }
            }
            ps0 += __shfl_xor_sync(0xffffffffu, ps0, 1);
            ps0 += __shfl_xor_sync(0xffffffffu, ps0, 2);
            ps1 += __shfl_xor_sync(0xffffffffu, ps1, 1);
            ps1 += __shfl_xor_sync(0xffffffffu, ps1, 2);
            if ((lane & 3) == 0) {
                PSUM[erow * 7 + grp]       = ps0;
                PSUM[(erow + 8) * 7 + grp] = ps1;
            }
        }
        __syncthreads();

        // ---- AV = P_hi * (V_hi + V_lo) : 16 warps, each 16x8 ----
        {
            float acv[4];
#pragma unroll
            for (int e = 0; e < 4; e++) acv[e] = 0.f;

            const int ar = av_wm + a_row16;
#pragma unroll
            for (int kk = 0; kk < 13; kk++) {
                uint32_t aoff = (uint32_t)(ar * PSTRB + (kk * 2 + a_kc1) * 16);
                uint32_t ah[4];
                LDSM_X4(ah[0], ah[1], ah[2], ah[3], sb + A_PH + aoff);
                uint32_t boff = swb(kk * 16 + (lane & 15), av_wd >> 3);
                uint32_t bl0, bl1;
                LDSM_X2_T(bl0, bl1, sb + A_VL + boff);
                MMA16816(acv, ah, vfh[kk][0], vfh[kk][1]);
                MMA16816(acv, ah, bl0, bl1);
            }
            const int oerow = av_wm + (lane >> 2);
            const int ec = (lane & 3) * 2;
#pragma unroll
            for (int hf = 0; hf < 2; hf++) {
                int rr = oerow + hf * 8;
                if (rr < rows) {
                    float s = PSUM[rr * 7];
#pragma unroll
                    for (int g = 1; g < 7; g++) s += PSUM[rr * 7 + g];
                    float inv = 1.f / s;
                    size_t gb = ((size_t)b * NT + r0 + rr) * DIM_ + h * 64 + av_wd;
                    __half h0, l0, h1, l1;
                    h_split(acv[hf * 2 + 0] * inv, h0, l0);
                    h_split(acv[hf * 2 + 1] * inv, h1, l1);
                    *(__half2*)(aohi + gb + ec) = __halves2half2(h0, h1);
                    *(__half2*)(aolo + gb + ec) = __halves2half2(l0, l1);
                }
            }
        }
        if (qt + 1 < 7) { CPA_WAIT(0); }
        __syncthreads();
    }
}

// ---------------- launch ----------------
extern "C" void kernel_launch(void* const* d_in, const int* in_sizes, int n_in,
                              void* d_out, int out_size)
{
    const float* x      = (const float*)d_in[0];
    const float* qkv_w  = (const float*)d_in[1];
    const float* qkv_b  = (const float*)d_in[2];
    const float* proj_w = (const float*)d_in[3];
    const float* proj_b = (const float*)d_in[4];
    const float* table  = (const float*)d_in[5];
    const int*   relidx = (const int*)d_in[6];
    float* out = (float*)d_out;

    float *p_bias;
    __half *p_qhi, *p_qlo, *p_xhi, *p_xlo, *p_aohi, *p_aolo;
    __half *p_qwhi, *p_qwlo, *p_pwhi, *p_pwlo;
    cudaGetSymbolAddress((void**)&p_qhi,  g_qhi);
    cudaGetSymbolAddress((void**)&p_qlo,  g_qlo);
    cudaGetSymbolAddress((void**)&p_xhi,  g_xhi);
    cudaGetSymbolAddress((void**)&p_xlo,  g_xlo);
    cudaGetSymbolAddress((void**)&p_aohi, g_aohi);
    cudaGetSymbolAddress((void**)&p_aolo, g_aolo);
    cudaGetSymbolAddress((void**)&p_qwhi, g_qwhi);
    cudaGetSymbolAddress((void**)&p_qwlo, g_qwlo);
    cudaGetSymbolAddress((void**)&p_pwhi, g_pwhi);
    cudaGetSymbolAddress((void**)&p_pwlo, g_pwlo);
    cudaGetSymbolAddress((void**)&p_bias, g_bias);

    cudaFuncSetAttribute(attn_hmma_kernel, cudaFuncAttributeMaxDynamicSharedMemorySize, A_TOT);
    cudaFuncSetAttribute(gemm_hmma_kernel<true>,  cudaFuncAttributeMaxDynamicSharedMemorySize, GSMEM);
    cudaFuncSetAttribute(gemm_hmma_kernel<false>, cudaFuncAttributeMaxDynamicSharedMemorySize, GSMEM);

    const int n0 = MTOK * DIM_;
    const int n1 = 2304 * DIM_;
    const int n2 = DIM_ * DIM_;
    split3_kernel<<<(n0 + n1 + n2 + 255) / 256, 256>>>(
        x, p_xhi, p_xlo, n0,
        qkv_w, p_qwhi, p_qwlo, n1,
        proj_w, p_pwhi, p_pwlo, n2);

    bias_kernel<<<(HH * NT * NT + 255) / 256, 256>>>(table, relidx, p_bias);

    // QKV: q,k tiles (cols < 1536) use 2-term; v tiles 3-term
    dim3 g1(2304 / 128, MTOK / 128);
    gemm_hmma_kernel<true><<<g1, 256, GSMEM>>>(p_xhi, p_xlo, p_qwhi, p_qwlo, qkv_b,
                                               nullptr, p_qhi, p_qlo, 2304, 1536);

    attn_hmma_kernel<<<B_ * HH, ATT, A_TOT>>>(p_qhi, p_qlo, p_bias, p_aohi, p_aolo);

    // proj: always 3-term (nFull3 = 0)
    dim3 g2(DIM_ / 128, MTOK / 128);
    gemm_hmma_kernel<false><<<g2, 256, GSMEM>>>(p_aohi, p_aolo, p_pwhi, p_pwlo, proj_b,
                                                out, nullptr, nullptr, DIM_, 0);
}

// round 14
// speedup vs baseline: 1.4053x; 1.0450x over previous
#include <cuda_runtime.h>
#include <cuda_fp16.h>
#include <cstdint>

#define B_   128
#define NT   197
#define HH   12
#define HD   64
#define DIM_ 768
#define MTOK (B_ * NT)          // 25216 = 197*128

// ---------------- scratch ----------------
__device__ __half g_qhi [(long long)MTOK * 2304];
__device__ __half g_qlo [(long long)MTOK * 2304];
__device__ __half g_xhi [(long long)MTOK * DIM_];
__device__ __half g_xlo [(long long)MTOK * DIM_];
__device__ __half g_aohi[(long long)MTOK * DIM_];
__device__ __half g_aolo[(long long)MTOK * DIM_];
__device__ __half g_qwhi[2304 * DIM_];
__device__ __half g_qwlo[2304 * DIM_];
__device__ __half g_pwhi[DIM_ * DIM_];
__device__ __half g_pwlo[DIM_ * DIM_];
__device__ float  g_bias[HH * NT * NT];

// ---------------- helpers ----------------
__device__ __forceinline__ uint32_t smem_u32(const void* p) {
    uint32_t a;
    asm("{ .reg .u64 t; cvta.to.shared.u64 t, %1; cvt.u32.u64 %0, t; }" : "=r"(a) : "l"(p));
    return a;
}

#define CPA16(dst, src)   asm volatile("cp.async.cg.shared.global [%0], [%1], 16;" :: "r"(dst), "l"(src) : "memory")
#define CPA_COMMIT()      asm volatile("cp.async.commit_group;" ::: "memory")
#define CPA_WAIT(n)       asm volatile("cp.async.wait_group %0;" :: "n"(n) : "memory")

#define LDSM_X4(r0, r1, r2, r3, addr) \
    asm volatile("ldmatrix.sync.aligned.m8n8.x4.shared.b16 {%0,%1,%2,%3}, [%4];" \
        : "=r"(r0), "=r"(r1), "=r"(r2), "=r"(r3) : "r"(addr))

#define LDSM_X2_T(r0, r1, addr) \
    asm volatile("ldmatrix.sync.aligned.m8n8.x2.trans.shared.b16 {%0,%1}, [%2];" \
        : "=r"(r0), "=r"(r1) : "r"(addr))

#define MMA16816(d, a, b0, b1) \
    asm volatile("mma.sync.aligned.m16n8k16.row.col.f32.f16.f16.f32 " \
        "{%0,%1,%2,%3}, {%4,%5,%6,%7}, {%8,%9}, {%0,%1,%2,%3};" \
        : "+f"((d)[0]), "+f"((d)[1]), "+f"((d)[2]), "+f"((d)[3]) \
        : "r"((a)[0]), "r"((a)[1]), "r"((a)[2]), "r"((a)[3]), "r"(b0), "r"(b1))

// swizzled tile offset for 64B rows (gemm tiles): chunk 0..3
__device__ __forceinline__ uint32_t sw_off(int row, int chunk) {
    return (uint32_t)(row * 64 + ((chunk ^ ((row >> 1) & 3)) << 4));
}
// swizzled offset for 128B rows (attention tiles): chunk 0..7
__device__ __forceinline__ uint32_t swb(int row, int chunk) {
    return (uint32_t)(row * 128 + ((chunk ^ (row & 7)) << 4));
}

static __device__ __forceinline__ void h_split(float v, __half& hi, __half& lo) {
    hi = __float2half_rn(v);
    lo = __float2half_rn(v - __half2float(hi));
}

// ---------------- merged elementwise fp16 split (3 arrays, 1 launch) ----------------
__global__ void split3_kernel(const float* __restrict__ in0, __half* __restrict__ hi0, __half* __restrict__ lo0, int n0,
                              const float* __restrict__ in1, __half* __restrict__ hi1, __half* __restrict__ lo1, int n1,
                              const float* __restrict__ in2, __half* __restrict__ hi2, __half* __restrict__ lo2, int n2)
{
    int t = blockIdx.x * 256 + threadIdx.x;
    const float* in; __half *hi, *lo;
    if (t < n0)               { in = in0;  hi = hi0; lo = lo0; }
    else if (t < n0 + n1)     { t -= n0;       in = in1; hi = hi1; lo = lo1; }
    else if (t < n0 + n1 + n2){ t -= n0 + n1;  in = in2; hi = hi2; lo = lo2; }
    else return;
    __half h, l;
    h_split(in[t], h, l);
    hi[t] = h; lo[t] = l;
}

// ---------------- bias gather ----------------
__global__ void bias_kernel(const float* __restrict__ table,
                            const int*   __restrict__ idx,
                            float* __restrict__ out)
{
    int t = blockIdx.x * blockDim.x + threadIdx.x;
    if (t < HH * NT * NT) {
        int ij = t % (NT * NT);
        int h  = t / (NT * NT);
        out[t] = table[idx[ij] * HH + h];
    }
}

// ---------------- 3xFP16 mma.sync GEMM, 3-stage pipeline ----------------
// full3=false (q/k column tiles): drop A_lo term AND skip Clo store (unused downstream)
#define GK     768
#define NCHUNK 24
#define TILEB  8192
#define STAGEB (4 * TILEB)
#define NSTAGE 3
#define GSMEM  (NSTAGE * STAGEB)       // 96 KB

static __device__ __forceinline__ void load_stage(
    uint32_t sb, const __half* __restrict__ Ahi, const __half* __restrict__ Alo,
    const __half* __restrict__ Whi, const __half* __restrict__ Wlo,
    int m0, int n0, int k0, int tid, bool full3)
{
#pragma unroll
    for (int j = 0; j < 2; j++) {
        int id = tid + (j << 8);
        int row = id >> 2, c = id & 3;
        uint32_t o = sw_off(row, c);
        size_t ga = (size_t)(m0 + row) * GK + k0 + c * 8;
        size_t gb = (size_t)(n0 + row) * GK + k0 + c * 8;
        CPA16(sb + o,             Ahi + ga);
        if (full3) CPA16(sb + TILEB + o, Alo + ga);
        CPA16(sb + 2 * TILEB + o, Whi + gb);
        CPA16(sb + 3 * TILEB + o, Wlo + gb);
    }
}

template<bool SPLIT>
__global__ __launch_bounds__(256, 2)
void gemm_hmma_kernel(const __half* __restrict__ Ahi, const __half* __restrict__ Alo,
                      const __half* __restrict__ Whi, const __half* __restrict__ Wlo,
                      const float* __restrict__ bias, float* __restrict__ C,
                      __half* __restrict__ Chi, __half* __restrict__ Clo,
                      int Nn, int nFull3)
{
    extern __shared__ char dsm[];
    const int tid = threadIdx.x;
    const int lane = tid & 31;
    const int wid = tid >> 5;
    const int wm = (wid & 3) * 32;
    const int wn = (wid >> 2) * 64;
    const int m0 = blockIdx.y * 128;
    const int n0 = blockIdx.x * 128;
    const uint32_t sb = smem_u32(dsm);
    const bool full3 = (n0 >= nFull3);   // v-tiles and proj keep 3-term

    float acc[2][8][4];
#pragma unroll
    for (int mt = 0; mt < 2; mt++)
#pragma unroll
        for (int nt = 0; nt < 8; nt++)
#pragma unroll
            for (int e = 0; e < 4; e++) acc[mt][nt][e] = 0.f;

    const int a_row = lane & 15;
    const int a_kc  = lane >> 4;
    const int b_row = (lane & 7) + ((lane >> 4) << 3);
    const int b_kc  = (lane >> 3) & 1;

    load_stage(sb,          Ahi, Alo, Whi, Wlo, m0, n0, 0,  tid, full3);
    CPA_COMMIT();
    load_stage(sb + STAGEB, Ahi, Alo, Whi, Wlo, m0, n0, 32, tid, full3);
    CPA_COMMIT();

    int st = 0;
    for (int k = 0; k < NCHUNK; k++) {
        if (k + 1 < NCHUNK) { CPA_WAIT(1); } else { CPA_WAIT(0); }
        __syncthreads();
        if (k + 2 < NCHUNK) {
            int ls = st + 2; if (ls >= NSTAGE) ls -= NSTAGE;
            load_stage(sb + ls * STAGEB, Ahi, Alo, Whi, Wlo, m0, n0, (k + 2) * 32, tid, full3);
            CPA_COMMIT();
        }

        const uint32_t cs  = sb + st * STAGEB;
        const uint32_t sAh = cs, sAl = cs + TILEB, sBh = cs + 2 * TILEB, sBl = cs + 3 * TILEB;

#pragma unroll
        for (int kk = 0; kk < 2; kk++) {
            const int kc = kk * 2;
            uint32_t ah[2][4], al[2][4];
#pragma unroll
            for (int mt = 0; mt < 2; mt++) {
                uint32_t o = sw_off(wm + mt * 16 + a_row, kc + a_kc);
                LDSM_X4(ah[mt][0], ah[mt][1], ah[mt][2], ah[mt][3], sAh + o);
                if (full3) LDSM_X4(al[mt][0], al[mt][1], al[mt][2], al[mt][3], sAl + o);
            }
#pragma unroll
            for (int ng = 0; ng < 4; ng++) {
                uint32_t bh[4], bl[4];
                uint32_t o = sw_off(wn + ng * 16 + b_row, kc + b_kc);
                LDSM_X4(bh[0], bh[1], bh[2], bh[3], sBh + o);
                LDSM_X4(bl[0], bl[1], bl[2], bl[3], sBl + o);
#pragma unroll
                for (int mt = 0; mt < 2; mt++) {
                    MMA16816(acc[mt][ng * 2 + 0], ah[mt], bh[0], bh[1]);
                    MMA16816(acc[mt][ng * 2 + 0], ah[mt], bl[0], bl[1]);
                    MMA16816(acc[mt][ng * 2 + 1], ah[mt], bh[2], bh[3]);
                    MMA16816(acc[mt][ng * 2 + 1], ah[mt], bl[2], bl[3]);
                    if (full3) {
                        MMA16816(acc[mt][ng * 2 + 0], al[mt], bh[0], bh[1]);
                        MMA16816(acc[mt][ng * 2 + 1], al[mt], bh[2], bh[3]);
                    }
                }
            }
        }
        if (++st == NSTAGE) st = 0;
    }

    const int erow = lane >> 2;
    const int ecol = (lane & 3) * 2;
#pragma unroll
    for (int mt = 0; mt < 2; mt++) {
#pragma unroll
        for (int nt = 0; nt < 8; nt++) {
            int col = n0 + wn + nt * 8 + ecol;
            float b0 = __ldg(bias + col), b1 = __ldg(bias + col + 1);
            int r0 = m0 + wm + mt * 16 + erow;
            float v00 = acc[mt][nt][0] + b0, v01 = acc[mt][nt][1] + b1;
            float v10 = acc[mt][nt][2] + b0, v11 = acc[mt][nt][3] + b1;
            if (SPLIT) {
                __half h0, l0, h1, l1;
                h_split(v00, h0, l0); h_split(v01, h1, l1);
                *(__half2*)(Chi + (size_t)r0 * Nn + col) = __halves2half2(h0, h1);
                if (full3) *(__half2*)(Clo + (size_t)r0 * Nn + col) = __halves2half2(l0, l1);
                h_split(v10, h0, l0); h_split(v11, h1, l1);
                *(__half2*)(Chi + (size_t)(r0 + 8) * Nn + col) = __halves2half2(h0, h1);
                if (full3) *(__half2*)(Clo + (size_t)(r0 + 8) * Nn + col) = __halves2half2(l0, l1);
            } else {
                *(float2*)(C + (size_t)r0 * Nn + col)       = make_float2(v00, v01);
                *(float2*)(C + (size_t)(r0 + 8) * Nn + col) = make_float2(v10, v11);
            }
        }
    }
}

// ---------------- HMMA attention: 512 thr, fp16 QK^T, reg softmax, P_hi AV ----------------
#define ATT    512
#define KP     224
#define VP     208
#define PSTRB  432
#define PSTRH  216
#define A_KH   0
#define A_VH   (A_KH + KP * 128)          // 28672
#define A_VL   (A_VH + VP * 128)          // 55296
#define A_QH   (A_VL + VP * 128)          // 81920 (2 bufs x 4096)
#define A_PH   (A_QH + 2 * 32 * 128)      // 90112
#define A_PMAX (A_PH + 32 * PSTRB)        // 103936
#define A_PSUM (A_PMAX + 32 * 7 * 4)      // 104832
#define A_TOT  (A_PSUM + 32 * 7 * 4)      // 105728

__global__ __launch_bounds__(ATT, 1) void attn_hmma_kernel(
    const __half* __restrict__ qhi, const __half* __restrict__ qlo,
    const float* __restrict__ bias,
    __half* __restrict__ aohi, __half* __restrict__ aolo)
{
    extern __shared__ char smb[];
    const uint32_t sb = smem_u32(smb);
    const int b = blockIdx.x / HH;
    const int h = blockIdx.x % HH;
    const int tid = threadIdx.x, lane = tid & 31, wid = tid >> 5;
    const __half* bh_ = qhi + (size_t)b * NT * 2304 + h * 64;
    const __half* bl_ = qlo + (size_t)b * NT * 2304 + h * 64;
    const float* biasH = bias + (size_t)h * NT * NT;
    float* PMAX = (float*)(smb + A_PMAX);
    float* PSUM = (float*)(smb + A_PSUM);

    for (int i = tid; i < ((KP - NT) * 128) / 4; i += ATT)
        ((uint32_t*)(smb + A_KH + NT * 128))[i] = 0;
    for (int i = tid; i < ((VP - NT) * 128) / 4; i += ATT) {
        ((uint32_t*)(smb + A_VH + NT * 128))[i] = 0;
        ((uint32_t*)(smb + A_VL + NT * 128))[i] = 0;
    }
    for (int i = tid; i < (32 * PSTRB) / 4; i += ATT)
        ((uint32_t*)(smb + A_PH))[i] = 0;

    for (int p = tid; p < NT * 8; p += ATT) {
        int row = p >> 3, c = p & 7;
        uint32_t o = swb(row, c);
        size_t goff = (size_t)row * 2304 + 768 + c * 8;
        CPA16(sb + A_KH + o, bh_ + goff);
        CPA16(sb + A_VH + o, bh_ + goff + 768);
        CPA16(sb + A_VL + o, bl_ + goff + 768);
    }
    for (int p = tid; p < 32 * 8; p += ATT) {
        int r = p >> 3, c = p & 7;
        int gr = (r < NT) ? r : 0;
        size_t goff = (size_t)gr * 2304 + c * 8;
        CPA16(sb + A_QH + swb(r, c), bh_ + goff);
    }
    CPA_COMMIT();
    CPA_WAIT(0);
    __syncthreads();

    const int a_row16 = lane & 15;
    const int a_kc1   = lane >> 4;
    const int b_row8  = (lane & 7) + ((lane >> 4) << 3);
    const int b_kc1   = (lane >> 3) & 1;

    // AV warp geometry (fixed across qt)
    const int av_wm = (wid & 1) * 16;
    const int av_wd = (wid >> 1) * 8;

    // hoist V_hi fragments (q-tile-invariant)
    uint32_t vfh[13][2];
#pragma unroll
    for (int kk = 0; kk < 13; kk++) {
        uint32_t boff = swb(kk * 16 + (lane & 15), av_wd >> 3);
        LDSM_X2_T(vfh[kk][0], vfh[kk][1], sb + A_VH + boff);
    }

    for (int qt = 0; qt < 7; qt++) {
        const int r0 = qt * 32;
        const int rows = min(32, NT - r0);
        const uint32_t qbuf = (uint32_t)((qt & 1) * 4096);

        // S-phase registers live across pass 1 / pass 2
        float acc[4][4];
        const int s_wm = (wid & 1) * 16;
        const int s_wn = (wid >> 1) * 32;
        const int erow = s_wm + (lane >> 2);     // local rows erow, erow+8
        const int ecol = (lane & 3) * 2;
        const int grp = wid >> 1;                // 0..6 for wid<14

        // ---- pass 1: S = 0.125*(q_hi k_hi^T) + bias in regs; partial row-max ----
        if (wid < 14) {
#pragma unroll
            for (int t = 0; t < 4; t++)
#pragma unroll
                for (int e = 0; e < 4; e++) acc[t][e] = 0.f;

            const int ar = s_wm + a_row16;
#pragma unroll
            for (int kk = 0; kk < 4; kk++) {
                uint32_t aoff = swb(ar, kk * 2 + a_kc1) + qbuf;
                uint32_t ah[4];
                LDSM_X4(ah[0], ah[1], ah[2], ah[3], sb + A_QH + aoff);
#pragma unroll
                for (int ng = 0; ng < 2; ng++) {
                    uint32_t boff = swb(s_wn + ng * 16 + b_row8, kk * 2 + b_kc1);
                    uint32_t bh[4];
                    LDSM_X4(bh[0], bh[1], bh[2], bh[3], sb + A_KH + boff);
                    MMA16816(acc[ng * 2 + 0], ah, bh[0], bh[1]);
                    MMA16816(acc[ng * 2 + 1], ah, bh[2], bh[3]);
                }
            }
            float pm0 = -3.4e38f, pm1 = -3.4e38f;
#pragma unroll
            for (int nt = 0; nt < 4; nt++) {
                int col = s_wn + nt * 8 + ecol;
                int gr0 = r0 + erow, gr1 = r0 + erow + 8;
                float b00 = 0.f, b01 = 0.f, b10 = 0.f, b11 = 0.f;
                if (col < NT) {
                    bool c1 = (col + 1 < NT);
                    if (gr0 < NT) {
                        b00 = biasH[(size_t)gr0 * NT + col];
                        if (c1) b01 = biasH[(size_t)gr0 * NT + col + 1];
                    }
                    if (gr1 < NT) {
                        b10 = biasH[(size_t)gr1 * NT + col];
                        if (c1) b11 = biasH[(size_t)gr1 * NT + col + 1];
                    }
                }
                acc[nt][0] = acc[nt][0] * 0.125f + b00;
                acc[nt][1] = acc[nt][1] * 0.125f + b01;
                acc[nt][2] = acc[nt][2] * 0.125f + b10;
                acc[nt][3] = acc[nt][3] * 0.125f + b11;
                if (col < NT)     { pm0 = fmaxf(pm0, acc[nt][0]); pm1 = fmaxf(pm1, acc[nt][2]); }
                if (col + 1 < NT) { pm0 = fmaxf(pm0, acc[nt][1]); pm1 = fmaxf(pm1, acc[nt][3]); }
            }
            pm0 = fmaxf(pm0, __shfl_xor_sync(0xffffffffu, pm0, 1));
            pm0 = fmaxf(pm0, __shfl_xor_sync(0xffffffffu, pm0, 2));
            pm1 = fmaxf(pm1, __shfl_xor_sync(0xffffffffu, pm1, 1));
            pm1 = fmaxf(pm1, __shfl_xor_sync(0xffffffffu, pm1, 2));
            if ((lane & 3) == 0) {
                PMAX[erow * 7 + grp]       = pm0;
                PMAX[(erow + 8) * 7 + grp] = pm1;
            }
        }
        __syncthreads();

        // Q prefetch for next tile (hi only)
        if (qt + 1 < 7) {
            const int nr0 = (qt + 1) * 32;
            const uint32_t nqb = (uint32_t)(((qt + 1) & 1) * 4096);
            for (int p = tid; p < 32 * 8; p += ATT) {
                int r = p >> 3, c = p & 7;
                int gr = (nr0 + r < NT) ? (nr0 + r) : 0;
                size_t goff = (size_t)gr * 2304 + c * 8;
                CPA16(sb + A_QH + swb(r, c) + nqb, bh_ + goff);
            }
            CPA_COMMIT();
        }

        // ---- pass 2: exp in regs, write P (fp16 only), partial row-sum ----
        if (wid < 14) {
            float gm0 = PMAX[erow * 7], gm1 = PMAX[(erow + 8) * 7];
#pragma unroll
            for (int g = 1; g < 7; g++) {
                gm0 = fmaxf(gm0, PMAX[erow * 7 + g]);
                gm1 = fmaxf(gm1, PMAX[(erow + 8) * 7 + g]);
            }
            __half* PH = (__half*)(smb + A_PH);
            float ps0 = 0.f, ps1 = 0.f;
#pragma unroll
            for (int nt = 0; nt < 4; nt++) {
                int col = s_wn + nt * 8 + ecol;
                if (col < NT) {
                    float e00 = __expf(acc[nt][0] - gm0);
                    float e01 = __expf(acc[nt][1] - gm0);
                    float e10 = __expf(acc[nt][2] - gm1);
                    float e11 = __expf(acc[nt][3] - gm1);
                    if (col + 1 >= NT) { e01 = 0.f; e11 = 0.f; }
                    ps0 += e00 + e01;
                    ps1 += e10 + e11;
                    *(__half2*)(PH + erow * PSTRH + col) =
                        __halves2half2(__float2half_rn(e00), __float2half_rn(e01));
                    *(__half2*)(PH + (erow + 8) * PSTRH + col) =
                        __halves2half2(__float2half_rn(e10), __float2half_rn(e11));
                }
            }
            ps0 += __shfl_xor_sync(0xffffffffu, ps0, 1);
            ps0 += __shfl_xor_sync(0xffffffffu, ps0, 2);
            ps1 += __shfl_xor_sync(0xffffffffu, ps1, 1);
            ps1 += __shfl_xor_sync(0xffffffffu, ps1, 2);
            if ((lane & 3) == 0) {
                PSUM[erow * 7 + grp]       = ps0;
                PSUM[(erow + 8) * 7 + grp] = ps1;
            }
        }
        __syncthreads();

        // ---- AV = P_hi * (V_hi + V_lo) : 16 warps, each 16x8 ----
        {
            float acv[4];
#pragma unroll
            for (int e = 0; e < 4; e++) acv[e] = 0.f;

            const int ar = av_wm + a_row16;
#pragma unroll
            for (int kk = 0; kk < 13; kk++) {
                uint32_t aoff = (uint32_t)(ar * PSTRB + (kk * 2 + a_kc1) * 16);
                uint32_t ah[4];
                LDSM_X4(ah[0], ah[1], ah[2], ah[3], sb + A_PH + aoff);
                uint32_t boff = swb(kk * 16 + (lane & 15), av_wd >> 3);
                uint32_t bl0, bl1;
                LDSM_X2_T(bl0, bl1, sb + A_VL + boff);
                MMA16816(acv, ah, vfh[kk][0], vfh[kk][1]);
                MMA16816(acv, ah, bl0, bl1);
            }
            const int oerow = av_wm + (lane >> 2);
            const int ec = (lane & 3) * 2;
#pragma unroll
            for (int hf = 0; hf < 2; hf++) {
                int rr = oerow + hf * 8;
                if (rr < rows) {
                    float s = PSUM[rr * 7];
#pragma unroll
                    for (int g = 1; g < 7; g++) s += PSUM[rr * 7 + g];
                    float inv = 1.f / s;
                    size_t gb = ((size_t)b * NT + r0 + rr) * DIM_ + h * 64 + av_wd;
                    __half h0, l0, h1, l1;
                    h_split(acv[hf * 2 + 0] * inv, h0, l0);
                    h_split(acv[hf * 2 + 1] * inv, h1, l1);
                    *(__half2*)(aohi + gb + ec) = __halves2half2(h0, h1);
                    *(__half2*)(aolo + gb + ec) = __halves2half2(l0, l1);
                }
            }
        }
        if (qt + 1 < 7) { CPA_WAIT(0); }
        __syncthreads();
    }
}

// ---------------- launch ----------------
extern "C" void kernel_launch(void* const* d_in, const int* in_sizes, int n_in,
                              void* d_out, int out_size)
{
    const float* x      = (const float*)d_in[0];
    const float* qkv_w  = (const float*)d_in[1];
    const float* qkv_b  = (const float*)d_in[2];
    const float* proj_w = (const float*)d_in[3];
    const float* proj_b = (const float*)d_in[4];
    const float* table  = (const float*)d_in[5];
    const int*   relidx = (const int*)d_in[6];
    float* out = (float*)d_out;

    float *p_bias;
    __half *p_qhi, *p_qlo, *p_xhi, *p_xlo, *p_aohi, *p_aolo;
    __half *p_qwhi, *p_qwlo, *p_pwhi, *p_pwlo;
    cudaGetSymbolAddress((void**)&p_qhi,  g_qhi);
    cudaGetSymbolAddress((void**)&p_qlo,  g_qlo);
    cudaGetSymbolAddress((void**)&p_xhi,  g_xhi);
    cudaGetSymbolAddress((void**)&p_xlo,  g_xlo);
    cudaGetSymbolAddress((void**)&p_aohi, g_aohi);
    cudaGetSymbolAddress((void**)&p_aolo, g_aolo);
    cudaGetSymbolAddress((void**)&p_qwhi, g_qwhi);
    cudaGetSymbolAddress((void**)&p_qwlo, g_qwlo);
    cudaGetSymbolAddress((void**)&p_pwhi, g_pwhi);
    cudaGetSymbolAddress((void**)&p_pwlo, g_pwlo);
    cudaGetSymbolAddress((void**)&p_bias, g_bias);

    cudaFuncSetAttribute(attn_hmma_kernel, cudaFuncAttributeMaxDynamicSharedMemorySize, A_TOT);
    cudaFuncSetAttribute(gemm_hmma_kernel<true>,  cudaFuncAttributeMaxDynamicSharedMemorySize, GSMEM);
    cudaFuncSetAttribute(gemm_hmma_kernel<false>, cudaFuncAttributeMaxDynamicSharedMemorySize, GSMEM);

    const int n0 = MTOK * DIM_;
    const int n1 = 2304 * DIM_;
    const int n2 = DIM_ * DIM_;
    split3_kernel<<<(n0 + n1 + n2 + 255) / 256, 256>>>(
        x, p_xhi, p_xlo, n0,
        qkv_w, p_qwhi, p_qwlo, n1,
        proj_w, p_pwhi, p_pwlo, n2);

    bias_kernel<<<(HH * NT * NT + 255) / 256, 256>>>(table, relidx, p_bias);

    // QKV: q,k tiles (cols < 1536) use 2-term, no lo store; v tiles 3-term
    dim3 g1(2304 / 128, MTOK / 128);
    gemm_hmma_kernel<true><<<g1, 256, GSMEM>>>(p_xhi, p_xlo, p_qwhi, p_qwlo, qkv_b,
                                               nullptr, p_qhi, p_qlo, 2304, 1536);

    attn_hmma_kernel<<<B_ * HH, ATT, A_TOT>>>(p_qhi, p_qlo, p_bias, p_aohi, p_aolo);

    // proj: always 3-term (nFull3 = 0)
    dim3 g2(DIM_ / 128, MTOK / 128);
    gemm_hmma_kernel<false><<<g2, 256, GSMEM>>>(p_aohi, p_aolo, p_pwhi, p_pwlo, proj_b,
                                                out, nullptr, nullptr, DIM_, 0);
}

// round 15
// speedup vs baseline: 1.4749x; 1.0495x over previous
#include <cuda_runtime.h>
#include <cuda_fp16.h>
#include <cstdint>

#define B_   128
#define NT   197
#define HH   12
#define HD   64
#define DIM_ 768
#define MTOK (B_ * NT)          // 25216 = 197*128

// ---------------- scratch ----------------
__device__ __half g_qhi [(long long)MTOK * 2304];
__device__ __half g_xhi [(long long)MTOK * DIM_];
__device__ __half g_xlo [(long long)MTOK * DIM_];
__device__ __half g_aohi[(long long)MTOK * DIM_];
__device__ __half g_aolo[(long long)MTOK * DIM_];
__device__ __half g_qwhi[2304 * DIM_];
__device__ __half g_qwlo[2304 * DIM_];
__device__ __half g_pwhi[DIM_ * DIM_];
__device__ __half g_pwlo[DIM_ * DIM_];
__device__ float  g_bias[HH * NT * NT];

// ---------------- helpers ----------------
__device__ __forceinline__ uint32_t smem_u32(const void* p) {
    uint32_t a;
    asm("{ .reg .u64 t; cvta.to.shared.u64 t, %1; cvt.u32.u64 %0, t; }" : "=r"(a) : "l"(p));
    return a;
}

#define CPA16(dst, src)   asm volatile("cp.async.cg.shared.global [%0], [%1], 16;" :: "r"(dst), "l"(src) : "memory")
#define CPA_COMMIT()      asm volatile("cp.async.commit_group;" ::: "memory")
#define CPA_WAIT(n)       asm volatile("cp.async.wait_group %0;" :: "n"(n) : "memory")

#define LDSM_X4(r0, r1, r2, r3, addr) \
    asm volatile("ldmatrix.sync.aligned.m8n8.x4.shared.b16 {%0,%1,%2,%3}, [%4];" \
        : "=r"(r0), "=r"(r1), "=r"(r2), "=r"(r3) : "r"(addr))

#define LDSM_X2_T(r0, r1, addr) \
    asm volatile("ldmatrix.sync.aligned.m8n8.x2.trans.shared.b16 {%0,%1}, [%2];" \
        : "=r"(r0), "=r"(r1) : "r"(addr))

#define MMA16816(d, a, b0, b1) \
    asm volatile("mma.sync.aligned.m16n8k16.row.col.f32.f16.f16.f32 " \
        "{%0,%1,%2,%3}, {%4,%5,%6,%7}, {%8,%9}, {%0,%1,%2,%3};" \
        : "+f"((d)[0]), "+f"((d)[1]), "+f"((d)[2]), "+f"((d)[3]) \
        : "r"((a)[0]), "r"((a)[1]), "r"((a)[2]), "r"((a)[3]), "r"(b0), "r"(b1))

// swizzled tile offset for 64B rows (gemm tiles): chunk 0..3
__device__ __forceinline__ uint32_t sw_off(int row, int chunk) {
    return (uint32_t)(row * 64 + ((chunk ^ ((row >> 1) & 3)) << 4));
}
// swizzled offset for 128B rows (attention tiles): chunk 0..7
__device__ __forceinline__ uint32_t swb(int row, int chunk) {
    return (uint32_t)(row * 128 + ((chunk ^ (row & 7)) << 4));
}

static __device__ __forceinline__ void h_split(float v, __half& hi, __half& lo) {
    hi = __float2half_rn(v);
    lo = __float2half_rn(v - __half2float(hi));
}

// ---------------- merged elementwise fp16 split (3 arrays, 1 launch) ----------------
__global__ void split3_kernel(const float* __restrict__ in0, __half* __restrict__ hi0, __half* __restrict__ lo0, int n0,
                              const float* __restrict__ in1, __half* __restrict__ hi1, __half* __restrict__ lo1, int n1,
                              const float* __restrict__ in2, __half* __restrict__ hi2, __half* __restrict__ lo2, int n2)
{
    int t = blockIdx.x * 256 + threadIdx.x;
    const float* in; __half *hi, *lo;
    if (t < n0)               { in = in0;  hi = hi0; lo = lo0; }
    else if (t < n0 + n1)     { t -= n0;       in = in1; hi = hi1; lo = lo1; }
    else if (t < n0 + n1 + n2){ t -= n0 + n1;  in = in2; hi = hi2; lo = lo2; }
    else return;
    __half h, l;
    h_split(in[t], h, l);
    hi[t] = h; lo[t] = l;
}

// ---------------- bias gather ----------------
__global__ void bias_kernel(const float* __restrict__ table,
                            const int*   __restrict__ idx,
                            float* __restrict__ out)
{
    int t = blockIdx.x * blockDim.x + threadIdx.x;
    if (t < HH * NT * NT) {
        int ij = t % (NT * NT);
        int h  = t / (NT * NT);
        out[t] = table[idx[ij] * HH + h];
    }
}

// ---------------- FP16 mma.sync GEMM, 3-stage pipeline ----------------
// full3=true : 3-term (ah*bh + ah*bl + al*bh), loads A hi/lo + W hi/lo
// full3=false: 1-term (ah*bh only), loads A hi + W hi only
#define GK     768
#define NCHUNK 24
#define TILEB  8192
#define STAGEB (4 * TILEB)
#define NSTAGE 3
#define GSMEM  (NSTAGE * STAGEB)       // 96 KB

static __device__ __forceinline__ void load_stage(
    uint32_t sb, const __half* __restrict__ Ahi, const __half* __restrict__ Alo,
    const __half* __restrict__ Whi, const __half* __restrict__ Wlo,
    int m0, int n0, int k0, int tid, bool full3)
{
#pragma unroll
    for (int j = 0; j < 2; j++) {
        int id = tid + (j << 8);
        int row = id >> 2, c = id & 3;
        uint32_t o = sw_off(row, c);
        size_t ga = (size_t)(m0 + row) * GK + k0 + c * 8;
        size_t gb = (size_t)(n0 + row) * GK + k0 + c * 8;
        CPA16(sb + o,             Ahi + ga);
        CPA16(sb + 2 * TILEB + o, Whi + gb);
        if (full3) {
            CPA16(sb + TILEB + o,     Alo + ga);
            CPA16(sb + 3 * TILEB + o, Wlo + gb);
        }
    }
}

template<bool SPLIT>
__global__ __launch_bounds__(256, 2)
void gemm_hmma_kernel(const __half* __restrict__ Ahi, const __half* __restrict__ Alo,
                      const __half* __restrict__ Whi, const __half* __restrict__ Wlo,
                      const float* __restrict__ bias, float* __restrict__ C,
                      __half* __restrict__ Chi,
                      int Nn, int nFull3)
{
    extern __shared__ char dsm[];
    const int tid = threadIdx.x;
    const int lane = tid & 31;
    const int wid = tid >> 5;
    const int wm = (wid & 3) * 32;
    const int wn = (wid >> 2) * 64;
    const int m0 = blockIdx.y * 128;
    const int n0 = blockIdx.x * 128;
    const uint32_t sb = smem_u32(dsm);
    const bool full3 = (n0 >= nFull3);   // v-tiles and proj keep 3-term

    float acc[2][8][4];
#pragma unroll
    for (int mt = 0; mt < 2; mt++)
#pragma unroll
        for (int nt = 0; nt < 8; nt++)
#pragma unroll
            for (int e = 0; e < 4; e++) acc[mt][nt][e] = 0.f;

    const int a_row = lane & 15;
    const int a_kc  = lane >> 4;
    const int b_row = (lane & 7) + ((lane >> 4) << 3);
    const int b_kc  = (lane >> 3) & 1;

    load_stage(sb,          Ahi, Alo, Whi, Wlo, m0, n0, 0,  tid, full3);
    CPA_COMMIT();
    load_stage(sb + STAGEB, Ahi, Alo, Whi, Wlo, m0, n0, 32, tid, full3);
    CPA_COMMIT();

    int st = 0;
    for (int k = 0; k < NCHUNK; k++) {
        if (k + 1 < NCHUNK) { CPA_WAIT(1); } else { CPA_WAIT(0); }
        __syncthreads();
        if (k + 2 < NCHUNK) {
            int ls = st + 2; if (ls >= NSTAGE) ls -= NSTAGE;
            load_stage(sb + ls * STAGEB, Ahi, Alo, Whi, Wlo, m0, n0, (k + 2) * 32, tid, full3);
            CPA_COMMIT();
        }

        const uint32_t cs  = sb + st * STAGEB;
        const uint32_t sAh = cs, sAl = cs + TILEB, sBh = cs + 2 * TILEB, sBl = cs + 3 * TILEB;

#pragma unroll
        for (int kk = 0; kk < 2; kk++) {
            const int kc = kk * 2;
            uint32_t ah[2][4], al[2][4];
#pragma unroll
            for (int mt = 0; mt < 2; mt++) {
                uint32_t o = sw_off(wm + mt * 16 + a_row, kc + a_kc);
                LDSM_X4(ah[mt][0], ah[mt][1], ah[mt][2], ah[mt][3], sAh + o);
                if (full3) LDSM_X4(al[mt][0], al[mt][1], al[mt][2], al[mt][3], sAl + o);
            }
#pragma unroll
            for (int ng = 0; ng < 4; ng++) {
                uint32_t bh[4], bl[4];
                uint32_t o = sw_off(wn + ng * 16 + b_row, kc + b_kc);
                LDSM_X4(bh[0], bh[1], bh[2], bh[3], sBh + o);
                if (full3) LDSM_X4(bl[0], bl[1], bl[2], bl[3], sBl + o);
#pragma unroll
                for (int mt = 0; mt < 2; mt++) {
                    MMA16816(acc[mt][ng * 2 + 0], ah[mt], bh[0], bh[1]);
                    MMA16816(acc[mt][ng * 2 + 1], ah[mt], bh[2], bh[3]);
                    if (full3) {
                        MMA16816(acc[mt][ng * 2 + 0], ah[mt], bl[0], bl[1]);
                        MMA16816(acc[mt][ng * 2 + 0], al[mt], bh[0], bh[1]);
                        MMA16816(acc[mt][ng * 2 + 1], ah[mt], bl[2], bl[3]);
                        MMA16816(acc[mt][ng * 2 + 1], al[mt], bh[2], bh[3]);
                    }
                }
            }
        }
        if (++st == NSTAGE) st = 0;
    }

    const int erow = lane >> 2;
    const int ecol = (lane & 3) * 2;
#pragma unroll
    for (int mt = 0; mt < 2; mt++) {
#pragma unroll
        for (int nt = 0; nt < 8; nt++) {
            int col = n0 + wn + nt * 8 + ecol;
            float b0 = __ldg(bias + col), b1 = __ldg(bias + col + 1);
            int r0 = m0 + wm + mt * 16 + erow;
            float v00 = acc[mt][nt][0] + b0, v01 = acc[mt][nt][1] + b1;
            float v10 = acc[mt][nt][2] + b0, v11 = acc[mt][nt][3] + b1;
            if (SPLIT) {
                *(__half2*)(Chi + (size_t)r0 * Nn + col) =
                    __halves2half2(__float2half_rn(v00), __float2half_rn(v01));
                *(__half2*)(Chi + (size_t)(r0 + 8) * Nn + col) =
                    __halves2half2(__float2half_rn(v10), __float2half_rn(v11));
            } else {
                *(float2*)(C + (size_t)r0 * Nn + col)       = make_float2(v00, v01);
                *(float2*)(C + (size_t)(r0 + 8) * Nn + col) = make_float2(v10, v11);
            }
        }
    }
}

// ---------------- HMMA attention: fp16 QK^T + fp16 PV (hi only), reg softmax ----------------
#define ATT    512
#define KP     224
#define VP     208
#define PSTRB  432
#define PSTRH  216
#define A_KH   0
#define A_VH   (A_KH + KP * 128)          // 28672
#define A_QH   (A_VH + VP * 128)          // 55296 (2 bufs x 4096)
#define A_PH   (A_QH + 2 * 32 * 128)      // 63488
#define A_PMAX (A_PH + 32 * PSTRB)        // 77312
#define A_PSUM (A_PMAX + 32 * 7 * 4)      // 78208
#define A_TOT  (A_PSUM + 32 * 7 * 4)      // 79104

__global__ __launch_bounds__(ATT, 1) void attn_hmma_kernel(
    const __half* __restrict__ qhi,
    const float* __restrict__ bias,
    __half* __restrict__ aohi, __half* __restrict__ aolo)
{
    extern __shared__ char smb[];
    const uint32_t sb = smem_u32(smb);
    const int b = blockIdx.x / HH;
    const int h = blockIdx.x % HH;
    const int tid = threadIdx.x, lane = tid & 31, wid = tid >> 5;
    const __half* bh_ = qhi + (size_t)b * NT * 2304 + h * 64;
    const float* biasH = bias + (size_t)h * NT * NT;
    float* PMAX = (float*)(smb + A_PMAX);
    float* PSUM = (float*)(smb + A_PSUM);

    for (int i = tid; i < ((KP - NT) * 128) / 4; i += ATT)
        ((uint32_t*)(smb + A_KH + NT * 128))[i] = 0;
    for (int i = tid; i < ((VP - NT) * 128) / 4; i += ATT)
        ((uint32_t*)(smb + A_VH + NT * 128))[i] = 0;
    for (int i = tid; i < (32 * PSTRB) / 4; i += ATT)
        ((uint32_t*)(smb + A_PH))[i] = 0;

    for (int p = tid; p < NT * 8; p += ATT) {
        int row = p >> 3, c = p & 7;
        uint32_t o = swb(row, c);
        size_t goff = (size_t)row * 2304 + 768 + c * 8;
        CPA16(sb + A_KH + o, bh_ + goff);
        CPA16(sb + A_VH + o, bh_ + goff + 768);
    }
    for (int p = tid; p < 32 * 8; p += ATT) {
        int r = p >> 3, c = p & 7;
        int gr = (r < NT) ? r : 0;
        size_t goff = (size_t)gr * 2304 + c * 8;
        CPA16(sb + A_QH + swb(r, c), bh_ + goff);
    }
    CPA_COMMIT();
    CPA_WAIT(0);
    __syncthreads();

    const int a_row16 = lane & 15;
    const int a_kc1   = lane >> 4;
    const int b_row8  = (lane & 7) + ((lane >> 4) << 3);
    const int b_kc1   = (lane >> 3) & 1;

    // AV warp geometry (fixed across qt)
    const int av_wm = (wid & 1) * 16;
    const int av_wd = (wid >> 1) * 8;

    // hoist V_hi fragments (q-tile-invariant)
    uint32_t vfh[13][2];
#pragma unroll
    for (int kk = 0; kk < 13; kk++) {
        uint32_t boff = swb(kk * 16 + (lane & 15), av_wd >> 3);
        LDSM_X2_T(vfh[kk][0], vfh[kk][1], sb + A_VH + boff);
    }

    for (int qt = 0; qt < 7; qt++) {
        const int r0 = qt * 32;
        const int rows = min(32, NT - r0);
        const uint32_t qbuf = (uint32_t)((qt & 1) * 4096);

        // S-phase registers live across pass 1 / pass 2
        float acc[4][4];
        const int s_wm = (wid & 1) * 16;
        const int s_wn = (wid >> 1) * 32;
        const int erow = s_wm + (lane >> 2);
        const int ecol = (lane & 3) * 2;
        const int grp = wid >> 1;                // 0..6 for wid<14

        // ---- pass 1: S = 0.125*(q_hi k_hi^T) + bias; partial row-max ----
        if (wid < 14) {
#pragma unroll
            for (int t = 0; t < 4; t++)
#pragma unroll
                for (int e = 0; e < 4; e++) acc[t][e] = 0.f;

            const int ar = s_wm + a_row16;
#pragma unroll
            for (int kk = 0; kk < 4; kk++) {
                uint32_t aoff = swb(ar, kk * 2 + a_kc1) + qbuf;
                uint32_t ah[4];
                LDSM_X4(ah[0], ah[1], ah[2], ah[3], sb + A_QH + aoff);
#pragma unroll
                for (int ng = 0; ng < 2; ng++) {
                    uint32_t boff = swb(s_wn + ng * 16 + b_row8, kk * 2 + b_kc1);
                    uint32_t bh[4];
                    LDSM_X4(bh[0], bh[1], bh[2], bh[3], sb + A_KH + boff);
                    MMA16816(acc[ng * 2 + 0], ah, bh[0], bh[1]);
                    MMA16816(acc[ng * 2 + 1], ah, bh[2], bh[3]);
                }
            }
            float pm0 = -3.4e38f, pm1 = -3.4e38f;
#pragma unroll
            for (int nt = 0; nt < 4; nt++) {
                int col = s_wn + nt * 8 + ecol;
                int gr0 = r0 + erow, gr1 = r0 + erow + 8;
                float b00 = 0.f, b01 = 0.f, b10 = 0.f, b11 = 0.f;
                if (col < NT) {
                    bool c1 = (col + 1 < NT);
                    if (gr0 < NT) {
                        b00 = biasH[(size_t)gr0 * NT + col];
                        if (c1) b01 = biasH[(size_t)gr0 * NT + col + 1];
                    }
                    if (gr1 < NT) {
                        b10 = biasH[(size_t)gr1 * NT + col];
                        if (c1) b11 = biasH[(size_t)gr1 * NT + col + 1];
                    }
                }
                acc[nt][0] = acc[nt][0] * 0.125f + b00;
                acc[nt][1] = acc[nt][1] * 0.125f + b01;
                acc[nt][2] = acc[nt][2] * 0.125f + b10;
                acc[nt][3] = acc[nt][3] * 0.125f + b11;
                if (col < NT)     { pm0 = fmaxf(pm0, acc[nt][0]); pm1 = fmaxf(pm1, acc[nt][2]); }
                if (col + 1 < NT) { pm0 = fmaxf(pm0, acc[nt][1]); pm1 = fmaxf(pm1, acc[nt][3]); }
            }
            pm0 = fmaxf(pm0, __shfl_xor_sync(0xffffffffu, pm0, 1));
            pm0 = fmaxf(pm0, __shfl_xor_sync(0xffffffffu, pm0, 2));
            pm1 = fmaxf(pm1, __shfl_xor_sync(0xffffffffu, pm1, 1));
            pm1 = fmaxf(pm1, __shfl_xor_sync(0xffffffffu, pm1, 2));
            if ((lane & 3) == 0) {
                PMAX[erow * 7 + grp]       = pm0;
                PMAX[(erow + 8) * 7 + grp] = pm1;
            }
        }
        __syncthreads();

        // Q prefetch for next tile
        if (qt + 1 < 7) {
            const int nr0 = (qt + 1) * 32;
            const uint32_t nqb = (uint32_t)(((qt + 1) & 1) * 4096);
            for (int p = tid; p < 32 * 8; p += ATT) {
                int r = p >> 3, c = p & 7;
                int gr = (nr0 + r < NT) ? (nr0 + r) : 0;
                size_t goff = (size_t)gr * 2304 + c * 8;
                CPA16(sb + A_QH + swb(r, c) + nqb, bh_ + goff);
            }
            CPA_COMMIT();
        }

        // ---- pass 2: exp in regs, write P (fp16), partial row-sum ----
        if (wid < 14) {
            float gm0 = PMAX[erow * 7], gm1 = PMAX[(erow + 8) * 7];
#pragma unroll
            for (int g = 1; g < 7; g++) {
                gm0 = fmaxf(gm0, PMAX[erow * 7 + g]);
                gm1 = fmaxf(gm1, PMAX[(erow + 8) * 7 + g]);
            }
            __half* PH = (__half*)(smb + A_PH);
            float ps0 = 0.f, ps1 = 0.f;
#pragma unroll
            for (int nt = 0; nt < 4; nt++) {
                int col = s_wn + nt * 8 + ecol;
                if (col < NT) {
                    float e00 = __expf(acc[nt][0] - gm0);
                    float e01 = __expf(acc[nt][1] - gm0);
                    float e10 = __expf(acc[nt][2] - gm1);
                    float e11 = __expf(acc[nt][3] - gm1);
                    if (col + 1 >= NT) { e01 = 0.f; e11 = 0.f; }
                    ps0 += e00 + e01;
                    ps1 += e10 + e11;
                    *(__half2*)(PH + erow * PSTRH + col) =
                        __halves2half2(__float2half_rn(e00), __float2half_rn(e01));
                    *(__half2*)(PH + (erow + 8) * PSTRH + col) =
                        __halves2half2(__float2half_rn(e10), __float2half_rn(e11));
                }
            }
            ps0 += __shfl_xor_sync(0xffffffffu, ps0, 1);
            ps0 += __shfl_xor_sync(0xffffffffu, ps0, 2);
            ps1 += __shfl_xor_sync(0xffffffffu, ps1, 1);
            ps1 += __shfl_xor_sync(0xffffffffu, ps1, 2);
            if ((lane & 3) == 0) {
                PSUM[erow * 7 + grp]       = ps0;
                PSUM[(erow + 8) * 7 + grp] = ps1;
            }
        }
        __syncthreads();

        // ---- AV = P_hi * V_hi : 16 warps, each 16x8; V_hi from registers ----
        {
            float acv[4];
#pragma unroll
            for (int e = 0; e < 4; e++) acv[e] = 0.f;

            const int ar = av_wm + a_row16;
#pragma unroll
            for (int kk = 0; kk < 13; kk++) {
                uint32_t aoff = (uint32_t)(ar * PSTRB + (kk * 2 + a_kc1) * 16);
                uint32_t ah[4];
                LDSM_X4(ah[0], ah[1], ah[2], ah[3], sb + A_PH + aoff);
                MMA16816(acv, ah, vfh[kk][0], vfh[kk][1]);
            }
            const int oerow = av_wm + (lane >> 2);
            const int ec = (lane & 3) * 2;
#pragma unroll
            for (int hf = 0; hf < 2; hf++) {
                int rr = oerow + hf * 8;
                if (rr < rows) {
                    float s = PSUM[rr * 7];
#pragma unroll
                    for (int g = 1; g < 7; g++) s += PSUM[rr * 7 + g];
                    float inv = 1.f / s;
                    size_t gb = ((size_t)b * NT + r0 + rr) * DIM_ + h * 64 + av_wd;
                    __half h0, l0, h1, l1;
                    h_split(acv[hf * 2 + 0] * inv, h0, l0);
                    h_split(acv[hf * 2 + 1] * inv, h1, l1);
                    *(__half2*)(aohi + gb + ec) = __halves2half2(h0, h1);
                    *(__half2*)(aolo + gb + ec) = __halves2half2(l0, l1);
                }
            }
        }
        if (qt + 1 < 7) { CPA_WAIT(0); }
        __syncthreads();
    }
}

// ---------------- launch ----------------
extern "C" void kernel_launch(void* const* d_in, const int* in_sizes, int n_in,
                              void* d_out, int out_size)
{
    const float* x      = (const float*)d_in[0];
    const float* qkv_w  = (const float*)d_in[1];
    const float* qkv_b  = (const float*)d_in[2];
    const float* proj_w = (const float*)d_in[3];
    const float* proj_b = (const float*)d_in[4];
    const float* table  = (const float*)d_in[5];
    const int*   relidx = (const int*)d_in[6];
    float* out = (float*)d_out;

    float *p_bias;
    __half *p_qhi, *p_xhi, *p_xlo, *p_aohi, *p_aolo;
    __half *p_qwhi, *p_qwlo, *p_pwhi, *p_pwlo;
    cudaGetSymbolAddress((void**)&p_qhi,  g_qhi);
    cudaGetSymbolAddress((void**)&p_xhi,  g_xhi);
    cudaGetSymbolAddress((void**)&p_xlo,  g_xlo);
    cudaGetSymbolAddress((void**)&p_aohi, g_aohi);
    cudaGetSymbolAddress((void**)&p_aolo, g_aolo);
    cudaGetSymbolAddress((void**)&p_qwhi, g_qwhi);
    cudaGetSymbolAddress((void**)&p_qwlo, g_qwlo);
    cudaGetSymbolAddress((void**)&p_pwhi, g_pwhi);
    cudaGetSymbolAddress((void**)&p_pwlo, g_pwlo);
    cudaGetSymbolAddress((void**)&p_bias, g_bias);

    cudaFuncSetAttribute(attn_hmma_kernel, cudaFuncAttributeMaxDynamicSharedMemorySize, A_TOT);
    cudaFuncSetAttribute(gemm_hmma_kernel<true>,  cudaFuncAttributeMaxDynamicSharedMemorySize, GSMEM);
    cudaFuncSetAttribute(gemm_hmma_kernel<false>, cudaFuncAttributeMaxDynamicSharedMemorySize, GSMEM);

    const int n0 = MTOK * DIM_;
    const int n1 = 2304 * DIM_;
    const int n2 = DIM_ * DIM_;
    split3_kernel<<<(n0 + n1 + n2 + 255) / 256, 256>>>(
        x, p_xhi, p_xlo, n0,
        qkv_w, p_qwhi, p_qwlo, n1,
        proj_w, p_pwhi, p_pwlo, n2);

    bias_kernel<<<(HH * NT * NT + 255) / 256, 256>>>(table, relidx, p_bias);

    // QKV: q,k tiles (cols < 1536) 1-term; v tiles 3-term; fp16 output (hi only)
    dim3 g1(2304 / 128, MTOK / 128);
    gemm_hmma_kernel<true><<<g1, 256, GSMEM>>>(p_xhi, p_xlo, p_qwhi, p_qwlo, qkv_b,
                                               nullptr, p_qhi, 2304, 1536);

    attn_hmma_kernel<<<B_ * HH, ATT, A_TOT>>>(p_qhi, p_bias, p_aohi, p_aolo);

    // proj: always 3-term (nFull3 = 0), fp32 output
    dim3 g2(DIM_ / 128, MTOK / 128);
    gemm_hmma_kernel<false><<<g2, 256, GSMEM>>>(p_aohi, p_aolo, p_pwhi, p_pwlo, proj_b,
                                                out, nullptr, DIM_, 0);
}

// round 16
// speedup vs baseline: 1.4990x; 1.0164x over previous
#include <cuda_runtime.h>
#include <cuda_fp16.h>
#include <cstdint>

#define B_   128
#define NT   197
#define HH   12
#define HD   64
#define DIM_ 768
#define MTOK (B_ * NT)          // 25216 = 197*128

// ---------------- scratch ----------------
__device__ __half g_qhi [(long long)MTOK * 2304];
__device__ __half g_xhi [(long long)MTOK * DIM_];
__device__ __half g_xlo [(long long)MTOK * DIM_];
__device__ __half g_aohi[(long long)MTOK * DIM_];
__device__ __half g_qwhi[2304 * DIM_];
__device__ __half g_qwlo[2304 * DIM_];
__device__ __half g_pwhi[DIM_ * DIM_];
__device__ __half g_pwlo[DIM_ * DIM_];
__device__ float  g_bias[HH * NT * NT];

// ---------------- helpers ----------------
__device__ __forceinline__ uint32_t smem_u32(const void* p) {
    uint32_t a;
    asm("{ .reg .u64 t; cvta.to.shared.u64 t, %1; cvt.u32.u64 %0, t; }" : "=r"(a) : "l"(p));
    return a;
}

#define CPA16(dst, src)   asm volatile("cp.async.cg.shared.global [%0], [%1], 16;" :: "r"(dst), "l"(src) : "memory")
#define CPA_COMMIT()      asm volatile("cp.async.commit_group;" ::: "memory")
#define CPA_WAIT(n)       asm volatile("cp.async.wait_group %0;" :: "n"(n) : "memory")

#define LDSM_X4(r0, r1, r2, r3, addr) \
    asm volatile("ldmatrix.sync.aligned.m8n8.x4.shared.b16 {%0,%1,%2,%3}, [%4];" \
        : "=r"(r0), "=r"(r1), "=r"(r2), "=r"(r3) : "r"(addr))

#define LDSM_X2_T(r0, r1, addr) \
    asm volatile("ldmatrix.sync.aligned.m8n8.x2.trans.shared.b16 {%0,%1}, [%2];" \
        : "=r"(r0), "=r"(r1) : "r"(addr))

#define MMA16816(d, a, b0, b1) \
    asm volatile("mma.sync.aligned.m16n8k16.row.col.f32.f16.f16.f32 " \
        "{%0,%1,%2,%3}, {%4,%5,%6,%7}, {%8,%9}, {%0,%1,%2,%3};" \
        : "+f"((d)[0]), "+f"((d)[1]), "+f"((d)[2]), "+f"((d)[3]) \
        : "r"((a)[0]), "r"((a)[1]), "r"((a)[2]), "r"((a)[3]), "r"(b0), "r"(b1))

// swizzled tile offset for 64B rows (gemm tiles): chunk 0..3
__device__ __forceinline__ uint32_t sw_off(int row, int chunk) {
    return (uint32_t)(row * 64 + ((chunk ^ ((row >> 1) & 3)) << 4));
}
// swizzled offset for 128B rows (attention tiles): chunk 0..7
__device__ __forceinline__ uint32_t swb(int row, int chunk) {
    return (uint32_t)(row * 128 + ((chunk ^ (row & 7)) << 4));
}

static __device__ __forceinline__ void h_split(float v, __half& hi, __half& lo) {
    hi = __float2half_rn(v);
    lo = __float2half_rn(v - __half2float(hi));
}

// ---------------- merged elementwise fp16 split (3 arrays, 1 launch) ----------------
__global__ void split3_kernel(const float* __restrict__ in0, __half* __restrict__ hi0, __half* __restrict__ lo0, int n0,
                              const float* __restrict__ in1, __half* __restrict__ hi1, __half* __restrict__ lo1, int n1,
                              const float* __restrict__ in2, __half* __restrict__ hi2, __half* __restrict__ lo2, int n2)
{
    int t = blockIdx.x * 256 + threadIdx.x;
    const float* in; __half *hi, *lo;
    if (t < n0)               { in = in0;  hi = hi0; lo = lo0; }
    else if (t < n0 + n1)     { t -= n0;       in = in1; hi = hi1; lo = lo1; }
    else if (t < n0 + n1 + n2){ t -= n0 + n1;  in = in2; hi = hi2; lo = lo2; }
    else return;
    __half h, l;
    h_split(in[t], h, l);
    hi[t] = h; lo[t] = l;
}

// ---------------- bias gather ----------------
__global__ void bias_kernel(const float* __restrict__ table,
                            const int*   __restrict__ idx,
                            float* __restrict__ out)
{
    int t = blockIdx.x * blockDim.x + threadIdx.x;
    if (t < HH * NT * NT) {
        int ij = t % (NT * NT);
        int h  = t / (NT * NT);
        out[t] = table[idx[ij] * HH + h];
    }
}

// ---------------- FP16 mma.sync GEMM, 3-stage pipeline ----------------
// Terms: always ah*bh; +ah*bl if useBlo; +al*bh if useAlo.
#define GK     768
#define NCHUNK 24
#define TILEB  8192
#define STAGEB (4 * TILEB)
#define NSTAGE 3
#define GSMEM  (NSTAGE * STAGEB)       // 96 KB

static __device__ __forceinline__ void load_stage(
    uint32_t sb, const __half* __restrict__ Ahi, const __half* __restrict__ Alo,
    const __half* __restrict__ Whi, const __half* __restrict__ Wlo,
    int m0, int n0, int k0, int tid, bool useAlo, bool useBlo)
{
#pragma unroll
    for (int j = 0; j < 2; j++) {
        int id = tid + (j << 8);
        int row = id >> 2, c = id & 3;
        uint32_t o = sw_off(row, c);
        size_t ga = (size_t)(m0 + row) * GK + k0 + c * 8;
        size_t gb = (size_t)(n0 + row) * GK + k0 + c * 8;
        CPA16(sb + o,             Ahi + ga);
        CPA16(sb + 2 * TILEB + o, Whi + gb);
        if (useAlo) CPA16(sb + TILEB + o,     Alo + ga);
        if (useBlo) CPA16(sb + 3 * TILEB + o, Wlo + gb);
    }
}

template<bool SPLIT>
__global__ __launch_bounds__(256, 2)
void gemm_hmma_kernel(const __half* __restrict__ Ahi, const __half* __restrict__ Alo,
                      const __half* __restrict__ Whi, const __half* __restrict__ Wlo,
                      const float* __restrict__ bias, float* __restrict__ C,
                      __half* __restrict__ Chi,
                      int Nn, int nAlo, int nBlo)
{
    extern __shared__ char dsm[];
    const int tid = threadIdx.x;
    const int lane = tid & 31;
    const int wid = tid >> 5;
    const int wm = (wid & 3) * 32;
    const int wn = (wid >> 2) * 64;
    const int m0 = blockIdx.y * 128;
    const int n0 = blockIdx.x * 128;
    const uint32_t sb = smem_u32(dsm);
    const bool useAlo = (n0 >= nAlo);
    const bool useBlo = (n0 >= nBlo);

    float acc[2][8][4];
#pragma unroll
    for (int mt = 0; mt < 2; mt++)
#pragma unroll
        for (int nt = 0; nt < 8; nt++)
#pragma unroll
            for (int e = 0; e < 4; e++) acc[mt][nt][e] = 0.f;

    const int a_row = lane & 15;
    const int a_kc  = lane >> 4;
    const int b_row = (lane & 7) + ((lane >> 4) << 3);
    const int b_kc  = (lane >> 3) & 1;

    load_stage(sb,          Ahi, Alo, Whi, Wlo, m0, n0, 0,  tid, useAlo, useBlo);
    CPA_COMMIT();
    load_stage(sb + STAGEB, Ahi, Alo, Whi, Wlo, m0, n0, 32, tid, useAlo, useBlo);
    CPA_COMMIT();

    int st = 0;
    for (int k = 0; k < NCHUNK; k++) {
        if (k + 1 < NCHUNK) { CPA_WAIT(1); } else { CPA_WAIT(0); }
        __syncthreads();
        if (k + 2 < NCHUNK) {
            int ls = st + 2; if (ls >= NSTAGE) ls -= NSTAGE;
            load_stage(sb + ls * STAGEB, Ahi, Alo, Whi, Wlo, m0, n0, (k + 2) * 32, tid, useAlo, useBlo);
            CPA_COMMIT();
        }

        const uint32_t cs  = sb + st * STAGEB;
        const uint32_t sAh = cs, sAl = cs + TILEB, sBh = cs + 2 * TILEB, sBl = cs + 3 * TILEB;

#pragma unroll
        for (int kk = 0; kk < 2; kk++) {
            const int kc = kk * 2;
            uint32_t ah[2][4], al[2][4];
#pragma unroll
            for (int mt = 0; mt < 2; mt++) {
                uint32_t o = sw_off(wm + mt * 16 + a_row, kc + a_kc);
                LDSM_X4(ah[mt][0], ah[mt][1], ah[mt][2], ah[mt][3], sAh + o);
                if (useAlo) LDSM_X4(al[mt][0], al[mt][1], al[mt][2], al[mt][3], sAl + o);
            }
#pragma unroll
            for (int ng = 0; ng < 4; ng++) {
                uint32_t bh[4], bl[4];
                uint32_t o = sw_off(wn + ng * 16 + b_row, kc + b_kc);
                LDSM_X4(bh[0], bh[1], bh[2], bh[3], sBh + o);
                if (useBlo) LDSM_X4(bl[0], bl[1], bl[2], bl[3], sBl + o);
#pragma unroll
                for (int mt = 0; mt < 2; mt++) {
                    MMA16816(acc[mt][ng * 2 + 0], ah[mt], bh[0], bh[1]);
                    MMA16816(acc[mt][ng * 2 + 1], ah[mt], bh[2], bh[3]);
                    if (useBlo) {
                        MMA16816(acc[mt][ng * 2 + 0], ah[mt], bl[0], bl[1]);
                        MMA16816(acc[mt][ng * 2 + 1], ah[mt], bl[2], bl[3]);
                    }
                    if (useAlo) {
                        MMA16816(acc[mt][ng * 2 + 0], al[mt], bh[0], bh[1]);
                        MMA16816(acc[mt][ng * 2 + 1], al[mt], bh[2], bh[3]);
                    }
                }
            }
        }
        if (++st == NSTAGE) st = 0;
    }

    const int erow = lane >> 2;
    const int ecol = (lane & 3) * 2;
#pragma unroll
    for (int mt = 0; mt < 2; mt++) {
#pragma unroll
        for (int nt = 0; nt < 8; nt++) {
            int col = n0 + wn + nt * 8 + ecol;
            float b0 = __ldg(bias + col), b1 = __ldg(bias + col + 1);
            int r0 = m0 + wm + mt * 16 + erow;
            float v00 = acc[mt][nt][0] + b0, v01 = acc[mt][nt][1] + b1;
            float v10 = acc[mt][nt][2] + b0, v11 = acc[mt][nt][3] + b1;
            if (SPLIT) {
                *(__half2*)(Chi + (size_t)r0 * Nn + col) =
                    __halves2half2(__float2half_rn(v00), __float2half_rn(v01));
                *(__half2*)(Chi + (size_t)(r0 + 8) * Nn + col) =
                    __halves2half2(__float2half_rn(v10), __float2half_rn(v11));
            } else {
                *(float2*)(C + (size_t)r0 * Nn + col)       = make_float2(v00, v01);
                *(float2*)(C + (size_t)(r0 + 8) * Nn + col) = make_float2(v10, v11);
            }
        }
    }
}

// ---------------- HMMA attention: fp16 QK^T + fp16 PV, reg softmax ----------------
#define ATT    512
#define KP     224
#define VP     208
#define PSTRB  432
#define PSTRH  216
#define A_KH   0
#define A_VH   (A_KH + KP * 128)          // 28672
#define A_QH   (A_VH + VP * 128)          // 55296 (2 bufs x 4096)
#define A_PH   (A_QH + 2 * 32 * 128)      // 63488
#define A_PMAX (A_PH + 32 * PSTRB)        // 77312
#define A_PSUM (A_PMAX + 32 * 7 * 4)      // 78208
#define A_TOT  (A_PSUM + 32 * 7 * 4)      // 79104

__global__ __launch_bounds__(ATT, 1) void attn_hmma_kernel(
    const __half* __restrict__ qhi,
    const float* __restrict__ bias,
    __half* __restrict__ aohi)
{
    extern __shared__ char smb[];
    const uint32_t sb = smem_u32(smb);
    const int b = blockIdx.x / HH;
    const int h = blockIdx.x % HH;
    const int tid = threadIdx.x, lane = tid & 31, wid = tid >> 5;
    const __half* bh_ = qhi + (size_t)b * NT * 2304 + h * 64;
    const float* biasH = bias + (size_t)h * NT * NT;
    float* PMAX = (float*)(smb + A_PMAX);
    float* PSUM = (float*)(smb + A_PSUM);

    for (int i = tid; i < ((KP - NT) * 128) / 4; i += ATT)
        ((uint32_t*)(smb + A_KH + NT * 128))[i] = 0;
    for (int i = tid; i < ((VP - NT) * 128) / 4; i += ATT)
        ((uint32_t*)(smb + A_VH + NT * 128))[i] = 0;
    for (int i = tid; i < (32 * PSTRB) / 4; i += ATT)
        ((uint32_t*)(smb + A_PH))[i] = 0;

    for (int p = tid; p < NT * 8; p += ATT) {
        int row = p >> 3, c = p & 7;
        uint32_t o = swb(row, c);
        size_t goff = (size_t)row * 2304 + 768 + c * 8;
        CPA16(sb + A_KH + o, bh_ + goff);
        CPA16(sb + A_VH + o, bh_ + goff + 768);
    }
    for (int p = tid; p < 32 * 8; p += ATT) {
        int r = p >> 3, c = p & 7;
        int gr = (r < NT) ? r : 0;
        size_t goff = (size_t)gr * 2304 + c * 8;
        CPA16(sb + A_QH + swb(r, c), bh_ + goff);
    }
    CPA_COMMIT();
    CPA_WAIT(0);
    __syncthreads();

    const int a_row16 = lane & 15;
    const int a_kc1   = lane >> 4;
    const int b_row8  = (lane & 7) + ((lane >> 4) << 3);
    const int b_kc1   = (lane >> 3) & 1;

    // AV warp geometry (fixed across qt)
    const int av_wm = (wid & 1) * 16;
    const int av_wd = (wid >> 1) * 8;

    // hoist V_hi fragments (q-tile-invariant)
    uint32_t vfh[13][2];
#pragma unroll
    for (int kk = 0; kk < 13; kk++) {
        uint32_t boff = swb(kk * 16 + (lane & 15), av_wd >> 3);
        LDSM_X2_T(vfh[kk][0], vfh[kk][1], sb + A_VH + boff);
    }

    for (int qt = 0; qt < 7; qt++) {
        const int r0 = qt * 32;
        const int rows = min(32, NT - r0);
        const uint32_t qbuf = (uint32_t)((qt & 1) * 4096);

        // S-phase registers live across pass 1 / pass 2
        float acc[4][4];
        const int s_wm = (wid & 1) * 16;
        const int s_wn = (wid >> 1) * 32;
        const int erow = s_wm + (lane >> 2);
        const int ecol = (lane & 3) * 2;
        const int grp = wid >> 1;                // 0..6 for wid<14

        // ---- pass 1: S = 0.125*(q_hi k_hi^T) + bias; partial row-max ----
        if (wid < 14) {
#pragma unroll
            for (int t = 0; t < 4; t++)
#pragma unroll
                for (int e = 0; e < 4; e++) acc[t][e] = 0.f;

            const int ar = s_wm + a_row16;
#pragma unroll
            for (int kk = 0; kk < 4; kk++) {
                uint32_t aoff = swb(ar, kk * 2 + a_kc1) + qbuf;
                uint32_t ah[4];
                LDSM_X4(ah[0], ah[1], ah[2], ah[3], sb + A_QH + aoff);
#pragma unroll
                for (int ng = 0; ng < 2; ng++) {
                    uint32_t boff = swb(s_wn + ng * 16 + b_row8, kk * 2 + b_kc1);
                    uint32_t bh[4];
                    LDSM_X4(bh[0], bh[1], bh[2], bh[3], sb + A_KH + boff);
                    MMA16816(acc[ng * 2 + 0], ah, bh[0], bh[1]);
                    MMA16816(acc[ng * 2 + 1], ah, bh[2], bh[3]);
                }
            }
            float pm0 = -3.4e38f, pm1 = -3.4e38f;
#pragma unroll
            for (int nt = 0; nt < 4; nt++) {
                int col = s_wn + nt * 8 + ecol;
                int gr0 = r0 + erow, gr1 = r0 + erow + 8;
                float b00 = 0.f, b01 = 0.f, b10 = 0.f, b11 = 0.f;
                if (col < NT) {
                    bool c1 = (col + 1 < NT);
                    if (gr0 < NT) {
                        b00 = biasH[(size_t)gr0 * NT + col];
                        if (c1) b01 = biasH[(size_t)gr0 * NT + col + 1];
                    }
                    if (gr1 < NT) {
                        b10 = biasH[(size_t)gr1 * NT + col];
                        if (c1) b11 = biasH[(size_t)gr1 * NT + col + 1];
                    }
                }
                acc[nt][0] = acc[nt][0] * 0.125f + b00;
                acc[nt][1] = acc[nt][1] * 0.125f + b01;
                acc[nt][2] = acc[nt][2] * 0.125f + b10;
                acc[nt][3] = acc[nt][3] * 0.125f + b11;
                if (col < NT)     { pm0 = fmaxf(pm0, acc[nt][0]); pm1 = fmaxf(pm1, acc[nt][2]); }
                if (col + 1 < NT) { pm0 = fmaxf(pm0, acc[nt][1]); pm1 = fmaxf(pm1, acc[nt][3]); }
            }
            pm0 = fmaxf(pm0, __shfl_xor_sync(0xffffffffu, pm0, 1));
            pm0 = fmaxf(pm0, __shfl_xor_sync(0xffffffffu, pm0, 2));
            pm1 = fmaxf(pm1, __shfl_xor_sync(0xffffffffu, pm1, 1));
            pm1 = fmaxf(pm1, __shfl_xor_sync(0xffffffffu, pm1, 2));
            if ((lane & 3) == 0) {
                PMAX[erow * 7 + grp]       = pm0;
                PMAX[(erow + 8) * 7 + grp] = pm1;
            }
        }
        __syncthreads();

        // Q prefetch for next tile
        if (qt + 1 < 7) {
            const int nr0 = (qt + 1) * 32;
            const uint32_t nqb = (uint32_t)(((qt + 1) & 1) * 4096);
            for (int p = tid; p < 32 * 8; p += ATT) {
                int r = p >> 3, c = p & 7;
                int gr = (nr0 + r < NT) ? (nr0 + r) : 0;
                size_t goff = (size_t)gr * 2304 + c * 8;
                CPA16(sb + A_QH + swb(r, c) + nqb, bh_ + goff);
            }
            CPA_COMMIT();
        }

        // ---- pass 2: exp in regs, write P (fp16), partial row-sum ----
        if (wid < 14) {
            float gm0 = PMAX[erow * 7], gm1 = PMAX[(erow + 8) * 7];
#pragma unroll
            for (int g = 1; g < 7; g++) {
                gm0 = fmaxf(gm0, PMAX[erow * 7 + g]);
                gm1 = fmaxf(gm1, PMAX[(erow + 8) * 7 + g]);
            }
            __half* PH = (__half*)(smb + A_PH);
            float ps0 = 0.f, ps1 = 0.f;
#pragma unroll
            for (int nt = 0; nt < 4; nt++) {
                int col = s_wn + nt * 8 + ecol;
                if (col < NT) {
                    float e00 = __expf(acc[nt][0] - gm0);
                    float e01 = __expf(acc[nt][1] - gm0);
                    float e10 = __expf(acc[nt][2] - gm1);
                    float e11 = __expf(acc[nt][3] - gm1);
                    if (col + 1 >= NT) { e01 = 0.f; e11 = 0.f; }
                    ps0 += e00 + e01;
                    ps1 += e10 + e11;
                    *(__half2*)(PH + erow * PSTRH + col) =
                        __halves2half2(__float2half_rn(e00), __float2half_rn(e01));
                    *(__half2*)(PH + (erow + 8) * PSTRH + col) =
                        __halves2half2(__float2half_rn(e10), __float2half_rn(e11));
                }
            }
            ps0 += __shfl_xor_sync(0xffffffffu, ps0, 1);
            ps0 += __shfl_xor_sync(0xffffffffu, ps0, 2);
            ps1 += __shfl_xor_sync(0xffffffffu, ps1, 1);
            ps1 += __shfl_xor_sync(0xffffffffu, ps1, 2);
            if ((lane & 3) == 0) {
                PSUM[erow * 7 + grp]       = ps0;
                PSUM[(erow + 8) * 7 + grp] = ps1;
            }
        }
        __syncthreads();

        // ---- AV = P_hi * V_hi : 16 warps, each 16x8; V_hi from registers ----
        {
            float acv[4];
#pragma unroll
            for (int e = 0; e < 4; e++) acv[e] = 0.f;

            const int ar = av_wm + a_row16;
#pragma unroll
            for (int kk = 0; kk < 13; kk++) {
                uint32_t aoff = (uint32_t)(ar * PSTRB + (kk * 2 + a_kc1) * 16);
                uint32_t ah[4];
                LDSM_X4(ah[0], ah[1], ah[2], ah[3], sb + A_PH + aoff);
                MMA16816(acv, ah, vfh[kk][0], vfh[kk][1]);
            }
            const int oerow = av_wm + (lane >> 2);
            const int ec = (lane & 3) * 2;
#pragma unroll
            for (int hf = 0; hf < 2; hf++) {
                int rr = oerow + hf * 8;
                if (rr < rows) {
                    float s = PSUM[rr * 7];
#pragma unroll
                    for (int g = 1; g < 7; g++) s += PSUM[rr * 7 + g];
                    float inv = 1.f / s;
                    size_t gb = ((size_t)b * NT + r0 + rr) * DIM_ + h * 64 + av_wd;
                    *(__half2*)(aohi + gb + ec) = __halves2half2(
                        __float2half_rn(acv[hf * 2 + 0] * inv),
                        __float2half_rn(acv[hf * 2 + 1] * inv));
                }
            }
        }
        if (qt + 1 < 7) { CPA_WAIT(0); }
        __syncthreads();
    }
}

// ---------------- launch ----------------
extern "C" void kernel_launch(void* const* d_in, const int* in_sizes, int n_in,
                              void* d_out, int out_size)
{
    const float* x      = (const float*)d_in[0];
    const float* qkv_w  = (const float*)d_in[1];
    const float* qkv_b  = (const float*)d_in[2];
    const float* proj_w = (const float*)d_in[3];
    const float* proj_b = (const float*)d_in[4];
    const float* table  = (const float*)d_in[5];
    const int*   relidx = (const int*)d_in[6];
    float* out = (float*)d_out;

    float *p_bias;
    __half *p_qhi, *p_xhi, *p_xlo, *p_aohi;
    __half *p_qwhi, *p_qwlo, *p_pwhi, *p_pwlo;
    cudaGetSymbolAddress((void**)&p_qhi,  g_qhi);
    cudaGetSymbolAddress((void**)&p_xhi,  g_xhi);
    cudaGetSymbolAddress((void**)&p_xlo,  g_xlo);
    cudaGetSymbolAddress((void**)&p_aohi, g_aohi);
    cudaGetSymbolAddress((void**)&p_qwhi, g_qwhi);
    cudaGetSymbolAddress((void**)&p_qwlo, g_qwlo);
    cudaGetSymbolAddress((void**)&p_pwhi, g_pwhi);
    cudaGetSymbolAddress((void**)&p_pwlo, g_pwlo);
    cudaGetSymbolAddress((void**)&p_bias, g_bias);

    cudaFuncSetAttribute(attn_hmma_kernel, cudaFuncAttributeMaxDynamicSharedMemorySize, A_TOT);
    cudaFuncSetAttribute(gemm_hmma_kernel<true>,  cudaFuncAttributeMaxDynamicSharedMemorySize, GSMEM);
    cudaFuncSetAttribute(gemm_hmma_kernel<false>, cudaFuncAttributeMaxDynamicSharedMemorySize, GSMEM);

    const int n0 = MTOK * DIM_;
    const int n1 = 2304 * DIM_;
    const int n2 = DIM_ * DIM_;
    split3_kernel<<<(n0 + n1 + n2 + 255) / 256, 256>>>(
        x, p_xhi, p_xlo, n0,
        qkv_w, p_qwhi, p_qwlo, n1,
        proj_w, p_pwhi, p_pwlo, n2);

    bias_kernel<<<(HH * NT * NT + 255) / 256, 256>>>(table, relidx, p_bias);

    // QKV: q,k tiles (cols < 1536) 1-term; v tiles 3-term; fp16 output (hi only)
    dim3 g1(2304 / 128, MTOK / 128);
    gemm_hmma_kernel<true><<<g1, 256, GSMEM>>>(p_xhi, p_xlo, p_qwhi, p_qwlo, qkv_b,
                                               nullptr, p_qhi, 2304, 1536, 1536);

    attn_hmma_kernel<<<B_ * HH, ATT, A_TOT>>>(p_qhi, p_bias, p_aohi);

    // proj: 2-term (ah*bh + ah*bl), no A_lo; fp32 output
    dim3 g2(DIM_ / 128, MTOK / 128);
    gemm_hmma_kernel<false><<<g2, 256, GSMEM>>>(p_aohi, p_aohi, p_pwhi, p_pwlo, proj_b,
                                                out, nullptr, DIM_, 1 << 30, 0);
}

// round 17
// speedup vs baseline: 1.5360x; 1.0247x over previous
#include <cuda_runtime.h>
#include <cuda_fp16.h>
#include <cstdint>

#define B_   128
#define NT   197
#define HH   12
#define HD   64
#define DIM_ 768
#define MTOK (B_ * NT)          // 25216 = 197*128

// ---------------- scratch ----------------
__device__ __half g_qhi [(long long)MTOK * 2304];
__device__ __half g_xhi [(long long)MTOK * DIM_];
__device__ __half g_aohi[(long long)MTOK * DIM_];
__device__ __half g_qwhi[2304 * DIM_];
__device__ __half g_qwlo[2304 * DIM_];
__device__ __half g_pwhi[DIM_ * DIM_];
__device__ float  g_bias[HH * NT * NT];

// ---------------- helpers ----------------
__device__ __forceinline__ uint32_t smem_u32(const void* p) {
    uint32_t a;
    asm("{ .reg .u64 t; cvta.to.shared.u64 t, %1; cvt.u32.u64 %0, t; }" : "=r"(a) : "l"(p));
    return a;
}

#define CPA16(dst, src)   asm volatile("cp.async.cg.shared.global [%0], [%1], 16;" :: "r"(dst), "l"(src) : "memory")
#define CPA_COMMIT()      asm volatile("cp.async.commit_group;" ::: "memory")
#define CPA_WAIT(n)       asm volatile("cp.async.wait_group %0;" :: "n"(n) : "memory")

#define LDSM_X4(r0, r1, r2, r3, addr) \
    asm volatile("ldmatrix.sync.aligned.m8n8.x4.shared.b16 {%0,%1,%2,%3}, [%4];" \
        : "=r"(r0), "=r"(r1), "=r"(r2), "=r"(r3) : "r"(addr))

#define LDSM_X2_T(r0, r1, addr) \
    asm volatile("ldmatrix.sync.aligned.m8n8.x2.trans.shared.b16 {%0,%1}, [%2];" \
        : "=r"(r0), "=r"(r1) : "r"(addr))

#define MMA16816(d, a, b0, b1) \
    asm volatile("mma.sync.aligned.m16n8k16.row.col.f32.f16.f16.f32 " \
        "{%0,%1,%2,%3}, {%4,%5,%6,%7}, {%8,%9}, {%0,%1,%2,%3};" \
        : "+f"((d)[0]), "+f"((d)[1]), "+f"((d)[2]), "+f"((d)[3]) \
        : "r"((a)[0]), "r"((a)[1]), "r"((a)[2]), "r"((a)[3]), "r"(b0), "r"(b1))

// swizzled tile offset for 64B rows (gemm tiles): chunk 0..3
__device__ __forceinline__ uint32_t sw_off(int row, int chunk) {
    return (uint32_t)(row * 64 + ((chunk ^ ((row >> 1) & 3)) << 4));
}
// swizzled offset for 128B rows (attention tiles): chunk 0..7
__device__ __forceinline__ uint32_t swb(int row, int chunk) {
    return (uint32_t)(row * 128 + ((chunk ^ (row & 7)) << 4));
}

static __device__ __forceinline__ void h_split(float v, __half& hi, __half& lo) {
    hi = __float2half_rn(v);
    lo = __float2half_rn(v - __half2float(hi));
}

// ---------------- merged elementwise fp16 split (lo optional) ----------------
__global__ void split3_kernel(const float* __restrict__ in0, __half* __restrict__ hi0, __half* __restrict__ lo0, int n0,
                              const float* __restrict__ in1, __half* __restrict__ hi1, __half* __restrict__ lo1, int n1,
                              const float* __restrict__ in2, __half* __restrict__ hi2, __half* __restrict__ lo2, int n2)
{
    int t = blockIdx.x * 256 + threadIdx.x;
    const float* in; __half *hi, *lo;
    if (t < n0)               { in = in0;  hi = hi0; lo = lo0; }
    else if (t < n0 + n1)     { t -= n0;       in = in1; hi = hi1; lo = lo1; }
    else if (t < n0 + n1 + n2){ t -= n0 + n1;  in = in2; hi = hi2; lo = lo2; }
    else return;
    float v = in[t];
    __half h = __float2half_rn(v);
    hi[t] = h;
    if (lo) lo[t] = __float2half_rn(v - __half2float(h));
}

// ---------------- bias gather ----------------
__global__ void bias_kernel(const float* __restrict__ table,
                            const int*   __restrict__ idx,
                            float* __restrict__ out)
{
    int t = blockIdx.x * blockDim.x + threadIdx.x;
    if (t < HH * NT * NT) {
        int ij = t % (NT * NT);
        int h  = t / (NT * NT);
        out[t] = table[idx[ij] * HH + h];
    }
}

// ---------------- FP16 mma.sync GEMM, 3-stage pipeline ----------------
// Terms: always ah*bh; +ah*bl if useBlo; +al*bh if useAlo.
#define GK     768
#define NCHUNK 24
#define TILEB  8192
#define STAGEB (4 * TILEB)
#define NSTAGE 3
#define GSMEM  (NSTAGE * STAGEB)       // 96 KB

static __device__ __forceinline__ void load_stage(
    uint32_t sb, const __half* __restrict__ Ahi, const __half* __restrict__ Alo,
    const __half* __restrict__ Whi, const __half* __restrict__ Wlo,
    int m0, int n0, int k0, int tid, bool useAlo, bool useBlo)
{
#pragma unroll
    for (int j = 0; j < 2; j++) {
        int id = tid + (j << 8);
        int row = id >> 2, c = id & 3;
        uint32_t o = sw_off(row, c);
        size_t ga = (size_t)(m0 + row) * GK + k0 + c * 8;
        size_t gb = (size_t)(n0 + row) * GK + k0 + c * 8;
        CPA16(sb + o,             Ahi + ga);
        CPA16(sb + 2 * TILEB + o, Whi + gb);
        if (useAlo) CPA16(sb + TILEB + o,     Alo + ga);
        if (useBlo) CPA16(sb + 3 * TILEB + o, Wlo + gb);
    }
}

template<bool SPLIT>
__global__ __launch_bounds__(256, 2)
void gemm_hmma_kernel(const __half* __restrict__ Ahi, const __half* __restrict__ Alo,
                      const __half* __restrict__ Whi, const __half* __restrict__ Wlo,
                      const float* __restrict__ bias, float* __restrict__ C,
                      __half* __restrict__ Chi,
                      int Nn, int nAlo, int nBlo)
{
    extern __shared__ char dsm[];
    const int tid = threadIdx.x;
    const int lane = tid & 31;
    const int wid = tid >> 5;
    const int wm = (wid & 3) * 32;
    const int wn = (wid >> 2) * 64;
    const int m0 = blockIdx.y * 128;
    const int n0 = blockIdx.x * 128;
    const uint32_t sb = smem_u32(dsm);
    const bool useAlo = (n0 >= nAlo);
    const bool useBlo = (n0 >= nBlo);

    float acc[2][8][4];
#pragma unroll
    for (int mt = 0; mt < 2; mt++)
#pragma unroll
        for (int nt = 0; nt < 8; nt++)
#pragma unroll
            for (int e = 0; e < 4; e++) acc[mt][nt][e] = 0.f;

    const int a_row = lane & 15;
    const int a_kc  = lane >> 4;
    const int b_row = (lane & 7) + ((lane >> 4) << 3);
    const int b_kc  = (lane >> 3) & 1;

    load_stage(sb,          Ahi, Alo, Whi, Wlo, m0, n0, 0,  tid, useAlo, useBlo);
    CPA_COMMIT();
    load_stage(sb + STAGEB, Ahi, Alo, Whi, Wlo, m0, n0, 32, tid, useAlo, useBlo);
    CPA_COMMIT();

    int st = 0;
    for (int k = 0; k < NCHUNK; k++) {
        if (k + 1 < NCHUNK) { CPA_WAIT(1); } else { CPA_WAIT(0); }
        __syncthreads();
        if (k + 2 < NCHUNK) {
            int ls = st + 2; if (ls >= NSTAGE) ls -= NSTAGE;
            load_stage(sb + ls * STAGEB, Ahi, Alo, Whi, Wlo, m0, n0, (k + 2) * 32, tid, useAlo, useBlo);
            CPA_COMMIT();
        }

        const uint32_t cs  = sb + st * STAGEB;
        const uint32_t sAh = cs, sAl = cs + TILEB, sBh = cs + 2 * TILEB, sBl = cs + 3 * TILEB;

#pragma unroll
        for (int kk = 0; kk < 2; kk++) {
            const int kc = kk * 2;
            uint32_t ah[2][4], al[2][4];
#pragma unroll
            for (int mt = 0; mt < 2; mt++) {
                uint32_t o = sw_off(wm + mt * 16 + a_row, kc + a_kc);
                LDSM_X4(ah[mt][0], ah[mt][1], ah[mt][2], ah[mt][3], sAh + o);
                if (useAlo) LDSM_X4(al[mt][0], al[mt][1], al[mt][2], al[mt][3], sAl + o);
            }
#pragma unroll
            for (int ng = 0; ng < 4; ng++) {
                uint32_t bh[4], bl[4];
                uint32_t o = sw_off(wn + ng * 16 + b_row, kc + b_kc);
                LDSM_X4(bh[0], bh[1], bh[2], bh[3], sBh + o);
                if (useBlo) LDSM_X4(bl[0], bl[1], bl[2], bl[3], sBl + o);
#pragma unroll
                for (int mt = 0; mt < 2; mt++) {
                    MMA16816(acc[mt][ng * 2 + 0], ah[mt], bh[0], bh[1]);
                    MMA16816(acc[mt][ng * 2 + 1], ah[mt], bh[2], bh[3]);
                    if (useBlo) {
                        MMA16816(acc[mt][ng * 2 + 0], ah[mt], bl[0], bl[1]);
                        MMA16816(acc[mt][ng * 2 + 1], ah[mt], bl[2], bl[3]);
                    }
                    if (useAlo) {
                        MMA16816(acc[mt][ng * 2 + 0], al[mt], bh[0], bh[1]);
                        MMA16816(acc[mt][ng * 2 + 1], al[mt], bh[2], bh[3]);
                    }
                }
            }
        }
        if (++st == NSTAGE) st = 0;
    }

    const int erow = lane >> 2;
    const int ecol = (lane & 3) * 2;
#pragma unroll
    for (int mt = 0; mt < 2; mt++) {
#pragma unroll
        for (int nt = 0; nt < 8; nt++) {
            int col = n0 + wn + nt * 8 + ecol;
            float b0 = __ldg(bias + col), b1 = __ldg(bias + col + 1);
            int r0 = m0 + wm + mt * 16 + erow;
            float v00 = acc[mt][nt][0] + b0, v01 = acc[mt][nt][1] + b1;
            float v10 = acc[mt][nt][2] + b0, v11 = acc[mt][nt][3] + b1;
            if (SPLIT) {
                *(__half2*)(Chi + (size_t)r0 * Nn + col) =
                    __halves2half2(__float2half_rn(v00), __float2half_rn(v01));
                *(__half2*)(Chi + (size_t)(r0 + 8) * Nn + col) =
                    __halves2half2(__float2half_rn(v10), __float2half_rn(v11));
            } else {
                *(float2*)(C + (size_t)r0 * Nn + col)       = make_float2(v00, v01);
                *(float2*)(C + (size_t)(r0 + 8) * Nn + col) = make_float2(v10, v11);
            }
        }
    }
}

// ---------------- HMMA attention: fp16 QK^T + fp16 PV, reg softmax ----------------
#define ATT    512
#define KP     224
#define VP     208
#define PSTRB  432
#define PSTRH  216
#define A_KH   0
#define A_VH   (A_KH + KP * 128)          // 28672
#define A_QH   (A_VH + VP * 128)          // 55296 (2 bufs x 4096)
#define A_PH   (A_QH + 2 * 32 * 128)      // 63488
#define A_PMAX (A_PH + 32 * PSTRB)        // 77312
#define A_PSUM (A_PMAX + 32 * 7 * 4)      // 78208
#define A_TOT  (A_PSUM + 32 * 7 * 4)      // 79104

__global__ __launch_bounds__(ATT, 1) void attn_hmma_kernel(
    const __half* __restrict__ qhi,
    const float* __restrict__ bias,
    __half* __restrict__ aohi)
{
    extern __shared__ char smb[];
    const uint32_t sb = smem_u32(smb);
    const int b = blockIdx.x / HH;
    const int h = blockIdx.x % HH;
    const int tid = threadIdx.x, lane = tid & 31, wid = tid >> 5;
    const __half* bh_ = qhi + (size_t)b * NT * 2304 + h * 64;
    const float* biasH = bias + (size_t)h * NT * NT;
    float* PMAX = (float*)(smb + A_PMAX);
    float* PSUM = (float*)(smb + A_PSUM);

    for (int i = tid; i < ((KP - NT) * 128) / 4; i += ATT)
        ((uint32_t*)(smb + A_KH + NT * 128))[i] = 0;
    for (int i = tid; i < ((VP - NT) * 128) / 4; i += ATT)
        ((uint32_t*)(smb + A_VH + NT * 128))[i] = 0;
    for (int i = tid; i < (32 * PSTRB) / 4; i += ATT)
        ((uint32_t*)(smb + A_PH))[i] = 0;

    for (int p = tid; p < NT * 8; p += ATT) {
        int row = p >> 3, c = p & 7;
        uint32_t o = swb(row, c);
        size_t goff = (size_t)row * 2304 + 768 + c * 8;
        CPA16(sb + A_KH + o, bh_ + goff);
        CPA16(sb + A_VH + o, bh_ + goff + 768);
    }
    for (int p = tid; p < 32 * 8; p += ATT) {
        int r = p >> 3, c = p & 7;
        int gr = (r < NT) ? r : 0;
        size_t goff = (size_t)gr * 2304 + c * 8;
        CPA16(sb + A_QH + swb(r, c), bh_ + goff);
    }
    CPA_COMMIT();
    CPA_WAIT(0);
    __syncthreads();

    const int a_row16 = lane & 15;
    const int a_kc1   = lane >> 4;
    const int b_row8  = (lane & 7) + ((lane >> 4) << 3);
    const int b_kc1   = (lane >> 3) & 1;

    // AV warp geometry (fixed across qt)
    const int av_wm = (wid & 1) * 16;
    const int av_wd = (wid >> 1) * 8;

    // hoist V_hi fragments (q-tile-invariant)
    uint32_t vfh[13][2];
#pragma unroll
    for (int kk = 0; kk < 13; kk++) {
        uint32_t boff = swb(kk * 16 + (lane & 15), av_wd >> 3);
        LDSM_X2_T(vfh[kk][0], vfh[kk][1], sb + A_VH + boff);
    }

    for (int qt = 0; qt < 7; qt++) {
        const int r0 = qt * 32;
        const int rows = min(32, NT - r0);
        const uint32_t qbuf = (uint32_t)((qt & 1) * 4096);

        // S-phase registers live across pass 1 / pass 2
        float acc[4][4];
        const int s_wm = (wid & 1) * 16;
        const int s_wn = (wid >> 1) * 32;
        const int erow = s_wm + (lane >> 2);
        const int ecol = (lane & 3) * 2;
        const int grp = wid >> 1;                // 0..6 for wid<14

        // ---- pass 1: S = 0.125*(q_hi k_hi^T) + bias; partial row-max ----
        if (wid < 14) {
#pragma unroll
            for (int t = 0; t < 4; t++)
#pragma unroll
                for (int e = 0; e < 4; e++) acc[t][e] = 0.f;

            const int ar = s_wm + a_row16;
#pragma unroll
            for (int kk = 0; kk < 4; kk++) {
                uint32_t aoff = swb(ar, kk * 2 + a_kc1) + qbuf;
                uint32_t ah[4];
                LDSM_X4(ah[0], ah[1], ah[2], ah[3], sb + A_QH + aoff);
#pragma unroll
                for (int ng = 0; ng < 2; ng++) {
                    uint32_t boff = swb(s_wn + ng * 16 + b_row8, kk * 2 + b_kc1);
                    uint32_t bh[4];
                    LDSM_X4(bh[0], bh[1], bh[2], bh[3], sb + A_KH + boff);
                    MMA16816(acc[ng * 2 + 0], ah, bh[0], bh[1]);
                    MMA16816(acc[ng * 2 + 1], ah, bh[2], bh[3]);
                }
            }
            float pm0 = -3.4e38f, pm1 = -3.4e38f;
#pragma unroll
            for (int nt = 0; nt < 4; nt++) {
                int col = s_wn + nt * 8 + ecol;
                int gr0 = r0 + erow, gr1 = r0 + erow + 8;
                float b00 = 0.f, b01 = 0.f, b10 = 0.f, b11 = 0.f;
                if (col < NT) {
                    bool c1 = (col + 1 < NT);
                    if (gr0 < NT) {
                        b00 = biasH[(size_t)gr0 * NT + col];
                        if (c1) b01 = biasH[(size_t)gr0 * NT + col + 1];
                    }
                    if (gr1 < NT) {
                        b10 = biasH[(size_t)gr1 * NT + col];
                        if (c1) b11 = biasH[(size_t)gr1 * NT + col + 1];
                    }
                }
                acc[nt][0] = acc[nt][0] * 0.125f + b00;
                acc[nt][1] = acc[nt][1] * 0.125f + b01;
                acc[nt][2] = acc[nt][2] * 0.125f + b10;
                acc[nt][3] = acc[nt][3] * 0.125f + b11;
                if (col < NT)     { pm0 = fmaxf(pm0, acc[nt][0]); pm1 = fmaxf(pm1, acc[nt][2]); }
                if (col + 1 < NT) { pm0 = fmaxf(pm0, acc[nt][1]); pm1 = fmaxf(pm1, acc[nt][3]); }
            }
            pm0 = fmaxf(pm0, __shfl_xor_sync(0xffffffffu, pm0, 1));
            pm0 = fmaxf(pm0, __shfl_xor_sync(0xffffffffu, pm0, 2));
            pm1 = fmaxf(pm1, __shfl_xor_sync(0xffffffffu, pm1, 1));
            pm1 = fmaxf(pm1, __shfl_xor_sync(0xffffffffu, pm1, 2));
            if ((lane & 3) == 0) {
                PMAX[erow * 7 + grp]       = pm0;
                PMAX[(erow + 8) * 7 + grp] = pm1;
            }
        }
        __syncthreads();

        // Q prefetch for next tile
        if (qt + 1 < 7) {
            const int nr0 = (qt + 1) * 32;
            const uint32_t nqb = (uint32_t)(((qt + 1) & 1) * 4096);
            for (int p = tid; p < 32 * 8; p += ATT) {
                int r = p >> 3, c = p & 7;
                int gr = (nr0 + r < NT) ? (nr0 + r) : 0;
                size_t goff = (size_t)gr * 2304 + c * 8;
                CPA16(sb + A_QH + swb(r, c) + nqb, bh_ + goff);
            }
            CPA_COMMIT();
        }

        // ---- pass 2: exp in regs, write P (fp16), partial row-sum ----
        if (wid < 14) {
            float gm0 = PMAX[erow * 7], gm1 = PMAX[(erow + 8) * 7];
#pragma unroll
            for (int g = 1; g < 7; g++) {
                gm0 = fmaxf(gm0, PMAX[erow * 7 + g]);
                gm1 = fmaxf(gm1, PMAX[(erow + 8) * 7 + g]);
            }
            __half* PH = (__half*)(smb + A_PH);
            float ps0 = 0.f, ps1 = 0.f;
#pragma unroll
            for (int nt = 0; nt < 4; nt++) {
                int col = s_wn + nt * 8 + ecol;
                if (col < NT) {
                    float e00 = __expf(acc[nt][0] - gm0);
                    float e01 = __expf(acc[nt][1] - gm0);
                    float e10 = __expf(acc[nt][2] - gm1);
                    float e11 = __expf(acc[nt][3] - gm1);
                    if (col + 1 >= NT) { e01 = 0.f; e11 = 0.f; }
                    ps0 += e00 + e01;
                    ps1 += e10 + e11;
                    *(__half2*)(PH + erow * PSTRH + col) =
                        __halves2half2(__float2half_rn(e00), __float2half_rn(e01));
                    *(__half2*)(PH + (erow + 8) * PSTRH + col) =
                        __halves2half2(__float2half_rn(e10), __float2half_rn(e11));
                }
            }
            ps0 += __shfl_xor_sync(0xffffffffu, ps0, 1);
            ps0 += __shfl_xor_sync(0xffffffffu, ps0, 2);
            ps1 += __shfl_xor_sync(0xffffffffu, ps1, 1);
            ps1 += __shfl_xor_sync(0xffffffffu, ps1, 2);
            if ((lane & 3) == 0) {
                PSUM[erow * 7 + grp]       = ps0;
                PSUM[(erow + 8) * 7 + grp] = ps1;
            }
        }
        __syncthreads();

        // ---- AV = P_hi * V_hi : 16 warps, each 16x8; V_hi from registers ----
        {
            float acv[4];
#pragma unroll
            for (int e = 0; e < 4; e++) acv[e] = 0.f;

            const int ar = av_wm + a_row16;
#pragma unroll
            for (int kk = 0; kk < 13; kk++) {
                uint32_t aoff = (uint32_t)(ar * PSTRB + (kk * 2 + a_kc1) * 16);
                uint32_t ah[4];
                LDSM_X4(ah[0], ah[1], ah[2], ah[3], sb + A_PH + aoff);
                MMA16816(acv, ah, vfh[kk][0], vfh[kk][1]);
            }
            const int oerow = av_wm + (lane >> 2);
            const int ec = (lane & 3) * 2;
#pragma unroll
            for (int hf = 0; hf < 2; hf++) {
                int rr = oerow + hf * 8;
                if (rr < rows) {
                    float s = PSUM[rr * 7];
#pragma unroll
                    for (int g = 1; g < 7; g++) s += PSUM[rr * 7 + g];
                    float inv = 1.f / s;
                    size_t gb = ((size_t)b * NT + r0 + rr) * DIM_ + h * 64 + av_wd;
                    *(__half2*)(aohi + gb + ec) = __halves2half2(
                        __float2half_rn(acv[hf * 2 + 0] * inv),
                        __float2half_rn(acv[hf * 2 + 1] * inv));
                }
            }
        }
        if (qt + 1 < 7) { CPA_WAIT(0); }
        __syncthreads();
    }
}

// ---------------- launch ----------------
extern "C" void kernel_launch(void* const* d_in, const int* in_sizes, int n_in,
                              void* d_out, int out_size)
{
    const float* x      = (const float*)d_in[0];
    const float* qkv_w  = (const float*)d_in[1];
    const float* qkv_b  = (const float*)d_in[2];
    const float* proj_w = (const float*)d_in[3];
    const float* proj_b = (const float*)d_in[4];
    const float* table  = (const float*)d_in[5];
    const int*   relidx = (const int*)d_in[6];
    float* out = (float*)d_out;

    float *p_bias;
    __half *p_qhi, *p_xhi, *p_aohi;
    __half *p_qwhi, *p_qwlo, *p_pwhi;
    cudaGetSymbolAddress((void**)&p_qhi,  g_qhi);
    cudaGetSymbolAddress((void**)&p_xhi,  g_xhi);
    cudaGetSymbolAddress((void**)&p_aohi, g_aohi);
    cudaGetSymbolAddress((void**)&p_qwhi, g_qwhi);
    cudaGetSymbolAddress((void**)&p_qwlo, g_qwlo);
    cudaGetSymbolAddress((void**)&p_pwhi, g_pwhi);
    cudaGetSymbolAddress((void**)&p_bias, g_bias);

    cudaFuncSetAttribute(attn_hmma_kernel, cudaFuncAttributeMaxDynamicSharedMemorySize, A_TOT);
    cudaFuncSetAttribute(gemm_hmma_kernel<true>,  cudaFuncAttributeMaxDynamicSharedMemorySize, GSMEM);
    cudaFuncSetAttribute(gemm_hmma_kernel<false>, cudaFuncAttributeMaxDynamicSharedMemorySize, GSMEM);

    const int n0 = MTOK * DIM_;
    const int n1 = 2304 * DIM_;
    const int n2 = DIM_ * DIM_;
    split3_kernel<<<(n0 + n1 + n2 + 255) / 256, 256>>>(
        x, p_xhi, nullptr, n0,                  // x: hi only (x_lo dead)
        qkv_w, p_qwhi, p_qwlo, n1,              // qkv_w: hi+lo (v tiles use lo)
        proj_w, p_pwhi, nullptr, n2);           // proj_w: hi only

    bias_kernel<<<(HH * NT * NT + 255) / 256, 256>>>(table, relidx, p_bias);

    // QKV: q,k tiles 1-term; v tiles 2-term (ah*bh + ah*bl); A_lo never used
    dim3 g1(2304 / 128, MTOK / 128);
    gemm_hmma_kernel<true><<<g1, 256, GSMEM>>>(p_xhi, p_xhi, p_qwhi, p_qwlo, qkv_b,
                                               nullptr, p_qhi, 2304, 1 << 30, 1536);

    attn_hmma_kernel<<<B_ * HH, ATT, A_TOT>>>(p_qhi, p_bias, p_aohi);

    // proj: pure fp16 1-term
    dim3 g2(DIM_ / 128, MTOK / 128);
    gemm_hmma_kernel<false><<<g2, 256, GSMEM>>>(p_aohi, p_aohi, p_pwhi, p_pwhi, proj_b,
                                                out, nullptr, DIM_, 1 << 30, 1 << 30);
}